// round 1
// baseline (speedup 1.0000x reference)
#include <cuda_runtime.h>

#define N_NODES 20000
#define N_EDGES 320000

// ---------------- scratch (device globals: allocation-free) ----------------
__device__ float g_tmp [N_NODES * 128];   // nodemlp hidden
__device__ float g_h1  [N_NODES * 128];   // nodemlp out
__device__ float g_fs  [N_NODES * 256];   // gat fc_src (reused both layers)
__device__ float g_fd  [N_NODES * 256];   // gat fc_dst
__device__ float g_gat1[N_NODES * 256];   // gat layer1 out (relu'd)
__device__ float g_gat2[N_NODES * 256];   // gat layer2 out (relu'd)
__device__ float g_acc [N_NODES * 256];   // gat scatter accumulator
__device__ float g_m   [N_NODES * 2];     // segment max
__device__ float g_s   [N_NODES * 2];     // segment sum
__device__ float g_w   [N_EDGES * 2];     // edge logits -> exp weights
__device__ float g_e1  [N_EDGES * 512];   // edgemlp hidden1 (pre-relu)
__device__ float g_e2  [N_EDGES * 256];   // edgemlp hidden2 (pre-relu)

// ---------------- generic tiled fp32 GEMM: C = act(A @ W + b) ----------------
// BM=64, BN=64, BK=16, 128 threads, each thread 8x4 outputs.
// N must be a multiple of 64, K a multiple of 16. M arbitrary (guarded).
#define BM 64
#define BN 64
#define BK 16

__global__ void gemm_kernel(const float* __restrict__ A,
                            const float* __restrict__ W,
                            const float* __restrict__ bias,
                            float* __restrict__ C,
                            int M, int N, int K,
                            int in_relu, int out_relu)
{
    __shared__ float As[BK][BM + 4];   // +4 pad keeps 16B alignment (68*4=272=17*16)
    __shared__ float Bs[BK][BN];

    const int tid = threadIdx.x;
    const int m0 = blockIdx.y * BM;
    const int n0 = blockIdx.x * BN;
    const int tx = tid & 15;          // 16 col-groups
    const int ty = tid >> 4;          // 8 row-groups

    float acc[8][4];
#pragma unroll
    for (int j = 0; j < 8; j++)
#pragma unroll
        for (int i = 0; i < 4; i++) acc[j][i] = 0.f;

    const int ar = tid >> 1;          // A tile row 0..63
    const int ac = (tid & 1) * 8;     // A tile k-offset 0 or 8
    const int br = tid >> 3;          // B tile k-row 0..15
    const int bc = (tid & 7) * 8;     // B tile col 0..56

    for (int k0 = 0; k0 < K; k0 += BK) {
        // load A tile (64 x 16), transposed into As[k][row]
        const bool arow_ok = (m0 + ar) < M;
        const float* Ap = A + (size_t)(m0 + ar) * K + k0 + ac;
#pragma unroll
        for (int i = 0; i < 8; i++) {
            float v = arow_ok ? Ap[i] : 0.f;
            if (in_relu) v = fmaxf(v, 0.f);
            As[ac + i][ar] = v;
        }
        // load B tile (16 x 64)
        const float* Wp = W + (size_t)(k0 + br) * N + n0 + bc;
#pragma unroll
        for (int i = 0; i < 8; i++) Bs[br][bc + i] = Wp[i];
        __syncthreads();

#pragma unroll
        for (int kk = 0; kk < BK; kk++) {
            const float4* a4 = reinterpret_cast<const float4*>(&As[kk][ty * 8]);
            float4 a0 = a4[0], a1 = a4[1];
            float4 b0 = *reinterpret_cast<const float4*>(&Bs[kk][tx * 4]);
            float a[8] = {a0.x, a0.y, a0.z, a0.w, a1.x, a1.y, a1.z, a1.w};
            float b[4] = {b0.x, b0.y, b0.z, b0.w};
#pragma unroll
            for (int j = 0; j < 8; j++)
#pragma unroll
                for (int i = 0; i < 4; i++) acc[j][i] += a[j] * b[i];
        }
        __syncthreads();
    }

#pragma unroll
    for (int j = 0; j < 8; j++) {
        int r = m0 + ty * 8 + j;
        if (r >= M) continue;
#pragma unroll
        for (int i = 0; i < 4; i++) {
            int c = n0 + tx * 4 + i;
            float v = acc[j][i] + bias[c];
            if (out_relu) v = fmaxf(v, 0.f);
            C[(size_t)r * N + c] = v;
        }
    }
}

// ---------------- EdgeMLP layer-1: fused gather-GEMM ----------------
// A(e,k) = concat(h1[src], h1[dst], h2[src], h2[dst])[k]; K=768, N=512.
// E and N are multiples of 64, so no guards.
__global__ void edge_gemm0_kernel(const float* __restrict__ h1n,
                                  const float* __restrict__ h2n,
                                  const int* __restrict__ src,
                                  const int* __restrict__ dst,
                                  const float* __restrict__ W,
                                  const float* __restrict__ bias,
                                  float* __restrict__ C)
{
    const int K = 768, N = 512;
    __shared__ float As[BK][BM + 4];
    __shared__ float Bs[BK][BN];

    const int tid = threadIdx.x;
    const int m0 = blockIdx.y * BM;
    const int n0 = blockIdx.x * BN;
    const int tx = tid & 15;
    const int ty = tid >> 4;

    float acc[8][4];
#pragma unroll
    for (int j = 0; j < 8; j++)
#pragma unroll
        for (int i = 0; i < 4; i++) acc[j][i] = 0.f;

    const int ar = tid >> 1;
    const int ac = (tid & 1) * 8;
    const int br = tid >> 3;
    const int bc = (tid & 7) * 8;
    const int e = m0 + ar;

    for (int k0 = 0; k0 < K; k0 += BK) {
        // region is uniform per k-tile (boundaries 0/128/256/512, BK=16)
        const float* base;
        int coff;
        if (k0 < 128)      { base = h1n + (size_t)src[e] * 128; coff = k0; }
        else if (k0 < 256) { base = h1n + (size_t)dst[e] * 128; coff = k0 - 128; }
        else if (k0 < 512) { base = h2n + (size_t)src[e] * 256; coff = k0 - 256; }
        else               { base = h2n + (size_t)dst[e] * 256; coff = k0 - 512; }

        const float4* p = reinterpret_cast<const float4*>(base + coff + ac);
        float4 v0 = p[0], v1 = p[1];
        As[ac + 0][ar] = v0.x; As[ac + 1][ar] = v0.y;
        As[ac + 2][ar] = v0.z; As[ac + 3][ar] = v0.w;
        As[ac + 4][ar] = v1.x; As[ac + 5][ar] = v1.y;
        As[ac + 6][ar] = v1.z; As[ac + 7][ar] = v1.w;

        const float* Wp = W + (size_t)(k0 + br) * N + n0 + bc;
#pragma unroll
        for (int i = 0; i < 8; i++) Bs[br][bc + i] = Wp[i];
        __syncthreads();

#pragma unroll
        for (int kk = 0; kk < BK; kk++) {
            const float4* a4 = reinterpret_cast<const float4*>(&As[kk][ty * 8]);
            float4 a0 = a4[0], a1 = a4[1];
            float4 b0 = *reinterpret_cast<const float4*>(&Bs[kk][tx * 4]);
            float a[8] = {a0.x, a0.y, a0.z, a0.w, a1.x, a1.y, a1.z, a1.w};
            float b[4] = {b0.x, b0.y, b0.z, b0.w};
#pragma unroll
            for (int j = 0; j < 8; j++)
#pragma unroll
                for (int i = 0; i < 4; i++) acc[j][i] += a[j] * b[i];
        }
        __syncthreads();
    }

#pragma unroll
    for (int j = 0; j < 8; j++) {
        int r = m0 + ty * 8 + j;
#pragma unroll
        for (int i = 0; i < 4; i++) {
            int c = n0 + tx * 4 + i;
            C[(size_t)r * N + c] = acc[j][i] + bias[c];
        }
    }
}

// ---------------- GAT edge kernels ----------------
__device__ __forceinline__ void atomicMaxFloat(float* addr, float v)
{
    if (v >= 0.f)
        atomicMax((int*)addr, __float_as_int(v));
    else
        atomicMin((unsigned int*)addr, (unsigned int)__float_as_int(v));
}

__global__ void gat_init_kernel(float* m, float* s, float* acc)
{
    int i = blockIdx.x * blockDim.x + threadIdx.x;
    if (i < N_NODES * 256) acc[i] = 0.f;
    if (i < N_NODES * 2) {
        m[i] = __int_as_float(0xff800000);  // -inf
        s[i] = 0.f;
    }
}

// one warp per edge, H=2, D=128
__global__ void gat_logits_kernel(const float* __restrict__ fs,
                                  const float* __restrict__ fd,
                                  const float* __restrict__ attn,
                                  const int* __restrict__ src,
                                  const int* __restrict__ dst,
                                  float* __restrict__ logit,
                                  float* __restrict__ m)
{
    int warp = (blockIdx.x * blockDim.x + threadIdx.x) >> 5;
    int lane = threadIdx.x & 31;
    if (warp >= N_EDGES) return;
    int sN = src[warp], tN = dst[warp];
#pragma unroll
    for (int h = 0; h < 2; h++) {
        const float* ps = fs + (size_t)sN * 256 + h * 128;
        const float* pd = fd + (size_t)tN * 256 + h * 128;
        const float* pa = attn + h * 128;
        float acc = 0.f;
#pragma unroll
        for (int i = 0; i < 4; i++) {
            int d = lane + 32 * i;
            float v = ps[d] + pd[d];
            v = (v > 0.f) ? v : 0.2f * v;   // leaky_relu(0.2)
            acc += v * pa[d];
        }
#pragma unroll
        for (int o = 16; o; o >>= 1) acc += __shfl_xor_sync(0xffffffffu, acc, o);
        if (lane == 0) {
            logit[(size_t)warp * 2 + h] = acc;
            atomicMaxFloat(&m[tN * 2 + h], acc);
        }
    }
}

__global__ void gat_expsum_kernel(const int* __restrict__ dst,
                                  float* __restrict__ w,
                                  const float* __restrict__ m,
                                  float* __restrict__ s)
{
    int idx = blockIdx.x * blockDim.x + threadIdx.x;
    if (idx >= N_EDGES * 2) return;
    int e = idx >> 1, h = idx & 1;
    int t = dst[e];
    float v = expf(w[idx] - m[t * 2 + h]);
    w[idx] = v;
    atomicAdd(&s[t * 2 + h], v);
}

// one warp per edge: acc[dst] += (w/s) * fs[src]
__global__ void gat_scatter_kernel(const float* __restrict__ fs,
                                   const int* __restrict__ src,
                                   const int* __restrict__ dst,
                                   const float* __restrict__ w,
                                   const float* __restrict__ s,
                                   float* __restrict__ acc)
{
    int warp = (blockIdx.x * blockDim.x + threadIdx.x) >> 5;
    int lane = threadIdx.x & 31;
    if (warp >= N_EDGES) return;
    int sN = src[warp], tN = dst[warp];
#pragma unroll
    for (int h = 0; h < 2; h++) {
        float coef = w[(size_t)warp * 2 + h] / s[tN * 2 + h];
        const float* ps = fs + (size_t)sN * 256 + h * 128;
        float* pa = acc + (size_t)tN * 256 + h * 128;
#pragma unroll
        for (int i = 0; i < 4; i++) {
            int d = lane + 32 * i;
            atomicAdd(&pa[d], coef * ps[d]);
        }
    }
}

__global__ void gat_relu_kernel(const float* __restrict__ acc, float* __restrict__ out)
{
    int i = blockIdx.x * blockDim.x + threadIdx.x;
    if (i < N_NODES * 256) out[i] = fmaxf(acc[i], 0.f);
}

// ---------------- EdgeMLP final layer: out = relu(e2) @ ew2 + eb2 ----------------
// one warp per edge, K=256
__global__ void edge_out_kernel(const float* __restrict__ e2,
                                const float* __restrict__ w,
                                const float* __restrict__ b,
                                float* __restrict__ out)
{
    int e = blockIdx.x * 8 + (threadIdx.x >> 5);
    int lane = threadIdx.x & 31;
    if (e >= N_EDGES) return;
    const float* row = e2 + (size_t)e * 256;
    float acc = 0.f;
#pragma unroll
    for (int i = 0; i < 8; i++) {
        int c = lane + 32 * i;
        float v = fmaxf(row[c], 0.f);
        acc += v * w[c];
    }
#pragma unroll
    for (int o = 16; o; o >>= 1) acc += __shfl_xor_sync(0xffffffffu, acc, o);
    if (lane == 0) out[e] = acc + b[0];
}

// ---------------- host launch ----------------
extern "C" void kernel_launch(void* const* d_in, const int* in_sizes, int n_in,
                              void* d_out, int out_size)
{
    const float* x    = (const float*)d_in[0];
    const int*   src  = (const int*)d_in[1];
    const int*   dst  = (const int*)d_in[2];
    const float* nw0  = (const float*)d_in[3];
    const float* nb0  = (const float*)d_in[4];
    const float* nw1  = (const float*)d_in[5];
    const float* nb1  = (const float*)d_in[6];
    const float* g1ws = (const float*)d_in[7];
    const float* g1bs = (const float*)d_in[8];
    const float* g1wd = (const float*)d_in[9];
    const float* g1bd = (const float*)d_in[10];
    const float* g1a  = (const float*)d_in[11];
    const float* g2ws = (const float*)d_in[12];
    const float* g2bs = (const float*)d_in[13];
    const float* g2wd = (const float*)d_in[14];
    const float* g2bd = (const float*)d_in[15];
    const float* g2a  = (const float*)d_in[16];
    const float* ew0  = (const float*)d_in[17];
    const float* eb0  = (const float*)d_in[18];
    const float* ew1  = (const float*)d_in[19];
    const float* eb1  = (const float*)d_in[20];
    const float* ew2  = (const float*)d_in[21];
    const float* eb2  = (const float*)d_in[22];
    float* out = (float*)d_out;

    float *tmp, *h1, *fs, *fd, *gat1, *gat2, *acc, *mB, *sB, *wB, *e1, *e2;
    cudaGetSymbolAddress((void**)&tmp,  g_tmp);
    cudaGetSymbolAddress((void**)&h1,   g_h1);
    cudaGetSymbolAddress((void**)&fs,   g_fs);
    cudaGetSymbolAddress((void**)&fd,   g_fd);
    cudaGetSymbolAddress((void**)&gat1, g_gat1);
    cudaGetSymbolAddress((void**)&gat2, g_gat2);
    cudaGetSymbolAddress((void**)&acc,  g_acc);
    cudaGetSymbolAddress((void**)&mB,   g_m);
    cudaGetSymbolAddress((void**)&sB,   g_s);
    cudaGetSymbolAddress((void**)&wB,   g_w);
    cudaGetSymbolAddress((void**)&e1,   g_e1);
    cudaGetSymbolAddress((void**)&e2,   g_e2);

    const int MB_NODES = (N_NODES + BM - 1) / BM;   // 313
    const int MB_EDGES = N_EDGES / BM;              // 5000

    // NodeMLP: h1 = relu(relu(x @ nw0 + nb0) @ nw1 + nb1)
    gemm_kernel<<<dim3(128 / BN, MB_NODES), 128>>>(x,   nw0, nb0, tmp, N_NODES, 128, 64,  0, 1);
    gemm_kernel<<<dim3(128 / BN, MB_NODES), 128>>>(tmp, nw1, nb1, h1,  N_NODES, 128, 128, 0, 1);

    // GAT layer 1 (in: x, 64 -> 256)
    gemm_kernel<<<dim3(256 / BN, MB_NODES), 128>>>(x, g1ws, g1bs, fs, N_NODES, 256, 64, 0, 0);
    gemm_kernel<<<dim3(256 / BN, MB_NODES), 128>>>(x, g1wd, g1bd, fd, N_NODES, 256, 64, 0, 0);
    gat_init_kernel<<<(N_NODES * 256 + 255) / 256, 256>>>(mB, sB, acc);
    gat_logits_kernel<<<N_EDGES / 8, 256>>>(fs, fd, g1a, src, dst, wB, mB);
    gat_expsum_kernel<<<(N_EDGES * 2 + 255) / 256, 256>>>(dst, wB, mB, sB);
    gat_scatter_kernel<<<N_EDGES / 8, 256>>>(fs, src, dst, wB, sB, acc);
    gat_relu_kernel<<<(N_NODES * 256 + 255) / 256, 256>>>(acc, gat1);

    // GAT layer 2 (in: gat1, 256 -> 256)
    gemm_kernel<<<dim3(256 / BN, MB_NODES), 128>>>(gat1, g2ws, g2bs, fs, N_NODES, 256, 256, 0, 0);
    gemm_kernel<<<dim3(256 / BN, MB_NODES), 128>>>(gat1, g2wd, g2bd, fd, N_NODES, 256, 256, 0, 0);
    gat_init_kernel<<<(N_NODES * 256 + 255) / 256, 256>>>(mB, sB, acc);
    gat_logits_kernel<<<N_EDGES / 8, 256>>>(fs, fd, g2a, src, dst, wB, mB);
    gat_expsum_kernel<<<(N_EDGES * 2 + 255) / 256, 256>>>(dst, wB, mB, sB);
    gat_scatter_kernel<<<N_EDGES / 8, 256>>>(fs, src, dst, wB, sB, acc);
    gat_relu_kernel<<<(N_NODES * 256 + 255) / 256, 256>>>(acc, gat2);

    // EdgeMLP
    edge_gemm0_kernel<<<dim3(512 / BN, MB_EDGES), 128>>>(h1, gat2, src, dst, ew0, eb0, e1);
    gemm_kernel<<<dim3(256 / BN, MB_EDGES), 128>>>(e1, ew1, eb1, e2, N_EDGES, 256, 512, 1, 0);
    edge_out_kernel<<<N_EDGES / 8, 256>>>(e2, ew2, eb2, out);
}

// round 3
// speedup vs baseline: 4.9435x; 4.9435x over previous
#include <cuda_runtime.h>
#include <cuda_fp16.h>
#include <cstdint>

#define N_NODES 20000
#define N_EDGES 320000

// ---------------- scratch (device globals: allocation-free) ----------------
__device__ float g_tmp [N_NODES * 128];
__device__ float g_h1  [N_NODES * 128];
__device__ float g_fs  [N_NODES * 256];
__device__ float g_fd  [N_NODES * 256];
__device__ float g_gat1[N_NODES * 256];
__device__ float g_gat2[N_NODES * 256];
__device__ float g_acc [N_NODES * 256];
__device__ float g_m   [N_NODES * 2];
__device__ float g_s   [N_NODES * 2];
__device__ float g_w   [N_EDGES * 2];
__device__ float g_z   [N_NODES * 384];   // [h1 | gat2]
__device__ float g_ps  [N_NODES * 512];   // Psrc
__device__ float g_pd  [N_NODES * 512];   // Pdst
__device__ __half g_w0sh[512 * 384], g_w0sl[512 * 384];
__device__ __half g_w0dh[512 * 384], g_w0dl[512 * 384];
__device__ __half g_w1h [256 * 512], g_w1l [256 * 512];

// ---------------- PTX helpers (base ISA only: sm_80+) ----------------
__device__ __forceinline__ uint32_t smem_u32(const void* p) {
    uint32_t a;
    asm("{ .reg .u64 t; cvta.to.shared.u64 t, %1; cvt.u32.u64 %0, t; }" : "=r"(a) : "l"(p));
    return a;
}
__device__ __forceinline__ void ldm_x4(uint32_t* r, uint32_t a) {
    asm volatile("ldmatrix.sync.aligned.m8n8.x4.shared.b16 {%0,%1,%2,%3}, [%4];"
                 : "=r"(r[0]), "=r"(r[1]), "=r"(r[2]), "=r"(r[3]) : "r"(a));
}
__device__ __forceinline__ void ldm_x2(uint32_t* r, uint32_t a) {
    asm volatile("ldmatrix.sync.aligned.m8n8.x2.shared.b16 {%0,%1}, [%2];"
                 : "=r"(r[0]), "=r"(r[1]) : "r"(a));
}
__device__ __forceinline__ void mma16816(float* c, const uint32_t* a, const uint32_t* b) {
    asm volatile("mma.sync.aligned.m16n8k16.row.col.f32.f16.f16.f32 "
                 "{%0,%1,%2,%3}, {%4,%5,%6,%7}, {%8,%9}, {%0,%1,%2,%3};"
                 : "+f"(c[0]), "+f"(c[1]), "+f"(c[2]), "+f"(c[3])
                 : "r"(a[0]), "r"(a[1]), "r"(a[2]), "r"(a[3]), "r"(b[0]), "r"(b[1]));
}
__device__ __forceinline__ void cp16(uint32_t d, const void* s) {
    asm volatile("cp.async.cg.shared.global [%0], [%1], 16;" :: "r"(d), "l"(s));
}
#define CP_COMMIT() asm volatile("cp.async.commit_group;")
#define CP_WAIT0()  asm volatile("cp.async.wait_group 0;")

// ---------------- unified HMMA GEMM, fp16 3-term split ----------------
// BM=128, BN=128, BK=32, 256 threads (8 warps: 2 M x 4 N), warp tile 64x32.
// Tile layout in smem: rows stride 80B (64B data + 16B pad -> conflict-free ldmatrix).
// Per stage (40960B): A_hi @0, A_lo @10240, B_hi @20480, B_lo @30720. 2 stages.
// MODE 0: A = fp32 matrix [M x K] (row-guarded), C = fp32 [M x NTOT].
// MODE 1: A(e,k) = relu(Psrc[src[e]][k] + Pdst[dst[e]][k] + abias[k]); epilogue:
//         out[e] += sum_col( relu(acc + eb1[col]) * ew2[col] )  (+ eb2 from x-block 0)
template <int MODE>
__global__ void __launch_bounds__(256)
mma_gemm_kernel(const float* __restrict__ A, int M, int K,
                const float* __restrict__ Psrc, const float* __restrict__ Pdst,
                const int* __restrict__ src, const int* __restrict__ dst,
                const float* __restrict__ abias,
                const __half* __restrict__ Bh, const __half* __restrict__ Bl,
                float* __restrict__ C, int NTOT,
                const float* __restrict__ eb1, const float* __restrict__ ew2,
                const float* __restrict__ eb2, float* __restrict__ out)
{
    extern __shared__ char smd[];
    __shared__ float red[128];
    const uint32_t sb = smem_u32(smd);
    const int tid  = threadIdx.x;
    const int lane = tid & 31;
    const int wid  = tid >> 5;
    const int wm   = wid >> 2;        // 0..1
    const int wn   = wid & 3;         // 0..3
    const int bm0  = blockIdx.y * 128;
    const int n0   = blockIdx.x * 128;
    const int r    = tid >> 1;        // 0..127 (tile row for loads)
    const int u0   = (tid & 1) * 2;   // 16B-unit base (0 or 2)

    int sn = 0, dn = 0;
    if (MODE == 1) {
        sn = src[bm0 + r];
        dn = dst[bm0 + r];
        if (tid < 128) red[tid] = 0.f;
    }

    float acc[4][4][4];
#pragma unroll
    for (int a = 0; a < 4; a++)
#pragma unroll
        for (int b = 0; b < 4; b++)
#pragma unroll
            for (int c = 0; c < 4; c++) acc[a][b][c] = 0.f;

    const int NC = K >> 5;
    float apre[16];

    auto prefA = [&](int c) {
        const int kb = c * 32 + u0 * 8;           // 16 contiguous k-values
        if (MODE == 0) {
            const int m = bm0 + r;
            if (m < M) {
                const float4* p = reinterpret_cast<const float4*>(A + (size_t)m * K + kb);
#pragma unroll
                for (int i = 0; i < 4; i++) {
                    float4 v = p[i];
                    apre[i * 4 + 0] = v.x; apre[i * 4 + 1] = v.y;
                    apre[i * 4 + 2] = v.z; apre[i * 4 + 3] = v.w;
                }
            } else {
#pragma unroll
                for (int i = 0; i < 16; i++) apre[i] = 0.f;
            }
        } else {
            const float4* ps = reinterpret_cast<const float4*>(Psrc + (size_t)sn * 512 + kb);
            const float4* pd = reinterpret_cast<const float4*>(Pdst + (size_t)dn * 512 + kb);
            const float4* pb = reinterpret_cast<const float4*>(abias + kb);
#pragma unroll
            for (int i = 0; i < 4; i++) {
                float4 a4 = ps[i], b4 = pd[i], c4 = pb[i];
                apre[i * 4 + 0] = a4.x + b4.x + c4.x;
                apre[i * 4 + 1] = a4.y + b4.y + c4.y;
                apre[i * 4 + 2] = a4.z + b4.z + c4.z;
                apre[i * 4 + 3] = a4.w + b4.w + c4.w;
            }
        }
    };

    auto storeA = [&](int s) {
        char* base = smd + s * 40960;
#pragma unroll
        for (int u = 0; u < 2; u++) {
            __half2 h2[4], l2[4];
#pragma unroll
            for (int j = 0; j < 4; j++) {
                float f0 = apre[u * 8 + 2 * j], f1 = apre[u * 8 + 2 * j + 1];
                if (MODE == 1) { f0 = fmaxf(f0, 0.f); f1 = fmaxf(f1, 0.f); }
                __half h0 = __float2half_rn(f0), h1 = __float2half_rn(f1);
                h2[j] = __halves2half2(h0, h1);
                l2[j] = __halves2half2(__float2half_rn(f0 - __half2float(h0)),
                                       __float2half_rn(f1 - __half2float(h1)));
            }
            *reinterpret_cast<uint4*>(base + r * 80 + (u0 + u) * 16) =
                *reinterpret_cast<uint4*>(h2);
            *reinterpret_cast<uint4*>(base + 10240 + r * 80 + (u0 + u) * 16) =
                *reinterpret_cast<uint4*>(l2);
        }
    };

    auto cpB = [&](int c, int s) {
        const size_t go = (size_t)(n0 + r) * K + c * 32;
        const uint32_t db = sb + s * 40960 + 20480 + r * 80;
#pragma unroll
        for (int u = 0; u < 2; u++) {
            cp16(db + (u0 + u) * 16,         Bh + go + (u0 + u) * 8);
            cp16(db + 10240 + (u0 + u) * 16, Bl + go + (u0 + u) * 8);
        }
    };

    auto comp = [&](int s) {
        const uint32_t base = sb + s * 40960;
#pragma unroll
        for (int ks = 0; ks < 2; ks++) {
            uint32_t ah[4][4], al[4][4], bh[4][2], bl[4][2];
            const uint32_t arow = wm * 64 + (lane & 15);
            const uint32_t au = ks * 2 + (lane >> 4);
#pragma unroll
            for (int mt = 0; mt < 4; mt++) {
                const uint32_t ad = base + (arow + mt * 16) * 80 + au * 16;
                ldm_x4(ah[mt], ad);
                ldm_x4(al[mt], ad + 10240);
            }
            const uint32_t brow = wn * 32 + (lane & 7);
            const uint32_t bu = ks * 2 + ((lane >> 3) & 1);
#pragma unroll
            for (int nt = 0; nt < 4; nt++) {
                const uint32_t bd = base + 20480 + (brow + nt * 8) * 80 + bu * 16;
                ldm_x2(bh[nt], bd);
                ldm_x2(bl[nt], bd + 10240);
            }
#pragma unroll
            for (int mt = 0; mt < 4; mt++)
#pragma unroll
                for (int nt = 0; nt < 4; nt++) {
                    mma16816(acc[mt][nt], ah[mt], bh[nt]);   // hi*hi
                    mma16816(acc[mt][nt], ah[mt], bl[nt]);   // hi*lo
                    mma16816(acc[mt][nt], al[mt], bh[nt]);   // lo*hi
                }
        }
    };

    // prologue
    prefA(0); storeA(0); cpB(0, 0);
    CP_COMMIT(); CP_WAIT0();
    __syncthreads();

    for (int c = 0; c < NC; c++) {
        const int s = c & 1;
        if (c + 1 < NC) { prefA(c + 1); cpB(c + 1, s ^ 1); CP_COMMIT(); }
        comp(s);
        if (c + 1 < NC) { storeA(s ^ 1); CP_WAIT0(); }
        __syncthreads();
    }

    // ---------------- epilogue ----------------
    if (MODE == 0) {
#pragma unroll
        for (int mt = 0; mt < 4; mt++) {
            const int row = bm0 + wm * 64 + mt * 16 + (lane >> 2);
#pragma unroll
            for (int nt = 0; nt < 4; nt++) {
                const int col = n0 + wn * 32 + nt * 8 + 2 * (lane & 3);
                if (row < M)
                    *reinterpret_cast<float2*>(C + (size_t)row * NTOT + col) =
                        make_float2(acc[mt][nt][0], acc[mt][nt][1]);
                if (row + 8 < M)
                    *reinterpret_cast<float2*>(C + (size_t)(row + 8) * NTOT + col) =
                        make_float2(acc[mt][nt][2], acc[mt][nt][3]);
            }
        }
    } else {
#pragma unroll
        for (int mt = 0; mt < 4; mt++) {
            float p0 = 0.f, p1 = 0.f;
#pragma unroll
            for (int nt = 0; nt < 4; nt++) {
                const int col = n0 + wn * 32 + nt * 8 + 2 * (lane & 3);
                const float b0 = eb1[col], b1 = eb1[col + 1];
                const float w0 = ew2[col], w1 = ew2[col + 1];
                p0 += fmaxf(acc[mt][nt][0] + b0, 0.f) * w0 + fmaxf(acc[mt][nt][1] + b1, 0.f) * w1;
                p1 += fmaxf(acc[mt][nt][2] + b0, 0.f) * w0 + fmaxf(acc[mt][nt][3] + b1, 0.f) * w1;
            }
            p0 += __shfl_xor_sync(0xffffffffu, p0, 1);
            p0 += __shfl_xor_sync(0xffffffffu, p0, 2);
            p1 += __shfl_xor_sync(0xffffffffu, p1, 1);
            p1 += __shfl_xor_sync(0xffffffffu, p1, 2);
            if ((lane & 3) == 0) {
                atomicAdd(&red[wm * 64 + mt * 16 + (lane >> 2)], p0);
                atomicAdd(&red[wm * 64 + mt * 16 + (lane >> 2) + 8], p1);
            }
        }
        __syncthreads();
        if (tid < 128) {
            float v = red[tid];
            if (blockIdx.x == 0) v += eb2[0];
            atomicAdd(&out[bm0 + tid], v);
        }
    }
}

// ---------------- prep kernels ----------------
__global__ void zbuild_kernel(const float* __restrict__ h1, const float* __restrict__ g2,
                              float* __restrict__ z)
{
    int i = blockIdx.x * blockDim.x + threadIdx.x;
    if (i >= N_NODES * 384) return;
    int n = i / 384, j = i % 384;
    z[i] = (j < 128) ? h1[n * 128 + j] : g2[n * 256 + (j - 128)];
}

// ew0 [768 x 512] -> W0s/W0d transposed [512n x 384k] fp16 hi/lo
__global__ void w0pack_kernel(const float* __restrict__ ew0,
                              __half* __restrict__ sh, __half* __restrict__ sl,
                              __half* __restrict__ dh, __half* __restrict__ dl)
{
    int i = blockIdx.x * blockDim.x + threadIdx.x;
    if (i >= 512 * 384) return;
    int n = i / 384, k = i % 384;
    int rs = (k < 128) ? k : k + 128;        // src blocks: rows 0:128, 256:512
    int rd = (k < 128) ? k + 128 : k + 384;  // dst blocks: rows 128:256, 512:768
    float f = ew0[rs * 512 + n];
    __half h = __float2half_rn(f);
    sh[i] = h; sl[i] = __float2half_rn(f - __half2float(h));
    f = ew0[rd * 512 + n];
    h = __float2half_rn(f);
    dh[i] = h; dl[i] = __float2half_rn(f - __half2float(h));
}

// ew1 [512 x 256] -> transposed [256n x 512k] fp16 hi/lo
__global__ void w1split_kernel(const float* __restrict__ ew1,
                               __half* __restrict__ th, __half* __restrict__ tl)
{
    int i = blockIdx.x * blockDim.x + threadIdx.x;
    if (i >= 256 * 512) return;
    int n = i / 512, k = i % 512;
    float f = ew1[k * 256 + n];
    __half h = __float2half_rn(f);
    th[i] = h; tl[i] = __float2half_rn(f - __half2float(h));
}

__global__ void out_init_kernel(float* __restrict__ out)
{
    int i = blockIdx.x * blockDim.x + threadIdx.x;
    if (i < N_EDGES) out[i] = 0.f;
}

// ---------------- fp32 SIMT GEMM (node-side) ----------------
#define BM 64
#define BN 64
#define BK 16

__global__ void gemm_kernel(const float* __restrict__ A, const float* __restrict__ W,
                            const float* __restrict__ bias, float* __restrict__ C,
                            int M, int N, int K, int in_relu, int out_relu)
{
    __shared__ float As[BK][BM + 4];
    __shared__ float Bs[BK][BN];
    const int tid = threadIdx.x;
    const int m0 = blockIdx.y * BM;
    const int n0 = blockIdx.x * BN;
    const int tx = tid & 15;
    const int ty = tid >> 4;

    float acc[8][4];
#pragma unroll
    for (int j = 0; j < 8; j++)
#pragma unroll
        for (int i = 0; i < 4; i++) acc[j][i] = 0.f;

    const int ar = tid >> 1;
    const int ac = (tid & 1) * 8;
    const int br = tid >> 3;
    const int bc = (tid & 7) * 8;

    for (int k0 = 0; k0 < K; k0 += BK) {
        const bool arow_ok = (m0 + ar) < M;
        const float* Ap = A + (size_t)(m0 + ar) * K + k0 + ac;
#pragma unroll
        for (int i = 0; i < 8; i++) {
            float v = arow_ok ? Ap[i] : 0.f;
            if (in_relu) v = fmaxf(v, 0.f);
            As[ac + i][ar] = v;
        }
        const float* Wp = W + (size_t)(k0 + br) * N + n0 + bc;
#pragma unroll
        for (int i = 0; i < 8; i++) Bs[br][bc + i] = Wp[i];
        __syncthreads();
#pragma unroll
        for (int kk = 0; kk < BK; kk++) {
            const float4* a4 = reinterpret_cast<const float4*>(&As[kk][ty * 8]);
            float4 a0 = a4[0], a1 = a4[1];
            float4 b0 = *reinterpret_cast<const float4*>(&Bs[kk][tx * 4]);
            float a[8] = {a0.x, a0.y, a0.z, a0.w, a1.x, a1.y, a1.z, a1.w};
            float b[4] = {b0.x, b0.y, b0.z, b0.w};
#pragma unroll
            for (int j = 0; j < 8; j++)
#pragma unroll
                for (int i = 0; i < 4; i++) acc[j][i] += a[j] * b[i];
        }
        __syncthreads();
    }
#pragma unroll
    for (int j = 0; j < 8; j++) {
        int row = m0 + ty * 8 + j;
        if (row >= M) continue;
#pragma unroll
        for (int i = 0; i < 4; i++) {
            int col = n0 + tx * 4 + i;
            float v = acc[j][i] + bias[col];
            if (out_relu) v = fmaxf(v, 0.f);
            C[(size_t)row * N + col] = v;
        }
    }
}

// ---------------- GAT kernels (proven in round 1) ----------------
__device__ __forceinline__ void atomicMaxFloat(float* addr, float v)
{
    if (v >= 0.f) atomicMax((int*)addr, __float_as_int(v));
    else          atomicMin((unsigned int*)addr, (unsigned int)__float_as_int(v));
}

__global__ void gat_init_kernel(float* m, float* s, float* acc)
{
    int i = blockIdx.x * blockDim.x + threadIdx.x;
    if (i < N_NODES * 256) acc[i] = 0.f;
    if (i < N_NODES * 2) { m[i] = __int_as_float(0xff800000); s[i] = 0.f; }
}

__global__ void gat_logits_kernel(const float* __restrict__ fs, const float* __restrict__ fd,
                                  const float* __restrict__ attn,
                                  const int* __restrict__ src, const int* __restrict__ dst,
                                  float* __restrict__ logit, float* __restrict__ m)
{
    int warp = (blockIdx.x * blockDim.x + threadIdx.x) >> 5;
    int lane = threadIdx.x & 31;
    if (warp >= N_EDGES) return;
    int sN = src[warp], tN = dst[warp];
#pragma unroll
    for (int h = 0; h < 2; h++) {
        const float* ps = fs + (size_t)sN * 256 + h * 128;
        const float* pd = fd + (size_t)tN * 256 + h * 128;
        const float* pa = attn + h * 128;
        float acc = 0.f;
#pragma unroll
        for (int i = 0; i < 4; i++) {
            int d = lane + 32 * i;
            float v = ps[d] + pd[d];
            v = (v > 0.f) ? v : 0.2f * v;
            acc += v * pa[d];
        }
#pragma unroll
        for (int o = 16; o; o >>= 1) acc += __shfl_xor_sync(0xffffffffu, acc, o);
        if (lane == 0) {
            logit[(size_t)warp * 2 + h] = acc;
            atomicMaxFloat(&m[tN * 2 + h], acc);
        }
    }
}

__global__ void gat_expsum_kernel(const int* __restrict__ dst, float* __restrict__ w,
                                  const float* __restrict__ m, float* __restrict__ s)
{
    int idx = blockIdx.x * blockDim.x + threadIdx.x;
    if (idx >= N_EDGES * 2) return;
    int e = idx >> 1, h = idx & 1;
    int t = dst[e];
    float v = expf(w[idx] - m[t * 2 + h]);
    w[idx] = v;
    atomicAdd(&s[t * 2 + h], v);
}

__global__ void gat_scatter_kernel(const float* __restrict__ fs,
                                   const int* __restrict__ src, const int* __restrict__ dst,
                                   const float* __restrict__ w, const float* __restrict__ s,
                                   float* __restrict__ acc)
{
    int warp = (blockIdx.x * blockDim.x + threadIdx.x) >> 5;
    int lane = threadIdx.x & 31;
    if (warp >= N_EDGES) return;
    int sN = src[warp], tN = dst[warp];
#pragma unroll
    for (int h = 0; h < 2; h++) {
        float coef = w[(size_t)warp * 2 + h] / s[tN * 2 + h];
        const float* ps = fs + (size_t)sN * 256 + h * 128;
        float* pa = acc + (size_t)tN * 256 + h * 128;
#pragma unroll
        for (int i = 0; i < 4; i++) {
            int d = lane + 32 * i;
            atomicAdd(&pa[d], coef * ps[d]);
        }
    }
}

__global__ void gat_relu_kernel(const float* __restrict__ acc, float* __restrict__ out)
{
    int i = blockIdx.x * blockDim.x + threadIdx.x;
    if (i < N_NODES * 256) out[i] = fmaxf(acc[i], 0.f);
}

// ---------------- host launch ----------------
extern "C" void kernel_launch(void* const* d_in, const int* in_sizes, int n_in,
                              void* d_out, int out_size)
{
    const float* x    = (const float*)d_in[0];
    const int*   src  = (const int*)d_in[1];
    const int*   dst  = (const int*)d_in[2];
    const float* nw0  = (const float*)d_in[3];
    const float* nb0  = (const float*)d_in[4];
    const float* nw1  = (const float*)d_in[5];
    const float* nb1  = (const float*)d_in[6];
    const float* g1ws = (const float*)d_in[7];
    const float* g1bs = (const float*)d_in[8];
    const float* g1wd = (const float*)d_in[9];
    const float* g1bd = (const float*)d_in[10];
    const float* g1a  = (const float*)d_in[11];
    const float* g2ws = (const float*)d_in[12];
    const float* g2bs = (const float*)d_in[13];
    const float* g2wd = (const float*)d_in[14];
    const float* g2bd = (const float*)d_in[15];
    const float* g2a  = (const float*)d_in[16];
    const float* ew0  = (const float*)d_in[17];
    const float* eb0  = (const float*)d_in[18];
    const float* ew1  = (const float*)d_in[19];
    const float* eb1  = (const float*)d_in[20];
    const float* ew2  = (const float*)d_in[21];
    const float* eb2  = (const float*)d_in[22];
    float* out = (float*)d_out;

    float *tmp, *h1, *fs, *fd, *gat1, *gat2, *acc, *mB, *sB, *wB, *z, *ps, *pd;
    __half *w0sh, *w0sl, *w0dh, *w0dl, *w1h, *w1l;
    cudaGetSymbolAddress((void**)&tmp,  g_tmp);
    cudaGetSymbolAddress((void**)&h1,   g_h1);
    cudaGetSymbolAddress((void**)&fs,   g_fs);
    cudaGetSymbolAddress((void**)&fd,   g_fd);
    cudaGetSymbolAddress((void**)&gat1, g_gat1);
    cudaGetSymbolAddress((void**)&gat2, g_gat2);
    cudaGetSymbolAddress((void**)&acc,  g_acc);
    cudaGetSymbolAddress((void**)&mB,   g_m);
    cudaGetSymbolAddress((void**)&sB,   g_s);
    cudaGetSymbolAddress((void**)&wB,   g_w);
    cudaGetSymbolAddress((void**)&z,    g_z);
    cudaGetSymbolAddress((void**)&ps,   g_ps);
    cudaGetSymbolAddress((void**)&pd,   g_pd);
    cudaGetSymbolAddress((void**)&w0sh, g_w0sh);
    cudaGetSymbolAddress((void**)&w0sl, g_w0sl);
    cudaGetSymbolAddress((void**)&w0dh, g_w0dh);
    cudaGetSymbolAddress((void**)&w0dl, g_w0dl);
    cudaGetSymbolAddress((void**)&w1h,  g_w1h);
    cudaGetSymbolAddress((void**)&w1l,  g_w1l);

    cudaFuncSetAttribute(mma_gemm_kernel<0>, cudaFuncAttributeMaxDynamicSharedMemorySize, 81920);
    cudaFuncSetAttribute(mma_gemm_kernel<1>, cudaFuncAttributeMaxDynamicSharedMemorySize, 81920);

    const int MB_NODES = (N_NODES + BM - 1) / BM;

    // independent prep
    w0pack_kernel<<<(512 * 384 + 255) / 256, 256>>>(ew0, w0sh, w0sl, w0dh, w0dl);
    w1split_kernel<<<(256 * 512 + 255) / 256, 256>>>(ew1, w1h, w1l);
    out_init_kernel<<<(N_EDGES + 255) / 256, 256>>>(out);

    // NodeMLP
    gemm_kernel<<<dim3(2, MB_NODES), 128>>>(x,   nw0, nb0, tmp, N_NODES, 128, 64,  0, 1);
    gemm_kernel<<<dim3(2, MB_NODES), 128>>>(tmp, nw1, nb1, h1,  N_NODES, 128, 128, 0, 1);

    // GAT layer 1
    gemm_kernel<<<dim3(4, MB_NODES), 128>>>(x, g1ws, g1bs, fs, N_NODES, 256, 64, 0, 0);
    gemm_kernel<<<dim3(4, MB_NODES), 128>>>(x, g1wd, g1bd, fd, N_NODES, 256, 64, 0, 0);
    gat_init_kernel<<<(N_NODES * 256 + 255) / 256, 256>>>(mB, sB, acc);
    gat_logits_kernel<<<N_EDGES / 8, 256>>>(fs, fd, g1a, src, dst, wB, mB);
    gat_expsum_kernel<<<(N_EDGES * 2 + 255) / 256, 256>>>(dst, wB, mB, sB);
    gat_scatter_kernel<<<N_EDGES / 8, 256>>>(fs, src, dst, wB, sB, acc);
    gat_relu_kernel<<<(N_NODES * 256 + 255) / 256, 256>>>(acc, gat1);

    // GAT layer 2
    gemm_kernel<<<dim3(4, MB_NODES), 128>>>(gat1, g2ws, g2bs, fs, N_NODES, 256, 256, 0, 0);
    gemm_kernel<<<dim3(4, MB_NODES), 128>>>(gat1, g2wd, g2bd, fd, N_NODES, 256, 256, 0, 0);
    gat_init_kernel<<<(N_NODES * 256 + 255) / 256, 256>>>(mB, sB, acc);
    gat_logits_kernel<<<N_EDGES / 8, 256>>>(fs, fd, g2a, src, dst, wB, mB);
    gat_expsum_kernel<<<(N_EDGES * 2 + 255) / 256, 256>>>(dst, wB, mB, sB);
    gat_scatter_kernel<<<N_EDGES / 8, 256>>>(fs, src, dst, wB, sB, acc);
    gat_relu_kernel<<<(N_NODES * 256 + 255) / 256, 256>>>(acc, gat2);

    // Z = [h1 | gat2]; Psrc/Pdst node-level GEMMs (HMMA, fp16 split)
    zbuild_kernel<<<(N_NODES * 384 + 255) / 256, 256>>>(h1, gat2, z);
    const int MBY = (N_NODES + 127) / 128;
    mma_gemm_kernel<0><<<dim3(4, MBY), 256, 81920>>>(
        z, N_NODES, 384, nullptr, nullptr, nullptr, nullptr, nullptr,
        w0sh, w0sl, ps, 512, nullptr, nullptr, nullptr, nullptr);
    mma_gemm_kernel<0><<<dim3(4, MBY), 256, 81920>>>(
        z, N_NODES, 384, nullptr, nullptr, nullptr, nullptr, nullptr,
        w0dh, w0dl, pd, 512, nullptr, nullptr, nullptr, nullptr);

    // EdgeMLP layers 2+3 fused (HMMA, gathered A, reduce epilogue)
    mma_gemm_kernel<1><<<dim3(2, N_EDGES / 128), 256, 81920>>>(
        nullptr, N_EDGES, 512, ps, pd, src, dst, eb0,
        w1h, w1l, nullptr, 256, eb1, ew2, eb2, out);
}

// round 4
// speedup vs baseline: 5.8056x; 1.1744x over previous
#include <cuda_runtime.h>
#include <cuda_fp16.h>
#include <cstdint>

#define N_NODES 20000
#define N_EDGES 320000

// ---------------- scratch (device globals: allocation-free) ----------------
__device__ float g_tmp [N_NODES * 128];
__device__ float g_h1  [N_NODES * 128];
__device__ float g_fsd [N_NODES * 512];    // [fs | fd] per node
__device__ float g_acc [N_NODES * 256];
__device__ float g_s   [N_NODES * 2];
__device__ float g_w   [N_EDGES * 2];
__device__ float g_z   [N_NODES * 384];    // [h1 | relu(gat2)]
__device__ float g_p   [N_NODES * 1024];   // [Psrc | Pdst] per node
// fp16 hi/lo split weights (all transposed to [N x K])
__device__ __half g_nw0h[128 * 64],   g_nw0l[128 * 64];
__device__ __half g_nw1h[128 * 128],  g_nw1l[128 * 128];
__device__ __half g_g1h [512 * 64],   g_g1l [512 * 64];    // [g1ws|g1wd]
__device__ __half g_g2h [512 * 256],  g_g2l [512 * 256];   // [g2ws|g2wd]
__device__ __half g_w0h [1024 * 384], g_w0l [1024 * 384];  // [W0src|W0dst]
__device__ __half g_w1h [256 * 512],  g_w1l [256 * 512];
__device__ float  g_b1cat[512], g_b2cat[512];

// ---------------- PTX helpers (base ISA only) ----------------
__device__ __forceinline__ uint32_t smem_u32(const void* p) {
    uint32_t a;
    asm("{ .reg .u64 t; cvta.to.shared.u64 t, %1; cvt.u32.u64 %0, t; }" : "=r"(a) : "l"(p));
    return a;
}
__device__ __forceinline__ void ldm_x4(uint32_t* r, uint32_t a) {
    asm volatile("ldmatrix.sync.aligned.m8n8.x4.shared.b16 {%0,%1,%2,%3}, [%4];"
                 : "=r"(r[0]), "=r"(r[1]), "=r"(r[2]), "=r"(r[3]) : "r"(a));
}
__device__ __forceinline__ void ldm_x2(uint32_t* r, uint32_t a) {
    asm volatile("ldmatrix.sync.aligned.m8n8.x2.shared.b16 {%0,%1}, [%2];"
                 : "=r"(r[0]), "=r"(r[1]) : "r"(a));
}
__device__ __forceinline__ void mma_f32(float* c, const uint32_t* a, const uint32_t* b) {
    asm volatile("mma.sync.aligned.m16n8k16.row.col.f32.f16.f16.f32 "
                 "{%0,%1,%2,%3}, {%4,%5,%6,%7}, {%8,%9}, {%0,%1,%2,%3};"
                 : "+f"(c[0]), "+f"(c[1]), "+f"(c[2]), "+f"(c[3])
                 : "r"(a[0]), "r"(a[1]), "r"(a[2]), "r"(a[3]), "r"(b[0]), "r"(b[1]));
}
__device__ __forceinline__ void mma_f16(uint32_t* c, const uint32_t* a, const uint32_t* b) {
    asm volatile("mma.sync.aligned.m16n8k16.row.col.f16.f16.f16.f16 "
                 "{%0,%1}, {%2,%3,%4,%5}, {%6,%7}, {%0,%1};"
                 : "+r"(c[0]), "+r"(c[1])
                 : "r"(a[0]), "r"(a[1]), "r"(a[2]), "r"(a[3]), "r"(b[0]), "r"(b[1]));
}
__device__ __forceinline__ void cp16(uint32_t d, const void* s) {
    asm volatile("cp.async.cg.shared.global [%0], [%1], 16;" :: "r"(d), "l"(s));
}
#define CP_COMMIT() asm volatile("cp.async.commit_group;")
#define CP_WAIT0()  asm volatile("cp.async.wait_group 0;")

// ---------------- unified HMMA GEMM, fp16 3-term split ----------------
// hi*hi in fp32 acc; cross terms (hi*lo + lo*hi) share one fp16 acc (2x rate).
// BM=128, BN=128, BK=32, 256 threads (2Mx4N warps), warp tile 64x32.
// smem per stage 40960B: A_hi@0, A_lo@10240, B_hi@20480, B_lo@30720 (80B row stride).
// MODE 0: A fp32 [MxK] (optional in_relu); epilogue C = [relu](acc + bias).
// MODE 1: A(e,k) = relu(P[src[e]][k] + P[dst[e]][512+k] + abias[k]);
//         epilogue out[e] += sum_col relu(acc + eb1[col]) * ew2[col] (+eb2 on x=0).
template <int MODE>
__global__ void __launch_bounds__(256)
mma_gemm_kernel(const float* __restrict__ A, int M, int K,
                const float* __restrict__ P,
                const int* __restrict__ src, const int* __restrict__ dst,
                const float* __restrict__ abias,
                const __half* __restrict__ Bh, const __half* __restrict__ Bl,
                const float* __restrict__ bias, int in_relu, int out_relu,
                float* __restrict__ C, int NTOT,
                const float* __restrict__ eb1, const float* __restrict__ ew2,
                const float* __restrict__ eb2, float* __restrict__ out)
{
    extern __shared__ char smd[];
    __shared__ float red[128];
    const uint32_t sb = smem_u32(smd);
    const int tid  = threadIdx.x;
    const int lane = tid & 31;
    const int wid  = tid >> 5;
    const int wm   = wid >> 2;
    const int wn   = wid & 3;
    const int bm0  = blockIdx.y * 128;
    const int n0   = blockIdx.x * 128;
    const int r    = tid >> 1;
    const int u0   = (tid & 1) * 2;

    int sn = 0, dn = 0;
    if (MODE == 1) {
        sn = src[bm0 + r];
        dn = dst[bm0 + r];
        if (tid < 128) red[tid] = 0.f;
    }

    float acc[4][4][4];
    uint32_t acx[4][4][2];
#pragma unroll
    for (int a = 0; a < 4; a++)
#pragma unroll
        for (int b = 0; b < 4; b++) {
#pragma unroll
            for (int c = 0; c < 4; c++) acc[a][b][c] = 0.f;
            acx[a][b][0] = 0u; acx[a][b][1] = 0u;
        }

    const int NC = K >> 5;
    float apre[16];

    auto prefA = [&](int c) {
        const int kb = c * 32 + u0 * 8;
        if (MODE == 0) {
            const int m = bm0 + r;
            if (m < M) {
                const float4* p = reinterpret_cast<const float4*>(A + (size_t)m * K + kb);
#pragma unroll
                for (int i = 0; i < 4; i++) {
                    float4 v = p[i];
                    apre[i * 4 + 0] = v.x; apre[i * 4 + 1] = v.y;
                    apre[i * 4 + 2] = v.z; apre[i * 4 + 3] = v.w;
                }
                if (in_relu) {
#pragma unroll
                    for (int i = 0; i < 16; i++) apre[i] = fmaxf(apre[i], 0.f);
                }
            } else {
#pragma unroll
                for (int i = 0; i < 16; i++) apre[i] = 0.f;
            }
        } else {
            const float4* ps = reinterpret_cast<const float4*>(P + (size_t)sn * 1024 + kb);
            const float4* pd = reinterpret_cast<const float4*>(P + (size_t)dn * 1024 + 512 + kb);
            const float4* pb = reinterpret_cast<const float4*>(abias + kb);
#pragma unroll
            for (int i = 0; i < 4; i++) {
                float4 a4 = ps[i], b4 = pd[i], c4 = pb[i];
                apre[i * 4 + 0] = fmaxf(a4.x + b4.x + c4.x, 0.f);
                apre[i * 4 + 1] = fmaxf(a4.y + b4.y + c4.y, 0.f);
                apre[i * 4 + 2] = fmaxf(a4.z + b4.z + c4.z, 0.f);
                apre[i * 4 + 3] = fmaxf(a4.w + b4.w + c4.w, 0.f);
            }
        }
    };

    auto storeA = [&](int s) {
        char* base = smd + s * 40960;
#pragma unroll
        for (int u = 0; u < 2; u++) {
            __half2 h2[4], l2[4];
#pragma unroll
            for (int j = 0; j < 4; j++) {
                float f0 = apre[u * 8 + 2 * j], f1 = apre[u * 8 + 2 * j + 1];
                __half h0 = __float2half_rn(f0), h1 = __float2half_rn(f1);
                h2[j] = __halves2half2(h0, h1);
                l2[j] = __halves2half2(__float2half_rn(f0 - __half2float(h0)),
                                       __float2half_rn(f1 - __half2float(h1)));
            }
            *reinterpret_cast<uint4*>(base + r * 80 + (u0 + u) * 16) =
                *reinterpret_cast<uint4*>(h2);
            *reinterpret_cast<uint4*>(base + 10240 + r * 80 + (u0 + u) * 16) =
                *reinterpret_cast<uint4*>(l2);
        }
    };

    auto cpB = [&](int c, int s) {
        const size_t go = (size_t)(n0 + r) * K + c * 32;
        const uint32_t db = sb + s * 40960 + 20480 + r * 80;
#pragma unroll
        for (int u = 0; u < 2; u++) {
            cp16(db + (u0 + u) * 16,         Bh + go + (u0 + u) * 8);
            cp16(db + 10240 + (u0 + u) * 16, Bl + go + (u0 + u) * 8);
        }
    };

    auto comp = [&](int s) {
        const uint32_t base = sb + s * 40960;
#pragma unroll
        for (int ks = 0; ks < 2; ks++) {
            uint32_t ah[4][4], al[4][4], bh[4][2], bl[4][2];
            const uint32_t arow = wm * 64 + (lane & 15);
            const uint32_t au = ks * 2 + (lane >> 4);
#pragma unroll
            for (int mt = 0; mt < 4; mt++) {
                const uint32_t ad = base + (arow + mt * 16) * 80 + au * 16;
                ldm_x4(ah[mt], ad);
                ldm_x4(al[mt], ad + 10240);
            }
            const uint32_t brow = wn * 32 + (lane & 7);
            const uint32_t bu = ks * 2 + ((lane >> 3) & 1);
#pragma unroll
            for (int nt = 0; nt < 4; nt++) {
                const uint32_t bd = base + 20480 + (brow + nt * 8) * 80 + bu * 16;
                ldm_x2(bh[nt], bd);
                ldm_x2(bl[nt], bd + 10240);
            }
#pragma unroll
            for (int mt = 0; mt < 4; mt++)
#pragma unroll
                for (int nt = 0; nt < 4; nt++) {
                    mma_f32(acc[mt][nt], ah[mt], bh[nt]);   // hi*hi (fp32 acc)
                    mma_f16(acx[mt][nt], ah[mt], bl[nt]);   // cross (fp16 acc)
                    mma_f16(acx[mt][nt], al[mt], bh[nt]);   // cross (fp16 acc)
                }
        }
    };

    prefA(0); storeA(0); cpB(0, 0);
    CP_COMMIT(); CP_WAIT0();
    __syncthreads();

    for (int c = 0; c < NC; c++) {
        const int s = c & 1;
        if (c + 1 < NC) { prefA(c + 1); cpB(c + 1, s ^ 1); CP_COMMIT(); }
        comp(s);
        if (c + 1 < NC) { storeA(s ^ 1); CP_WAIT0(); }
        __syncthreads();
    }

    // fold fp16 cross accumulators into fp32
#pragma unroll
    for (int mt = 0; mt < 4; mt++)
#pragma unroll
        for (int nt = 0; nt < 4; nt++) {
            float2 f0 = __half22float2(*reinterpret_cast<__half2*>(&acx[mt][nt][0]));
            float2 f1 = __half22float2(*reinterpret_cast<__half2*>(&acx[mt][nt][1]));
            acc[mt][nt][0] += f0.x; acc[mt][nt][1] += f0.y;
            acc[mt][nt][2] += f1.x; acc[mt][nt][3] += f1.y;
        }

    if (MODE == 0) {
#pragma unroll
        for (int mt = 0; mt < 4; mt++) {
            const int row = bm0 + wm * 64 + mt * 16 + (lane >> 2);
#pragma unroll
            for (int nt = 0; nt < 4; nt++) {
                const int col = n0 + wn * 32 + nt * 8 + 2 * (lane & 3);
                float b0 = bias ? bias[col] : 0.f;
                float b1 = bias ? bias[col + 1] : 0.f;
                float v0 = acc[mt][nt][0] + b0, v1 = acc[mt][nt][1] + b1;
                float v2 = acc[mt][nt][2] + b0, v3 = acc[mt][nt][3] + b1;
                if (out_relu) {
                    v0 = fmaxf(v0, 0.f); v1 = fmaxf(v1, 0.f);
                    v2 = fmaxf(v2, 0.f); v3 = fmaxf(v3, 0.f);
                }
                if (row < M)
                    *reinterpret_cast<float2*>(C + (size_t)row * NTOT + col) = make_float2(v0, v1);
                if (row + 8 < M)
                    *reinterpret_cast<float2*>(C + (size_t)(row + 8) * NTOT + col) = make_float2(v2, v3);
            }
        }
    } else {
#pragma unroll
        for (int mt = 0; mt < 4; mt++) {
            float p0 = 0.f, p1 = 0.f;
#pragma unroll
            for (int nt = 0; nt < 4; nt++) {
                const int col = n0 + wn * 32 + nt * 8 + 2 * (lane & 3);
                const float b0 = eb1[col], b1 = eb1[col + 1];
                const float w0 = ew2[col], w1 = ew2[col + 1];
                p0 += fmaxf(acc[mt][nt][0] + b0, 0.f) * w0 + fmaxf(acc[mt][nt][1] + b1, 0.f) * w1;
                p1 += fmaxf(acc[mt][nt][2] + b0, 0.f) * w0 + fmaxf(acc[mt][nt][3] + b1, 0.f) * w1;
            }
            p0 += __shfl_xor_sync(0xffffffffu, p0, 1);
            p0 += __shfl_xor_sync(0xffffffffu, p0, 2);
            p1 += __shfl_xor_sync(0xffffffffu, p1, 1);
            p1 += __shfl_xor_sync(0xffffffffu, p1, 2);
            if ((lane & 3) == 0) {
                atomicAdd(&red[wm * 64 + mt * 16 + (lane >> 2)], p0);
                atomicAdd(&red[wm * 64 + mt * 16 + (lane >> 2) + 8], p1);
            }
        }
        __syncthreads();
        if (tid < 128) {
            float v = red[tid];
            if (blockIdx.x == 0) v += eb2[0];
            atomicAdd(&out[bm0 + tid], v);
        }
    }
}

// ---------------- prep kernels ----------------
// W [K x N] fp32 -> th/tl [N x K] fp16 hi/lo (th/tl may be pre-offset for concat)
__global__ void wsplit_kernel(const float* __restrict__ W,
                              __half* __restrict__ th, __half* __restrict__ tl,
                              int K, int N)
{
    int i = blockIdx.x * blockDim.x + threadIdx.x;
    if (i >= K * N) return;
    int n = i / K, k = i % K;
    float f = W[(size_t)k * N + n];
    __half h = __float2half_rn(f);
    th[i] = h; tl[i] = __float2half_rn(f - __half2float(h));
}

// ew0 [768 x 512] -> [1024n x 384k]: n<512 from src rows (0:128,256:512),
// n>=512 from dst rows (128:256, 512:768)
__global__ void w0pack_kernel(const float* __restrict__ ew0,
                              __half* __restrict__ th, __half* __restrict__ tl)
{
    int i = blockIdx.x * blockDim.x + threadIdx.x;
    if (i >= 512 * 384) return;
    int n = i / 384, k = i % 384;
    int rs = (k < 128) ? k : k + 128;
    int rd = (k < 128) ? k + 128 : k + 384;
    float f = ew0[rs * 512 + n];
    __half h = __float2half_rn(f);
    th[i] = h; tl[i] = __float2half_rn(f - __half2float(h));
    f = ew0[rd * 512 + n];
    h = __float2half_rn(f);
    th[512 * 384 + i] = h;
    tl[512 * 384 + i] = __float2half_rn(f - __half2float(h));
}

__global__ void bcat_kernel(const float* a, const float* b, float* o, int n)
{
    int i = blockIdx.x * blockDim.x + threadIdx.x;
    if (i < n) o[i] = a[i];
    else if (i < 2 * n) o[i] = b[i - n];
}

__global__ void zbuild_kernel(const float* __restrict__ h1, const float* __restrict__ a2,
                              float* __restrict__ z)
{
    int i = blockIdx.x * blockDim.x + threadIdx.x;
    if (i >= N_NODES * 384) return;
    int n = i / 384, j = i % 384;
    z[i] = (j < 128) ? h1[n * 128 + j] : fmaxf(a2[n * 256 + (j - 128)], 0.f);
}

__global__ void out_init_kernel(float* __restrict__ out)
{
    int i = blockIdx.x * blockDim.x + threadIdx.x;
    if (i < N_EDGES) out[i] = 0.f;
}

// ---------------- GAT kernels ----------------
__global__ void gat_init_kernel(float* s, float* acc)
{
    int i = blockIdx.x * blockDim.x + threadIdx.x;
    if (i < N_NODES * 256) acc[i] = 0.f;
    if (i < N_NODES * 2) s[i] = 0.f;
}

// merged: logit -> exp -> segment sum (no max pass; fp32 range is sufficient)
__global__ void gat_att_kernel(const float* __restrict__ fsd,
                               const float* __restrict__ attn,
                               const int* __restrict__ src, const int* __restrict__ dst,
                               float* __restrict__ w, float* __restrict__ s)
{
    int e = (blockIdx.x * blockDim.x + threadIdx.x) >> 5;
    int lane = threadIdx.x & 31;
    if (e >= N_EDGES) return;
    int sN = src[e], tN = dst[e];
#pragma unroll
    for (int h = 0; h < 2; h++) {
        float4 a = *reinterpret_cast<const float4*>(fsd + (size_t)sN * 512 + h * 128 + lane * 4);
        float4 b = *reinterpret_cast<const float4*>(fsd + (size_t)tN * 512 + 256 + h * 128 + lane * 4);
        float4 t = *reinterpret_cast<const float4*>(attn + h * 128 + lane * 4);
        float v0 = a.x + b.x, v1 = a.y + b.y, v2 = a.z + b.z, v3 = a.w + b.w;
        v0 = (v0 > 0.f) ? v0 : 0.2f * v0;
        v1 = (v1 > 0.f) ? v1 : 0.2f * v1;
        v2 = (v2 > 0.f) ? v2 : 0.2f * v2;
        v3 = (v3 > 0.f) ? v3 : 0.2f * v3;
        float acc = v0 * t.x + v1 * t.y + v2 * t.z + v3 * t.w;
#pragma unroll
        for (int o = 16; o; o >>= 1) acc += __shfl_xor_sync(0xffffffffu, acc, o);
        if (lane == 0) {
            float ev = expf(acc);
            w[(size_t)e * 2 + h] = ev;
            atomicAdd(&s[tN * 2 + h], ev);
        }
    }
}

// acc[dst] += (w/s) * fs[src], float4 atomics (sm_90+)
__global__ void gat_scatter_kernel(const float* __restrict__ fsd,
                                   const int* __restrict__ src, const int* __restrict__ dst,
                                   const float* __restrict__ w, const float* __restrict__ s,
                                   float* __restrict__ acc)
{
    int e = (blockIdx.x * blockDim.x + threadIdx.x) >> 5;
    int lane = threadIdx.x & 31;
    if (e >= N_EDGES) return;
    int sN = src[e], tN = dst[e];
#pragma unroll
    for (int h = 0; h < 2; h++) {
        float coef = w[(size_t)e * 2 + h] / s[tN * 2 + h];
        float4 v = *reinterpret_cast<const float4*>(fsd + (size_t)sN * 512 + h * 128 + lane * 4);
        v.x *= coef; v.y *= coef; v.z *= coef; v.w *= coef;
        atomicAdd(reinterpret_cast<float4*>(acc + (size_t)tN * 256 + h * 128 + lane * 4), v);
    }
}

// ---------------- host launch ----------------
extern "C" void kernel_launch(void* const* d_in, const int* in_sizes, int n_in,
                              void* d_out, int out_size)
{
    const float* x    = (const float*)d_in[0];
    const int*   src  = (const int*)d_in[1];
    const int*   dst  = (const int*)d_in[2];
    const float* nw0  = (const float*)d_in[3];
    const float* nb0  = (const float*)d_in[4];
    const float* nw1  = (const float*)d_in[5];
    const float* nb1  = (const float*)d_in[6];
    const float* g1ws = (const float*)d_in[7];
    const float* g1bs = (const float*)d_in[8];
    const float* g1wd = (const float*)d_in[9];
    const float* g1bd = (const float*)d_in[10];
    const float* g1a  = (const float*)d_in[11];
    const float* g2ws = (const float*)d_in[12];
    const float* g2bs = (const float*)d_in[13];
    const float* g2wd = (const float*)d_in[14];
    const float* g2bd = (const float*)d_in[15];
    const float* g2a  = (const float*)d_in[16];
    const float* ew0  = (const float*)d_in[17];
    const float* eb0  = (const float*)d_in[18];
    const float* ew1  = (const float*)d_in[19];
    const float* eb1  = (const float*)d_in[20];
    const float* ew2  = (const float*)d_in[21];
    const float* eb2  = (const float*)d_in[22];
    float* out = (float*)d_out;

    float *tmp, *h1, *fsd, *acc, *sB, *wB, *z, *P, *b1c, *b2c;
    __half *nw0h, *nw0l, *nw1h, *nw1l, *g1h, *g1l, *g2h, *g2l, *w0h, *w0l, *w1h, *w1l;
    cudaGetSymbolAddress((void**)&tmp,  g_tmp);
    cudaGetSymbolAddress((void**)&h1,   g_h1);
    cudaGetSymbolAddress((void**)&fsd,  g_fsd);
    cudaGetSymbolAddress((void**)&acc,  g_acc);
    cudaGetSymbolAddress((void**)&sB,   g_s);
    cudaGetSymbolAddress((void**)&wB,   g_w);
    cudaGetSymbolAddress((void**)&z,    g_z);
    cudaGetSymbolAddress((void**)&P,    g_p);
    cudaGetSymbolAddress((void**)&b1c,  g_b1cat);
    cudaGetSymbolAddress((void**)&b2c,  g_b2cat);
    cudaGetSymbolAddress((void**)&nw0h, g_nw0h);
    cudaGetSymbolAddress((void**)&nw0l, g_nw0l);
    cudaGetSymbolAddress((void**)&nw1h, g_nw1h);
    cudaGetSymbolAddress((void**)&nw1l, g_nw1l);
    cudaGetSymbolAddress((void**)&g1h,  g_g1h);
    cudaGetSymbolAddress((void**)&g1l,  g_g1l);
    cudaGetSymbolAddress((void**)&g2h,  g_g2h);
    cudaGetSymbolAddress((void**)&g2l,  g_g2l);
    cudaGetSymbolAddress((void**)&w0h,  g_w0h);
    cudaGetSymbolAddress((void**)&w0l,  g_w0l);
    cudaGetSymbolAddress((void**)&w1h,  g_w1h);
    cudaGetSymbolAddress((void**)&w1l,  g_w1l);

    cudaFuncSetAttribute(mma_gemm_kernel<0>, cudaFuncAttributeMaxDynamicSharedMemorySize, 81920);
    cudaFuncSetAttribute(mma_gemm_kernel<1>, cudaFuncAttributeMaxDynamicSharedMemorySize, 81920);

    // ---- prep (weight splits, bias concats, out init) ----
    wsplit_kernel<<<(128 * 64 + 255) / 256, 256>>>(nw0, nw0h, nw0l, 64, 128);
    wsplit_kernel<<<(128 * 128 + 255) / 256, 256>>>(nw1, nw1h, nw1l, 128, 128);
    wsplit_kernel<<<(256 * 64 + 255) / 256, 256>>>(g1ws, g1h, g1l, 64, 256);
    wsplit_kernel<<<(256 * 64 + 255) / 256, 256>>>(g1wd, g1h + 256 * 64, g1l + 256 * 64, 64, 256);
    wsplit_kernel<<<(256 * 256 + 255) / 256, 256>>>(g2ws, g2h, g2l, 256, 256);
    wsplit_kernel<<<(256 * 256 + 255) / 256, 256>>>(g2wd, g2h + 256 * 256, g2l + 256 * 256, 256, 256);
    w0pack_kernel<<<(512 * 384 + 255) / 256, 256>>>(ew0, w0h, w0l);
    wsplit_kernel<<<(256 * 512 + 255) / 256, 256>>>(ew1, w1h, w1l, 512, 256);
    bcat_kernel<<<2, 256>>>(g1bs, g1bd, b1c, 256);
    bcat_kernel<<<2, 256>>>(g2bs, g2bd, b2c, 256);
    out_init_kernel<<<(N_EDGES + 255) / 256, 256>>>(out);

    const int MBY = (N_NODES + 127) / 128;   // 157

    // ---- NodeMLP ----
    mma_gemm_kernel<0><<<dim3(1, MBY), 256, 81920>>>(
        x, N_NODES, 64, nullptr, nullptr, nullptr, nullptr,
        nw0h, nw0l, nb0, 0, 1, tmp, 128, nullptr, nullptr, nullptr, nullptr);
    mma_gemm_kernel<0><<<dim3(1, MBY), 256, 81920>>>(
        tmp, N_NODES, 128, nullptr, nullptr, nullptr, nullptr,
        nw1h, nw1l, nb1, 0, 1, h1, 128, nullptr, nullptr, nullptr, nullptr);

    // ---- GAT layer 1 ----
    mma_gemm_kernel<0><<<dim3(4, MBY), 256, 81920>>>(
        x, N_NODES, 64, nullptr, nullptr, nullptr, nullptr,
        g1h, g1l, b1c, 0, 0, fsd, 512, nullptr, nullptr, nullptr, nullptr);
    gat_init_kernel<<<(N_NODES * 256 + 255) / 256, 256>>>(sB, acc);
    gat_att_kernel<<<N_EDGES / 8, 256>>>(fsd, g1a, src, dst, wB, sB);
    gat_scatter_kernel<<<N_EDGES / 8, 256>>>(fsd, src, dst, wB, sB, acc);

    // ---- GAT layer 2 (input = relu(acc) inside GEMM) ----
    mma_gemm_kernel<0><<<dim3(4, MBY), 256, 81920>>>(
        acc, N_NODES, 256, nullptr, nullptr, nullptr, nullptr,
        g2h, g2l, b2c, 1, 0, fsd, 512, nullptr, nullptr, nullptr, nullptr);
    gat_init_kernel<<<(N_NODES * 256 + 255) / 256, 256>>>(sB, acc);
    gat_att_kernel<<<N_EDGES / 8, 256>>>(fsd, g2a, src, dst, wB, sB);
    gat_scatter_kernel<<<N_EDGES / 8, 256>>>(fsd, src, dst, wB, sB, acc);

    // ---- Z = [h1 | relu(gat2)], P = Z @ [W0s|W0d] ----
    zbuild_kernel<<<(N_NODES * 384 + 255) / 256, 256>>>(h1, acc, z);
    mma_gemm_kernel<0><<<dim3(8, MBY), 256, 81920>>>(
        z, N_NODES, 384, nullptr, nullptr, nullptr, nullptr,
        w0h, w0l, nullptr, 0, 0, P, 1024, nullptr, nullptr, nullptr, nullptr);

    // ---- EdgeMLP layers 2+3 fused (gathered A, reduce epilogue) ----
    mma_gemm_kernel<1><<<dim3(2, N_EDGES / 128), 256, 81920>>>(
        nullptr, N_EDGES, 512, P, src, dst, eb0,
        w1h, w1l, nullptr, 0, 0, nullptr, 256, eb1, ew2, eb2, out);
}

// round 5
// speedup vs baseline: 6.0716x; 1.0458x over previous
#include <cuda_runtime.h>
#include <cuda_fp16.h>
#include <cstdint>

#define N_NODES 20000
#define N_EDGES 320000

// ---------------- scratch (device globals: allocation-free) ----------------
__device__ float g_tmp [N_NODES * 128];
__device__ float g_h1  [N_NODES * 128];
__device__ float g_fsd [N_NODES * 512];    // [fs | fd] per node
__device__ float g_acc [N_NODES * 256];    // unnormalized segment sum
__device__ float g_s   [N_NODES * 2];      // segment exp-sum
__device__ float g_z   [N_NODES * 384];    // [h1 | gat2]
__device__ float g_p   [N_NODES * 1024];   // [Psrc | Pdst]
__device__ __half g_nw0h[128 * 64],   g_nw0l[128 * 64];
__device__ __half g_nw1h[128 * 128],  g_nw1l[128 * 128];
__device__ __half g_g1h [512 * 64],   g_g1l [512 * 64];
__device__ __half g_g2h [512 * 256],  g_g2l [512 * 256];
__device__ __half g_w0h [1024 * 384], g_w0l [1024 * 384];
__device__ __half g_w1h [256 * 512],  g_w1l [256 * 512];
__device__ float  g_b1cat[512], g_b2cat[512];

// ---------------- PTX helpers ----------------
__device__ __forceinline__ uint32_t smem_u32(const void* p) {
    uint32_t a;
    asm("{ .reg .u64 t; cvta.to.shared.u64 t, %1; cvt.u32.u64 %0, t; }" : "=r"(a) : "l"(p));
    return a;
}
__device__ __forceinline__ void ldm_x4(uint32_t* r, uint32_t a) {
    asm volatile("ldmatrix.sync.aligned.m8n8.x4.shared.b16 {%0,%1,%2,%3}, [%4];"
                 : "=r"(r[0]), "=r"(r[1]), "=r"(r[2]), "=r"(r[3]) : "r"(a));
}
__device__ __forceinline__ void ldm_x2(uint32_t* r, uint32_t a) {
    asm volatile("ldmatrix.sync.aligned.m8n8.x2.shared.b16 {%0,%1}, [%2];"
                 : "=r"(r[0]), "=r"(r[1]) : "r"(a));
}
__device__ __forceinline__ void mma_f32(float* c, const uint32_t* a, const uint32_t* b) {
    asm volatile("mma.sync.aligned.m16n8k16.row.col.f32.f16.f16.f32 "
                 "{%0,%1,%2,%3}, {%4,%5,%6,%7}, {%8,%9}, {%0,%1,%2,%3};"
                 : "+f"(c[0]), "+f"(c[1]), "+f"(c[2]), "+f"(c[3])
                 : "r"(a[0]), "r"(a[1]), "r"(a[2]), "r"(a[3]), "r"(b[0]), "r"(b[1]));
}
__device__ __forceinline__ void mma_f16(uint32_t* c, const uint32_t* a, const uint32_t* b) {
    asm volatile("mma.sync.aligned.m16n8k16.row.col.f16.f16.f16.f16 "
                 "{%0,%1}, {%2,%3,%4,%5}, {%6,%7}, {%0,%1};"
                 : "+r"(c[0]), "+r"(c[1])
                 : "r"(a[0]), "r"(a[1]), "r"(a[2]), "r"(a[3]), "r"(b[0]), "r"(b[1]));
}
__device__ __forceinline__ void cp16(uint32_t d, const void* s) {
    asm volatile("cp.async.cg.shared.global [%0], [%1], 16;" :: "r"(d), "l"(s));
}
#define CP_COMMIT() asm volatile("cp.async.commit_group;")
#define CP_WAIT0()  asm volatile("cp.async.wait_group 0;")

// ================= MODE-0 HMMA GEMM (node-side), fp16 3-term split =================
// BM=128, BN=128, BK=32, 256 threads (2Mx4N warps), warp tile 64x32.
// Optional rowscale: A(m,k) -> A(m,k) / rowscale[m*2 + (k>=128)] before relu.
__global__ void __launch_bounds__(256)
mma_gemm_kernel(const float* __restrict__ A, int M, int K,
                const __half* __restrict__ Bh, const __half* __restrict__ Bl,
                const float* __restrict__ bias, int in_relu, int out_relu,
                const float* __restrict__ rowscale,
                float* __restrict__ C, int NTOT)
{
    extern __shared__ char smd[];
    const uint32_t sb = smem_u32(smd);
    const int tid  = threadIdx.x;
    const int lane = tid & 31;
    const int wid  = tid >> 5;
    const int wm   = wid >> 2;
    const int wn   = wid & 3;
    const int bm0  = blockIdx.y * 128;
    const int n0   = blockIdx.x * 128;
    const int r    = tid >> 1;
    const int u0   = (tid & 1) * 2;

    float acc[4][4][4];
    uint32_t acx[4][4][2];
#pragma unroll
    for (int a = 0; a < 4; a++)
#pragma unroll
        for (int b = 0; b < 4; b++) {
#pragma unroll
            for (int c = 0; c < 4; c++) acc[a][b][c] = 0.f;
            acx[a][b][0] = 0u; acx[a][b][1] = 0u;
        }

    const int NC = K >> 5;
    float apre[16];

    auto prefA = [&](int c) {
        const int kb = c * 32 + u0 * 8;
        const int m = bm0 + r;
        if (m < M) {
            const float4* p = reinterpret_cast<const float4*>(A + (size_t)m * K + kb);
#pragma unroll
            for (int i = 0; i < 4; i++) {
                float4 v = p[i];
                apre[i * 4 + 0] = v.x; apre[i * 4 + 1] = v.y;
                apre[i * 4 + 2] = v.z; apre[i * 4 + 3] = v.w;
            }
            if (rowscale) {
                float rs = 1.f / rowscale[m * 2 + (kb >= 128 ? 1 : 0)];
#pragma unroll
                for (int i = 0; i < 16; i++) apre[i] *= rs;
            }
            if (in_relu) {
#pragma unroll
                for (int i = 0; i < 16; i++) apre[i] = fmaxf(apre[i], 0.f);
            }
        } else {
#pragma unroll
            for (int i = 0; i < 16; i++) apre[i] = 0.f;
        }
    };

    auto storeA = [&](int s) {
        char* base = smd + s * 40960;
#pragma unroll
        for (int u = 0; u < 2; u++) {
            __half2 h2[4], l2[4];
#pragma unroll
            for (int j = 0; j < 4; j++) {
                float f0 = apre[u * 8 + 2 * j], f1 = apre[u * 8 + 2 * j + 1];
                __half h0 = __float2half_rn(f0), h1 = __float2half_rn(f1);
                h2[j] = __halves2half2(h0, h1);
                l2[j] = __halves2half2(__float2half_rn(f0 - __half2float(h0)),
                                       __float2half_rn(f1 - __half2float(h1)));
            }
            *reinterpret_cast<uint4*>(base + r * 80 + (u0 + u) * 16) =
                *reinterpret_cast<uint4*>(h2);
            *reinterpret_cast<uint4*>(base + 10240 + r * 80 + (u0 + u) * 16) =
                *reinterpret_cast<uint4*>(l2);
        }
    };

    auto cpB = [&](int c, int s) {
        const size_t go = (size_t)(n0 + r) * K + c * 32;
        const uint32_t db = sb + s * 40960 + 20480 + r * 80;
#pragma unroll
        for (int u = 0; u < 2; u++) {
            cp16(db + (u0 + u) * 16,         Bh + go + (u0 + u) * 8);
            cp16(db + 10240 + (u0 + u) * 16, Bl + go + (u0 + u) * 8);
        }
    };

    auto comp = [&](int s) {
        const uint32_t base = sb + s * 40960;
#pragma unroll
        for (int ks = 0; ks < 2; ks++) {
            uint32_t ah[4][4], al[4][4], bh[4][2], bl[4][2];
            const uint32_t arow = wm * 64 + (lane & 15);
            const uint32_t au = ks * 2 + (lane >> 4);
#pragma unroll
            for (int mt = 0; mt < 4; mt++) {
                const uint32_t ad = base + (arow + mt * 16) * 80 + au * 16;
                ldm_x4(ah[mt], ad);
                ldm_x4(al[mt], ad + 10240);
            }
            const uint32_t brow = wn * 32 + (lane & 7);
            const uint32_t bu = ks * 2 + ((lane >> 3) & 1);
#pragma unroll
            for (int nt = 0; nt < 4; nt++) {
                const uint32_t bd = base + 20480 + (brow + nt * 8) * 80 + bu * 16;
                ldm_x2(bh[nt], bd);
                ldm_x2(bl[nt], bd + 10240);
            }
#pragma unroll
            for (int mt = 0; mt < 4; mt++)
#pragma unroll
                for (int nt = 0; nt < 4; nt++) {
                    mma_f32(acc[mt][nt], ah[mt], bh[nt]);
                    mma_f16(acx[mt][nt], ah[mt], bl[nt]);
                    mma_f16(acx[mt][nt], al[mt], bh[nt]);
                }
        }
    };

    prefA(0); storeA(0); cpB(0, 0);
    CP_COMMIT(); CP_WAIT0();
    __syncthreads();

    for (int c = 0; c < NC; c++) {
        const int s = c & 1;
        if (c + 1 < NC) { prefA(c + 1); cpB(c + 1, s ^ 1); CP_COMMIT(); }
        comp(s);
        if (c + 1 < NC) { storeA(s ^ 1); CP_WAIT0(); }
        __syncthreads();
    }

#pragma unroll
    for (int mt = 0; mt < 4; mt++)
#pragma unroll
        for (int nt = 0; nt < 4; nt++) {
            float2 f0 = __half22float2(*reinterpret_cast<__half2*>(&acx[mt][nt][0]));
            float2 f1 = __half22float2(*reinterpret_cast<__half2*>(&acx[mt][nt][1]));
            acc[mt][nt][0] += f0.x; acc[mt][nt][1] += f0.y;
            acc[mt][nt][2] += f1.x; acc[mt][nt][3] += f1.y;
        }

#pragma unroll
    for (int mt = 0; mt < 4; mt++) {
        const int row = bm0 + wm * 64 + mt * 16 + (lane >> 2);
#pragma unroll
        for (int nt = 0; nt < 4; nt++) {
            const int col = n0 + wn * 32 + nt * 8 + 2 * (lane & 3);
            float b0 = bias ? bias[col] : 0.f;
            float b1 = bias ? bias[col + 1] : 0.f;
            float v0 = acc[mt][nt][0] + b0, v1 = acc[mt][nt][1] + b1;
            float v2 = acc[mt][nt][2] + b0, v3 = acc[mt][nt][3] + b1;
            if (out_relu) {
                v0 = fmaxf(v0, 0.f); v1 = fmaxf(v1, 0.f);
                v2 = fmaxf(v2, 0.f); v3 = fmaxf(v3, 0.f);
            }
            if (row < M)
                *reinterpret_cast<float2*>(C + (size_t)row * NTOT + col) = make_float2(v0, v1);
            if (row + 8 < M)
                *reinterpret_cast<float2*>(C + (size_t)(row + 8) * NTOT + col) = make_float2(v2, v3);
        }
    }
}

// ================= edge HMMA kernel: BM=64, BN=256 (full N in one CTA) =================
// A(e,k) = relu(P[src[e]][k] + P[dst[e]][512+k] + eb0[k]); K=512.
// Epilogue: out[e] = eb2 + sum_col relu(acc + eb1[col]) * ew2[col].  Pure store.
// smem per stage 51200: A_hi@0 (64x80), A_lo@5120, B_hi@10240 (256x80), B_lo@30720.
__global__ void __launch_bounds__(256)
edge_mma_kernel(const float* __restrict__ P,
                const int* __restrict__ src, const int* __restrict__ dst,
                const float* __restrict__ eb0,
                const __half* __restrict__ Bh, const __half* __restrict__ Bl,
                const float* __restrict__ eb1, const float* __restrict__ ew2,
                const float* __restrict__ eb2, float* __restrict__ out)
{
    extern __shared__ char smd[];
    __shared__ float red[64];
    const uint32_t sb = smem_u32(smd);
    const int tid  = threadIdx.x;
    const int lane = tid & 31;
    const int wid  = tid >> 5;
    const int wm   = wid >> 2;        // 0..1 (M halves of 32)
    const int wn   = wid & 3;         // 0..3 (N quarters of 64)
    const int e0   = blockIdx.x * 64;
    const int r    = tid >> 2;        // A row 0..63
    const int u0   = tid & 3;         // 16B unit 0..3

    const int sn = src[e0 + r];
    const int dn = dst[e0 + r];
    if (tid < 64) red[tid] = 0.f;

    float acc[2][8][4];
    uint32_t acx[2][8][2];
#pragma unroll
    for (int a = 0; a < 2; a++)
#pragma unroll
        for (int b = 0; b < 8; b++) {
#pragma unroll
            for (int c = 0; c < 4; c++) acc[a][b][c] = 0.f;
            acx[a][b][0] = 0u; acx[a][b][1] = 0u;
        }

    float apre[8];

    auto prefA = [&](int c) {
        const int kb = c * 32 + u0 * 8;
        const float4* ps = reinterpret_cast<const float4*>(P + (size_t)sn * 1024 + kb);
        const float4* pd = reinterpret_cast<const float4*>(P + (size_t)dn * 1024 + 512 + kb);
        const float4* pb = reinterpret_cast<const float4*>(eb0 + kb);
#pragma unroll
        for (int i = 0; i < 2; i++) {
            float4 a4 = ps[i], b4 = pd[i], c4 = pb[i];
            apre[i * 4 + 0] = fmaxf(a4.x + b4.x + c4.x, 0.f);
            apre[i * 4 + 1] = fmaxf(a4.y + b4.y + c4.y, 0.f);
            apre[i * 4 + 2] = fmaxf(a4.z + b4.z + c4.z, 0.f);
            apre[i * 4 + 3] = fmaxf(a4.w + b4.w + c4.w, 0.f);
        }
    };

    auto storeA = [&](int s) {
        char* base = smd + s * 51200;
        __half2 h2[4], l2[4];
#pragma unroll
        for (int j = 0; j < 4; j++) {
            float f0 = apre[2 * j], f1 = apre[2 * j + 1];
            __half h0 = __float2half_rn(f0), h1 = __float2half_rn(f1);
            h2[j] = __halves2half2(h0, h1);
            l2[j] = __halves2half2(__float2half_rn(f0 - __half2float(h0)),
                                   __float2half_rn(f1 - __half2float(h1)));
        }
        *reinterpret_cast<uint4*>(base + r * 80 + u0 * 16) = *reinterpret_cast<uint4*>(h2);
        *reinterpret_cast<uint4*>(base + 5120 + r * 80 + u0 * 16) = *reinterpret_cast<uint4*>(l2);
    };

    auto cpB = [&](int c, int s) {
        const size_t go = (size_t)tid * 512 + c * 32;   // B row = tid (0..255)
        const uint32_t db = sb + s * 51200 + 10240 + tid * 80;
#pragma unroll
        for (int u = 0; u < 4; u++) {
            cp16(db + u * 16,         Bh + go + u * 8);
            cp16(db + 20480 + u * 16, Bl + go + u * 8);
        }
    };

    auto comp = [&](int s) {
        const uint32_t base = sb + s * 51200;
#pragma unroll
        for (int ks = 0; ks < 2; ks++) {
            uint32_t ah[2][4], al[2][4], bh[8][2], bl[8][2];
            const uint32_t arow = wm * 32 + (lane & 15);
            const uint32_t au = ks * 2 + (lane >> 4);
#pragma unroll
            for (int mt = 0; mt < 2; mt++) {
                const uint32_t ad = base + (arow + mt * 16) * 80 + au * 16;
                ldm_x4(ah[mt], ad);
                ldm_x4(al[mt], ad + 5120);
            }
            // B: ldm_x4 covers 2 n-tiles (16 rows) x 2 k-units
            const uint32_t brow0 = wn * 64 + (lane & 7) + ((lane >> 4) << 3);
            const uint32_t bu = ks * 2 + ((lane >> 3) & 1);
#pragma unroll
            for (int pr = 0; pr < 4; pr++) {
                uint32_t t[4];
                const uint32_t bd = base + 10240 + (brow0 + pr * 16) * 80 + bu * 16;
                ldm_x4(t, bd);
                bh[2 * pr][0] = t[0]; bh[2 * pr][1] = t[1];
                bh[2 * pr + 1][0] = t[2]; bh[2 * pr + 1][1] = t[3];
                ldm_x4(t, bd + 20480);
                bl[2 * pr][0] = t[0]; bl[2 * pr][1] = t[1];
                bl[2 * pr + 1][0] = t[2]; bl[2 * pr + 1][1] = t[3];
            }
#pragma unroll
            for (int mt = 0; mt < 2; mt++)
#pragma unroll
                for (int nt = 0; nt < 8; nt++) {
                    mma_f32(acc[mt][nt], ah[mt], bh[nt]);
                    mma_f16(acx[mt][nt], ah[mt], bl[nt]);
                    mma_f16(acx[mt][nt], al[mt], bh[nt]);
                }
        }
    };

    prefA(0); storeA(0); cpB(0, 0);
    CP_COMMIT(); CP_WAIT0();
    __syncthreads();

#pragma unroll 1
    for (int c = 0; c < 16; c++) {
        const int s = c & 1;
        if (c + 1 < 16) { prefA(c + 1); cpB(c + 1, s ^ 1); CP_COMMIT(); }
        comp(s);
        if (c + 1 < 16) { storeA(s ^ 1); CP_WAIT0(); }
        __syncthreads();
    }

    // fold fp16 crosses, then fused bias+relu+dot epilogue
#pragma unroll
    for (int mt = 0; mt < 2; mt++) {
        float p0 = 0.f, p1 = 0.f;
#pragma unroll
        for (int nt = 0; nt < 8; nt++) {
            float2 f0 = __half22float2(*reinterpret_cast<__half2*>(&acx[mt][nt][0]));
            float2 f1 = __half22float2(*reinterpret_cast<__half2*>(&acx[mt][nt][1]));
            const int col = wn * 64 + nt * 8 + 2 * (lane & 3);
            const float b0 = eb1[col], b1 = eb1[col + 1];
            const float w0 = ew2[col], w1 = ew2[col + 1];
            p0 += fmaxf(acc[mt][nt][0] + f0.x + b0, 0.f) * w0
                + fmaxf(acc[mt][nt][1] + f0.y + b1, 0.f) * w1;
            p1 += fmaxf(acc[mt][nt][2] + f1.x + b0, 0.f) * w0
                + fmaxf(acc[mt][nt][3] + f1.y + b1, 0.f) * w1;
        }
        p0 += __shfl_xor_sync(0xffffffffu, p0, 1);
        p0 += __shfl_xor_sync(0xffffffffu, p0, 2);
        p1 += __shfl_xor_sync(0xffffffffu, p1, 1);
        p1 += __shfl_xor_sync(0xffffffffu, p1, 2);
        if ((lane & 3) == 0) {
            atomicAdd(&red[wm * 32 + mt * 16 + (lane >> 2)], p0);
            atomicAdd(&red[wm * 32 + mt * 16 + (lane >> 2) + 8], p1);
        }
    }
    __syncthreads();
    if (tid < 64) out[e0 + tid] = red[tid] + eb2[0];
}

// ---------------- prep kernels ----------------
__global__ void wsplit_kernel(const float* __restrict__ W,
                              __half* __restrict__ th, __half* __restrict__ tl,
                              int K, int N)
{
    int i = blockIdx.x * blockDim.x + threadIdx.x;
    if (i >= K * N) return;
    int n = i / K, k = i % K;
    float f = W[(size_t)k * N + n];
    __half h = __float2half_rn(f);
    th[i] = h; tl[i] = __float2half_rn(f - __half2float(h));
}

__global__ void w0pack_kernel(const float* __restrict__ ew0,
                              __half* __restrict__ th, __half* __restrict__ tl)
{
    int i = blockIdx.x * blockDim.x + threadIdx.x;
    if (i >= 512 * 384) return;
    int n = i / 384, k = i % 384;
    int rs = (k < 128) ? k : k + 128;
    int rd = (k < 128) ? k + 128 : k + 384;
    float f = ew0[rs * 512 + n];
    __half h = __float2half_rn(f);
    th[i] = h; tl[i] = __float2half_rn(f - __half2float(h));
    f = ew0[rd * 512 + n];
    h = __float2half_rn(f);
    th[512 * 384 + i] = h;
    tl[512 * 384 + i] = __float2half_rn(f - __half2float(h));
}

__global__ void bcat_kernel(const float* a, const float* b, float* o, int n)
{
    int i = blockIdx.x * blockDim.x + threadIdx.x;
    if (i < n) o[i] = a[i];
    else if (i < 2 * n) o[i] = b[i - n];
}

// z = [h1 | relu(acc/s)]
__global__ void zbuild_kernel(const float* __restrict__ h1, const float* __restrict__ a2,
                              const float* __restrict__ s, float* __restrict__ z)
{
    int i = blockIdx.x * blockDim.x + threadIdx.x;
    if (i >= N_NODES * 384) return;
    int n = i / 384, j = i % 384;
    if (j < 128) z[i] = h1[n * 128 + j];
    else {
        int q = j - 128;
        z[i] = fmaxf(a2[n * 256 + q] / s[n * 2 + (q >= 128 ? 1 : 0)], 0.f);
    }
}

// ---------------- GAT kernels ----------------
__global__ void gat_init_kernel(float* s, float* acc)
{
    int i = blockIdx.x * blockDim.x + threadIdx.x;
    if (i < N_NODES * 256) acc[i] = 0.f;
    if (i < N_NODES * 2) s[i] = 0.f;
}

// fused: logits -> exp -> unnormalized scatter (acc += ev*fs, s += ev)
__global__ void gat_fused_kernel(const float* __restrict__ fsd,
                                 const float* __restrict__ attn,
                                 const int* __restrict__ src, const int* __restrict__ dst,
                                 float* __restrict__ s, float* __restrict__ acc)
{
    int e = (blockIdx.x * blockDim.x + threadIdx.x) >> 5;
    int lane = threadIdx.x & 31;
    if (e >= N_EDGES) return;
    int sN = src[e], tN = dst[e];
#pragma unroll
    for (int h = 0; h < 2; h++) {
        float4 a = *reinterpret_cast<const float4*>(fsd + (size_t)sN * 512 + h * 128 + lane * 4);
        float4 b = *reinterpret_cast<const float4*>(fsd + (size_t)tN * 512 + 256 + h * 128 + lane * 4);
        float4 t = *reinterpret_cast<const float4*>(attn + h * 128 + lane * 4);
        float v0 = a.x + b.x, v1 = a.y + b.y, v2 = a.z + b.z, v3 = a.w + b.w;
        v0 = (v0 > 0.f) ? v0 : 0.2f * v0;
        v1 = (v1 > 0.f) ? v1 : 0.2f * v1;
        v2 = (v2 > 0.f) ? v2 : 0.2f * v2;
        v3 = (v3 > 0.f) ? v3 : 0.2f * v3;
        float lg = v0 * t.x + v1 * t.y + v2 * t.z + v3 * t.w;
#pragma unroll
        for (int o = 16; o; o >>= 1) lg += __shfl_xor_sync(0xffffffffu, lg, o);
        float ev = expf(lg);
        if (lane == 0) atomicAdd(&s[tN * 2 + h], ev);
        float4 v = make_float4(a.x * ev, a.y * ev, a.z * ev, a.w * ev);
        atomicAdd(reinterpret_cast<float4*>(acc + (size_t)tN * 256 + h * 128 + lane * 4), v);
    }
}

// ---------------- host launch ----------------
extern "C" void kernel_launch(void* const* d_in, const int* in_sizes, int n_in,
                              void* d_out, int out_size)
{
    const float* x    = (const float*)d_in[0];
    const int*   src  = (const int*)d_in[1];
    const int*   dst  = (const int*)d_in[2];
    const float* nw0  = (const float*)d_in[3];
    const float* nb0  = (const float*)d_in[4];
    const float* nw1  = (const float*)d_in[5];
    const float* nb1  = (const float*)d_in[6];
    const float* g1ws = (const float*)d_in[7];
    const float* g1bs = (const float*)d_in[8];
    const float* g1wd = (const float*)d_in[9];
    const float* g1bd = (const float*)d_in[10];
    const float* g1a  = (const float*)d_in[11];
    const float* g2ws = (const float*)d_in[12];
    const float* g2bs = (const float*)d_in[13];
    const float* g2wd = (const float*)d_in[14];
    const float* g2bd = (const float*)d_in[15];
    const float* g2a  = (const float*)d_in[16];
    const float* ew0  = (const float*)d_in[17];
    const float* eb0  = (const float*)d_in[18];
    const float* ew1  = (const float*)d_in[19];
    const float* eb1  = (const float*)d_in[20];
    const float* ew2  = (const float*)d_in[21];
    const float* eb2  = (const float*)d_in[22];
    float* out = (float*)d_out;

    float *tmp, *h1, *fsd, *acc, *sB, *z, *P, *b1c, *b2c;
    __half *nw0h, *nw0l, *nw1h, *nw1l, *g1h, *g1l, *g2h, *g2l, *w0h, *w0l, *w1h, *w1l;
    cudaGetSymbolAddress((void**)&tmp,  g_tmp);
    cudaGetSymbolAddress((void**)&h1,   g_h1);
    cudaGetSymbolAddress((void**)&fsd,  g_fsd);
    cudaGetSymbolAddress((void**)&acc,  g_acc);
    cudaGetSymbolAddress((void**)&sB,   g_s);
    cudaGetSymbolAddress((void**)&z,    g_z);
    cudaGetSymbolAddress((void**)&P,    g_p);
    cudaGetSymbolAddress((void**)&b1c,  g_b1cat);
    cudaGetSymbolAddress((void**)&b2c,  g_b2cat);
    cudaGetSymbolAddress((void**)&nw0h, g_nw0h);
    cudaGetSymbolAddress((void**)&nw0l, g_nw0l);
    cudaGetSymbolAddress((void**)&nw1h, g_nw1h);
    cudaGetSymbolAddress((void**)&nw1l, g_nw1l);
    cudaGetSymbolAddress((void**)&g1h,  g_g1h);
    cudaGetSymbolAddress((void**)&g1l,  g_g1l);
    cudaGetSymbolAddress((void**)&g2h,  g_g2h);
    cudaGetSymbolAddress((void**)&g2l,  g_g2l);
    cudaGetSymbolAddress((void**)&w0h,  g_w0h);
    cudaGetSymbolAddress((void**)&w0l,  g_w0l);
    cudaGetSymbolAddress((void**)&w1h,  g_w1h);
    cudaGetSymbolAddress((void**)&w1l,  g_w1l);

    cudaFuncSetAttribute(mma_gemm_kernel, cudaFuncAttributeMaxDynamicSharedMemorySize, 81920);
    cudaFuncSetAttribute(edge_mma_kernel, cudaFuncAttributeMaxDynamicSharedMemorySize, 102400);

    // ---- prep ----
    wsplit_kernel<<<(128 * 64 + 255) / 256, 256>>>(nw0, nw0h, nw0l, 64, 128);
    wsplit_kernel<<<(128 * 128 + 255) / 256, 256>>>(nw1, nw1h, nw1l, 128, 128);
    wsplit_kernel<<<(256 * 64 + 255) / 256, 256>>>(g1ws, g1h, g1l, 64, 256);
    wsplit_kernel<<<(256 * 64 + 255) / 256, 256>>>(g1wd, g1h + 256 * 64, g1l + 256 * 64, 64, 256);
    wsplit_kernel<<<(256 * 256 + 255) / 256, 256>>>(g2ws, g2h, g2l, 256, 256);
    wsplit_kernel<<<(256 * 256 + 255) / 256, 256>>>(g2wd, g2h + 256 * 256, g2l + 256 * 256, 256, 256);
    w0pack_kernel<<<(512 * 384 + 255) / 256, 256>>>(ew0, w0h, w0l);
    wsplit_kernel<<<(256 * 512 + 255) / 256, 256>>>(ew1, w1h, w1l, 512, 256);
    bcat_kernel<<<2, 256>>>(g1bs, g1bd, b1c, 256);
    bcat_kernel<<<2, 256>>>(g2bs, g2bd, b2c, 256);

    const int MBY = (N_NODES + 127) / 128;   // 157

    // ---- NodeMLP ----
    mma_gemm_kernel<<<dim3(1, MBY), 256, 81920>>>(
        x, N_NODES, 64, nw0h, nw0l, nb0, 0, 1, nullptr, tmp, 128);
    mma_gemm_kernel<<<dim3(1, MBY), 256, 81920>>>(
        tmp, N_NODES, 128, nw1h, nw1l, nb1, 0, 1, nullptr, h1, 128);

    // ---- GAT layer 1 ----
    mma_gemm_kernel<<<dim3(4, MBY), 256, 81920>>>(
        x, N_NODES, 64, g1h, g1l, b1c, 0, 0, nullptr, fsd, 512);
    gat_init_kernel<<<(N_NODES * 256 + 255) / 256, 256>>>(sB, acc);
    gat_fused_kernel<<<N_EDGES / 8, 256>>>(fsd, g1a, src, dst, sB, acc);

    // ---- GAT layer 2: input = relu(acc/s) via rowscale ----
    mma_gemm_kernel<<<dim3(4, MBY), 256, 81920>>>(
        acc, N_NODES, 256, g2h, g2l, b2c, 1, 0, sB, fsd, 512);
    gat_init_kernel<<<(N_NODES * 256 + 255) / 256, 256>>>(sB, acc);
    gat_fused_kernel<<<N_EDGES / 8, 256>>>(fsd, g2a, src, dst, sB, acc);

    // ---- Z = [h1 | relu(acc/s)], P = Z @ [W0s|W0d] ----
    zbuild_kernel<<<(N_NODES * 384 + 255) / 256, 256>>>(h1, acc, sB, z);
    mma_gemm_kernel<<<dim3(8, MBY), 256, 81920>>>(
        z, N_NODES, 384, w0h, w0l, nullptr, 0, 0, nullptr, P, 1024);

    // ---- EdgeMLP layers 2+3 fused ----
    edge_mma_kernel<<<N_EDGES / 64, 256, 102400>>>(
        P, src, dst, eb0, w1h, w1l, eb1, ew2, eb2, out);
}

// round 6
// speedup vs baseline: 7.6540x; 1.2606x over previous
#include <cuda_runtime.h>
#include <cuda_fp16.h>
#include <cstdint>

#define N_NODES 20000
#define N_EDGES 320000

// ---------------- scratch ----------------
__device__ float g_tmp [N_NODES * 128];
__device__ float g_h1  [N_NODES * 128];
__device__ float g_fsd [N_NODES * 512];
__device__ float g_acc [N_NODES * 256];
__device__ float g_s   [N_NODES * 2];
__device__ float g_z   [N_NODES * 384];
__device__ float g_p   [N_NODES * 1024];
__device__ __half g_nw0h[128 * 64],   g_nw0l[128 * 64];
__device__ __half g_nw1h[128 * 128],  g_nw1l[128 * 128];
__device__ __half g_g1h [512 * 64],   g_g1l [512 * 64];
__device__ __half g_g2h [512 * 256],  g_g2l [512 * 256];
__device__ __half g_w0h [1024 * 384], g_w0l [1024 * 384];
__device__ __half g_w1h [256 * 512],  g_w1l [256 * 512];
__device__ float  g_b1cat[512], g_b2cat[512];

// ---------------- PTX helpers ----------------
__device__ __forceinline__ uint32_t smem_u32(const void* p) {
    uint32_t a;
    asm("{ .reg .u64 t; cvta.to.shared.u64 t, %1; cvt.u32.u64 %0, t; }" : "=r"(a) : "l"(p));
    return a;
}
__device__ __forceinline__ void ldm_x4(uint32_t* r, uint32_t a) {
    asm volatile("ldmatrix.sync.aligned.m8n8.x4.shared.b16 {%0,%1,%2,%3}, [%4];"
                 : "=r"(r[0]), "=r"(r[1]), "=r"(r[2]), "=r"(r[3]) : "r"(a));
}
__device__ __forceinline__ void ldm_x2(uint32_t* r, uint32_t a) {
    asm volatile("ldmatrix.sync.aligned.m8n8.x2.shared.b16 {%0,%1}, [%2];"
                 : "=r"(r[0]), "=r"(r[1]) : "r"(a));
}
__device__ __forceinline__ void mma_f32(float* c, const uint32_t* a, const uint32_t* b) {
    asm volatile("mma.sync.aligned.m16n8k16.row.col.f32.f16.f16.f32 "
                 "{%0,%1,%2,%3}, {%4,%5,%6,%7}, {%8,%9}, {%0,%1,%2,%3};"
                 : "+f"(c[0]), "+f"(c[1]), "+f"(c[2]), "+f"(c[3])
                 : "r"(a[0]), "r"(a[1]), "r"(a[2]), "r"(a[3]), "r"(b[0]), "r"(b[1]));
}
__device__ __forceinline__ void mma_f16(uint32_t* c, const uint32_t* a, const uint32_t* b) {
    asm volatile("mma.sync.aligned.m16n8k16.row.col.f16.f16.f16.f16 "
                 "{%0,%1}, {%2,%3,%4,%5}, {%6,%7}, {%0,%1};"
                 : "+r"(c[0]), "+r"(c[1])
                 : "r"(a[0]), "r"(a[1]), "r"(a[2]), "r"(a[3]), "r"(b[0]), "r"(b[1]));
}
__device__ __forceinline__ void cp16(uint32_t d, const void* s) {
    asm volatile("cp.async.cg.shared.global [%0], [%1], 16;" :: "r"(d), "l"(s));
}
#define CP_COMMIT() asm volatile("cp.async.commit_group;")
#define CP_WAIT0()  asm volatile("cp.async.wait_group 0;")

// ================= node-side HMMA GEMM (unchanged, proven) =================
__global__ void __launch_bounds__(256)
mma_gemm_kernel(const float* __restrict__ A, int M, int K,
                const __half* __restrict__ Bh, const __half* __restrict__ Bl,
                const float* __restrict__ bias, int in_relu, int out_relu,
                const float* __restrict__ rowscale,
                float* __restrict__ C, int NTOT)
{
    extern __shared__ char smd[];
    const uint32_t sb = smem_u32(smd);
    const int tid  = threadIdx.x;
    const int lane = tid & 31;
    const int wid  = tid >> 5;
    const int wm   = wid >> 2;
    const int wn   = wid & 3;
    const int bm0  = blockIdx.y * 128;
    const int n0   = blockIdx.x * 128;
    const int r    = tid >> 1;
    const int u0   = (tid & 1) * 2;

    float acc[4][4][4];
    uint32_t acx[4][4][2];
#pragma unroll
    for (int a = 0; a < 4; a++)
#pragma unroll
        for (int b = 0; b < 4; b++) {
#pragma unroll
            for (int c = 0; c < 4; c++) acc[a][b][c] = 0.f;
            acx[a][b][0] = 0u; acx[a][b][1] = 0u;
        }

    const int NC = K >> 5;
    float apre[16];

    auto prefA = [&](int c) {
        const int kb = c * 32 + u0 * 8;
        const int m = bm0 + r;
        if (m < M) {
            const float4* p = reinterpret_cast<const float4*>(A + (size_t)m * K + kb);
#pragma unroll
            for (int i = 0; i < 4; i++) {
                float4 v = p[i];
                apre[i * 4 + 0] = v.x; apre[i * 4 + 1] = v.y;
                apre[i * 4 + 2] = v.z; apre[i * 4 + 3] = v.w;
            }
            if (rowscale) {
                float rs = 1.f / rowscale[m * 2 + (kb >= 128 ? 1 : 0)];
#pragma unroll
                for (int i = 0; i < 16; i++) apre[i] *= rs;
            }
            if (in_relu) {
#pragma unroll
                for (int i = 0; i < 16; i++) apre[i] = fmaxf(apre[i], 0.f);
            }
        } else {
#pragma unroll
            for (int i = 0; i < 16; i++) apre[i] = 0.f;
        }
    };

    auto storeA = [&](int s) {
        char* base = smd + s * 40960;
#pragma unroll
        for (int u = 0; u < 2; u++) {
            __half2 h2[4], l2[4];
#pragma unroll
            for (int j = 0; j < 4; j++) {
                float f0 = apre[u * 8 + 2 * j], f1 = apre[u * 8 + 2 * j + 1];
                __half h0 = __float2half_rn(f0), h1 = __float2half_rn(f1);
                h2[j] = __halves2half2(h0, h1);
                l2[j] = __halves2half2(__float2half_rn(f0 - __half2float(h0)),
                                       __float2half_rn(f1 - __half2float(h1)));
            }
            *reinterpret_cast<uint4*>(base + r * 80 + (u0 + u) * 16) =
                *reinterpret_cast<uint4*>(h2);
            *reinterpret_cast<uint4*>(base + 10240 + r * 80 + (u0 + u) * 16) =
                *reinterpret_cast<uint4*>(l2);
        }
    };

    auto cpB = [&](int c, int s) {
        const size_t go = (size_t)(n0 + r) * K + c * 32;
        const uint32_t db = sb + s * 40960 + 20480 + r * 80;
#pragma unroll
        for (int u = 0; u < 2; u++) {
            cp16(db + (u0 + u) * 16,         Bh + go + (u0 + u) * 8);
            cp16(db + 10240 + (u0 + u) * 16, Bl + go + (u0 + u) * 8);
        }
    };

    auto comp = [&](int s) {
        const uint32_t base = sb + s * 40960;
#pragma unroll
        for (int ks = 0; ks < 2; ks++) {
            uint32_t ah[4][4], al[4][4], bh[4][2], bl[4][2];
            const uint32_t arow = wm * 64 + (lane & 15);
            const uint32_t au = ks * 2 + (lane >> 4);
#pragma unroll
            for (int mt = 0; mt < 4; mt++) {
                const uint32_t ad = base + (arow + mt * 16) * 80 + au * 16;
                ldm_x4(ah[mt], ad);
                ldm_x4(al[mt], ad + 10240);
            }
            const uint32_t brow = wn * 32 + (lane & 7);
            const uint32_t bu = ks * 2 + ((lane >> 3) & 1);
#pragma unroll
            for (int nt = 0; nt < 4; nt++) {
                const uint32_t bd = base + 20480 + (brow + nt * 8) * 80 + bu * 16;
                ldm_x2(bh[nt], bd);
                ldm_x2(bl[nt], bd + 10240);
            }
#pragma unroll
            for (int mt = 0; mt < 4; mt++)
#pragma unroll
                for (int nt = 0; nt < 4; nt++) {
                    mma_f32(acc[mt][nt], ah[mt], bh[nt]);
                    mma_f16(acx[mt][nt], ah[mt], bl[nt]);
                    mma_f16(acx[mt][nt], al[mt], bh[nt]);
                }
        }
    };

    prefA(0); storeA(0); cpB(0, 0);
    CP_COMMIT(); CP_WAIT0();
    __syncthreads();

    for (int c = 0; c < NC; c++) {
        const int s = c & 1;
        if (c + 1 < NC) { prefA(c + 1); cpB(c + 1, s ^ 1); CP_COMMIT(); }
        comp(s);
        if (c + 1 < NC) { storeA(s ^ 1); CP_WAIT0(); }
        __syncthreads();
    }

#pragma unroll
    for (int mt = 0; mt < 4; mt++)
#pragma unroll
        for (int nt = 0; nt < 4; nt++) {
            float2 f0 = __half22float2(*reinterpret_cast<__half2*>(&acx[mt][nt][0]));
            float2 f1 = __half22float2(*reinterpret_cast<__half2*>(&acx[mt][nt][1]));
            acc[mt][nt][0] += f0.x; acc[mt][nt][1] += f0.y;
            acc[mt][nt][2] += f1.x; acc[mt][nt][3] += f1.y;
        }

#pragma unroll
    for (int mt = 0; mt < 4; mt++) {
        const int row = bm0 + wm * 64 + mt * 16 + (lane >> 2);
#pragma unroll
        for (int nt = 0; nt < 4; nt++) {
            const int col = n0 + wn * 32 + nt * 8 + 2 * (lane & 3);
            float b0 = bias ? bias[col] : 0.f;
            float b1 = bias ? bias[col + 1] : 0.f;
            float v0 = acc[mt][nt][0] + b0, v1 = acc[mt][nt][1] + b1;
            float v2 = acc[mt][nt][2] + b0, v3 = acc[mt][nt][3] + b1;
            if (out_relu) {
                v0 = fmaxf(v0, 0.f); v1 = fmaxf(v1, 0.f);
                v2 = fmaxf(v2, 0.f); v3 = fmaxf(v3, 0.f);
            }
            if (row < M)
                *reinterpret_cast<float2*>(C + (size_t)row * NTOT + col) = make_float2(v0, v1);
            if (row + 8 < M)
                *reinterpret_cast<float2*>(C + (size_t)(row + 8) * NTOT + col) = make_float2(v2, v3);
        }
    }
}

// ================= edge HMMA kernel: BM=128, BN=256, 512 threads =================
// 16 warps (4M x 4N), warp tile 32x64. Halves B re-read traffic vs BM=64.
// smem/stage 61440: A_hi@0 (128x80=10240), A_lo@10240, B_hi@20480 (256x80=20480), B_lo@40960.
__global__ void __launch_bounds__(512)
edge_mma_kernel(const float* __restrict__ P,
                const int* __restrict__ src, const int* __restrict__ dst,
                const float* __restrict__ eb0,
                const __half* __restrict__ Bh, const __half* __restrict__ Bl,
                const float* __restrict__ eb1, const float* __restrict__ ew2,
                const float* __restrict__ eb2, float* __restrict__ out)
{
    extern __shared__ char smd[];
    __shared__ float red[128];
    const uint32_t sb = smem_u32(smd);
    const int tid  = threadIdx.x;
    const int lane = tid & 31;
    const int wid  = tid >> 5;
    const int wm   = wid >> 2;        // 0..3 (M quarters of 32)
    const int wn   = wid & 3;         // 0..3 (N quarters of 64)
    const int e0   = blockIdx.x * 128;
    const int ra   = tid >> 2;        // A row 0..127
    const int ua   = tid & 3;         // A k-unit 0..3
    const int rb   = tid >> 1;        // B row 0..255
    const int ub   = (tid & 1) * 2;   // B k-unit base

    const int sn = src[e0 + ra];
    const int dn = dst[e0 + ra];
    if (tid < 128) red[tid] = 0.f;

    float acc[2][8][4];
    uint32_t acx[2][8][2];
#pragma unroll
    for (int a = 0; a < 2; a++)
#pragma unroll
        for (int b = 0; b < 8; b++) {
#pragma unroll
            for (int c = 0; c < 4; c++) acc[a][b][c] = 0.f;
            acx[a][b][0] = 0u; acx[a][b][1] = 0u;
        }

    float apre[8];

    auto prefA = [&](int c) {
        const int kb = c * 32 + ua * 8;
        const float4* ps = reinterpret_cast<const float4*>(P + (size_t)sn * 1024 + kb);
        const float4* pd = reinterpret_cast<const float4*>(P + (size_t)dn * 1024 + 512 + kb);
        const float4* pb = reinterpret_cast<const float4*>(eb0 + kb);
#pragma unroll
        for (int i = 0; i < 2; i++) {
            float4 a4 = ps[i], b4 = pd[i], c4 = pb[i];
            apre[i * 4 + 0] = fmaxf(a4.x + b4.x + c4.x, 0.f);
            apre[i * 4 + 1] = fmaxf(a4.y + b4.y + c4.y, 0.f);
            apre[i * 4 + 2] = fmaxf(a4.z + b4.z + c4.z, 0.f);
            apre[i * 4 + 3] = fmaxf(a4.w + b4.w + c4.w, 0.f);
        }
    };

    auto storeA = [&](int s) {
        char* base = smd + s * 61440;
        __half2 h2[4], l2[4];
#pragma unroll
        for (int j = 0; j < 4; j++) {
            float f0 = apre[2 * j], f1 = apre[2 * j + 1];
            __half h0 = __float2half_rn(f0), h1 = __float2half_rn(f1);
            h2[j] = __halves2half2(h0, h1);
            l2[j] = __halves2half2(__float2half_rn(f0 - __half2float(h0)),
                                   __float2half_rn(f1 - __half2float(h1)));
        }
        *reinterpret_cast<uint4*>(base + ra * 80 + ua * 16) = *reinterpret_cast<uint4*>(h2);
        *reinterpret_cast<uint4*>(base + 10240 + ra * 80 + ua * 16) = *reinterpret_cast<uint4*>(l2);
    };

    auto cpB = [&](int c, int s) {
        const size_t go = (size_t)rb * 512 + c * 32;
        const uint32_t db = sb + s * 61440 + 20480 + rb * 80;
#pragma unroll
        for (int u = 0; u < 2; u++) {
            cp16(db + (ub + u) * 16,         Bh + go + (ub + u) * 8);
            cp16(db + 20480 + (ub + u) * 16, Bl + go + (ub + u) * 8);
        }
    };

    auto comp = [&](int s) {
        const uint32_t base = sb + s * 61440;
#pragma unroll
        for (int ks = 0; ks < 2; ks++) {
            uint32_t ah[2][4], al[2][4], bh[8][2], bl[8][2];
            const uint32_t arow = wm * 32 + (lane & 15);
            const uint32_t au = ks * 2 + (lane >> 4);
#pragma unroll
            for (int mt = 0; mt < 2; mt++) {
                const uint32_t ad = base + (arow + mt * 16) * 80 + au * 16;
                ldm_x4(ah[mt], ad);
                ldm_x4(al[mt], ad + 10240);
            }
            const uint32_t brow0 = wn * 64 + (lane & 7) + ((lane >> 4) << 3);
            const uint32_t bu = ks * 2 + ((lane >> 3) & 1);
#pragma unroll
            for (int pr = 0; pr < 4; pr++) {
                uint32_t t[4];
                const uint32_t bd = base + 20480 + (brow0 + pr * 16) * 80 + bu * 16;
                ldm_x4(t, bd);
                bh[2 * pr][0] = t[0]; bh[2 * pr][1] = t[1];
                bh[2 * pr + 1][0] = t[2]; bh[2 * pr + 1][1] = t[3];
                ldm_x4(t, bd + 20480);
                bl[2 * pr][0] = t[0]; bl[2 * pr][1] = t[1];
                bl[2 * pr + 1][0] = t[2]; bl[2 * pr + 1][1] = t[3];
            }
#pragma unroll
            for (int mt = 0; mt < 2; mt++)
#pragma unroll
                for (int nt = 0; nt < 8; nt++) {
                    mma_f32(acc[mt][nt], ah[mt], bh[nt]);
                    mma_f16(acx[mt][nt], ah[mt], bl[nt]);
                    mma_f16(acx[mt][nt], al[mt], bh[nt]);
                }
        }
    };

    prefA(0); storeA(0); cpB(0, 0);
    CP_COMMIT(); CP_WAIT0();
    __syncthreads();

#pragma unroll 1
    for (int c = 0; c < 16; c++) {
        const int s = c & 1;
        if (c + 1 < 16) { prefA(c + 1); cpB(c + 1, s ^ 1); CP_COMMIT(); }
        comp(s);
        if (c + 1 < 16) { storeA(s ^ 1); CP_WAIT0(); }
        __syncthreads();
    }

#pragma unroll
    for (int mt = 0; mt < 2; mt++) {
        float p0 = 0.f, p1 = 0.f;
#pragma unroll
        for (int nt = 0; nt < 8; nt++) {
            float2 f0 = __half22float2(*reinterpret_cast<__half2*>(&acx[mt][nt][0]));
            float2 f1 = __half22float2(*reinterpret_cast<__half2*>(&acx[mt][nt][1]));
            const int col = wn * 64 + nt * 8 + 2 * (lane & 3);
            const float b0 = eb1[col], b1 = eb1[col + 1];
            const float w0 = ew2[col], w1 = ew2[col + 1];
            p0 += fmaxf(acc[mt][nt][0] + f0.x + b0, 0.f) * w0
                + fmaxf(acc[mt][nt][1] + f0.y + b1, 0.f) * w1;
            p1 += fmaxf(acc[mt][nt][2] + f1.x + b0, 0.f) * w0
                + fmaxf(acc[mt][nt][3] + f1.y + b1, 0.f) * w1;
        }
        p0 += __shfl_xor_sync(0xffffffffu, p0, 1);
        p0 += __shfl_xor_sync(0xffffffffu, p0, 2);
        p1 += __shfl_xor_sync(0xffffffffu, p1, 1);
        p1 += __shfl_xor_sync(0xffffffffu, p1, 2);
        if ((lane & 3) == 0) {
            atomicAdd(&red[wm * 32 + mt * 16 + (lane >> 2)], p0);
            atomicAdd(&red[wm * 32 + mt * 16 + (lane >> 2) + 8], p1);
        }
    }
    __syncthreads();
    if (tid < 128) out[e0 + tid] = red[tid] + eb2[0];
}

// ================= fused prep kernel (single launch) =================
__device__ __forceinline__ void split_at(const float* W, __half* th, __half* tl,
                                         int K, int N, int i)
{
    int n = i / K, k = i % K;
    float f = W[(size_t)k * N + n];
    __half h = __float2half_rn(f);
    th[i] = h; tl[i] = __float2half_rn(f - __half2float(h));
}

__global__ void prep_kernel(const float* nw0, const float* nw1,
                            const float* g1ws, const float* g1wd,
                            const float* g2ws, const float* g2wd,
                            const float* ew0, const float* ew1,
                            const float* g1bs, const float* g1bd,
                            const float* g2bs, const float* g2bd,
                            __half* nw0h, __half* nw0l, __half* nw1h, __half* nw1l,
                            __half* g1h, __half* g1l, __half* g2h, __half* g2l,
                            __half* w0h, __half* w0l, __half* w1h, __half* w1l,
                            float* b1c, float* b2c)
{
    int i = blockIdx.x * blockDim.x + threadIdx.x;
    if (i < 8192) { split_at(nw0, nw0h, nw0l, 64, 128, i); return; }
    i -= 8192;
    if (i < 16384) { split_at(nw1, nw1h, nw1l, 128, 128, i); return; }
    i -= 16384;
    if (i < 16384) { split_at(g1ws, g1h, g1l, 64, 256, i); return; }
    i -= 16384;
    if (i < 16384) { split_at(g1wd, g1h + 16384, g1l + 16384, 64, 256, i); return; }
    i -= 16384;
    if (i < 65536) { split_at(g2ws, g2h, g2l, 256, 256, i); return; }
    i -= 65536;
    if (i < 65536) { split_at(g2wd, g2h + 65536, g2l + 65536, 256, 256, i); return; }
    i -= 65536;
    if (i < 196608) {   // w0pack: i over 512*384
        int n = i / 384, k = i % 384;
        int rs = (k < 128) ? k : k + 128;
        int rd = (k < 128) ? k + 128 : k + 384;
        float f = ew0[rs * 512 + n];
        __half h = __float2half_rn(f);
        w0h[i] = h; w0l[i] = __float2half_rn(f - __half2float(h));
        f = ew0[rd * 512 + n];
        h = __float2half_rn(f);
        w0h[196608 + i] = h;
        w0l[196608 + i] = __float2half_rn(f - __half2float(h));
        return;
    }
    i -= 196608;
    if (i < 131072) { split_at(ew1, w1h, w1l, 512, 256, i); return; }
    i -= 131072;
    if (i < 512) { b1c[i] = (i < 256) ? g1bs[i] : g1bd[i - 256]; return; }
    i -= 512;
    if (i < 512) { b2c[i] = (i < 256) ? g2bs[i] : g2bd[i - 256]; return; }
}

// ---------------- misc kernels ----------------
__global__ void zbuild_kernel(const float* __restrict__ h1, const float* __restrict__ a2,
                              const float* __restrict__ s, float* __restrict__ z)
{
    int i = blockIdx.x * blockDim.x + threadIdx.x;
    if (i >= N_NODES * 384) return;
    int n = i / 384, j = i % 384;
    if (j < 128) z[i] = h1[n * 128 + j];
    else {
        int q = j - 128;
        z[i] = fmaxf(a2[n * 256 + q] / s[n * 2 + (q >= 128 ? 1 : 0)], 0.f);
    }
}

__global__ void gat_init_kernel(float* s, float* acc)
{
    int i = blockIdx.x * blockDim.x + threadIdx.x;
    if (i < N_NODES * 256) acc[i] = 0.f;
    if (i < N_NODES * 2) s[i] = 0.f;
}

__global__ void gat_fused_kernel(const float* __restrict__ fsd,
                                 const float* __restrict__ attn,
                                 const int* __restrict__ src, const int* __restrict__ dst,
                                 float* __restrict__ s, float* __restrict__ acc)
{
    int e = (blockIdx.x * blockDim.x + threadIdx.x) >> 5;
    int lane = threadIdx.x & 31;
    if (e >= N_EDGES) return;
    int sN = src[e], tN = dst[e];
#pragma unroll
    for (int h = 0; h < 2; h++) {
        float4 a = *reinterpret_cast<const float4*>(fsd + (size_t)sN * 512 + h * 128 + lane * 4);
        float4 b = *reinterpret_cast<const float4*>(fsd + (size_t)tN * 512 + 256 + h * 128 + lane * 4);
        float4 t = *reinterpret_cast<const float4*>(attn + h * 128 + lane * 4);
        float v0 = a.x + b.x, v1 = a.y + b.y, v2 = a.z + b.z, v3 = a.w + b.w;
        v0 = (v0 > 0.f) ? v0 : 0.2f * v0;
        v1 = (v1 > 0.f) ? v1 : 0.2f * v1;
        v2 = (v2 > 0.f) ? v2 : 0.2f * v2;
        v3 = (v3 > 0.f) ? v3 : 0.2f * v3;
        float lg = v0 * t.x + v1 * t.y + v2 * t.z + v3 * t.w;
#pragma unroll
        for (int o = 16; o; o >>= 1) lg += __shfl_xor_sync(0xffffffffu, lg, o);
        float ev = expf(lg);
        if (lane == 0) atomicAdd(&s[tN * 2 + h], ev);
        float4 v = make_float4(a.x * ev, a.y * ev, a.z * ev, a.w * ev);
        atomicAdd(reinterpret_cast<float4*>(acc + (size_t)tN * 256 + h * 128 + lane * 4), v);
    }
}

// ---------------- host launch ----------------
extern "C" void kernel_launch(void* const* d_in, const int* in_sizes, int n_in,
                              void* d_out, int out_size)
{
    const float* x    = (const float*)d_in[0];
    const int*   src  = (const int*)d_in[1];
    const int*   dst  = (const int*)d_in[2];
    const float* nw0  = (const float*)d_in[3];
    const float* nb0  = (const float*)d_in[4];
    const float* nw1  = (const float*)d_in[5];
    const float* nb1  = (const float*)d_in[6];
    const float* g1ws = (const float*)d_in[7];
    const float* g1bs = (const float*)d_in[8];
    const float* g1wd = (const float*)d_in[9];
    const float* g1bd = (const float*)d_in[10];
    const float* g1a  = (const float*)d_in[11];
    const float* g2ws = (const float*)d_in[12];
    const float* g2bs = (const float*)d_in[13];
    const float* g2wd = (const float*)d_in[14];
    const float* g2bd = (const float*)d_in[15];
    const float* g2a  = (const float*)d_in[16];
    const float* ew0  = (const float*)d_in[17];
    const float* eb0  = (const float*)d_in[18];
    const float* ew1  = (const float*)d_in[19];
    const float* eb1  = (const float*)d_in[20];
    const float* ew2  = (const float*)d_in[21];
    const float* eb2  = (const float*)d_in[22];
    float* out = (float*)d_out;

    float *tmp, *h1, *fsd, *acc, *sB, *z, *P, *b1c, *b2c;
    __half *nw0h, *nw0l, *nw1h, *nw1l, *g1h, *g1l, *g2h, *g2l, *w0h, *w0l, *w1h, *w1l;
    cudaGetSymbolAddress((void**)&tmp,  g_tmp);
    cudaGetSymbolAddress((void**)&h1,   g_h1);
    cudaGetSymbolAddress((void**)&fsd,  g_fsd);
    cudaGetSymbolAddress((void**)&acc,  g_acc);
    cudaGetSymbolAddress((void**)&sB,   g_s);
    cudaGetSymbolAddress((void**)&z,    g_z);
    cudaGetSymbolAddress((void**)&P,    g_p);
    cudaGetSymbolAddress((void**)&b1c,  g_b1cat);
    cudaGetSymbolAddress((void**)&b2c,  g_b2cat);
    cudaGetSymbolAddress((void**)&nw0h, g_nw0h);
    cudaGetSymbolAddress((void**)&nw0l, g_nw0l);
    cudaGetSymbolAddress((void**)&nw1h, g_nw1h);
    cudaGetSymbolAddress((void**)&nw1l, g_nw1l);
    cudaGetSymbolAddress((void**)&g1h,  g_g1h);
    cudaGetSymbolAddress((void**)&g1l,  g_g1l);
    cudaGetSymbolAddress((void**)&g2h,  g_g2h);
    cudaGetSymbolAddress((void**)&g2l,  g_g2l);
    cudaGetSymbolAddress((void**)&w0h,  g_w0h);
    cudaGetSymbolAddress((void**)&w0l,  g_w0l);
    cudaGetSymbolAddress((void**)&w1h,  g_w1h);
    cudaGetSymbolAddress((void**)&w1l,  g_w1l);

    cudaFuncSetAttribute(mma_gemm_kernel, cudaFuncAttributeMaxDynamicSharedMemorySize, 81920);
    cudaFuncSetAttribute(edge_mma_kernel, cudaFuncAttributeMaxDynamicSharedMemorySize, 122880);

    // launch 0: all prep in one kernel (517120 items)
    prep_kernel<<<(517120 + 255) / 256, 256>>>(
        nw0, nw1, g1ws, g1wd, g2ws, g2wd, ew0, ew1,
        g1bs, g1bd, g2bs, g2bd,
        nw0h, nw0l, nw1h, nw1l, g1h, g1l, g2h, g2l,
        w0h, w0l, w1h, w1l, b1c, b2c);

    const int MBY = (N_NODES + 127) / 128;   // 157

    // 1,2: NodeMLP
    mma_gemm_kernel<<<dim3(1, MBY), 256, 81920>>>(
        x, N_NODES, 64, nw0h, nw0l, nb0, 0, 1, nullptr, tmp, 128);
    mma_gemm_kernel<<<dim3(1, MBY), 256, 81920>>>(
        tmp, N_NODES, 128, nw1h, nw1l, nb1, 0, 1, nullptr, h1, 128);

    // 3,4,5: GAT layer 1 (launch 5 = gat_fused -> profiled)
    mma_gemm_kernel<<<dim3(4, MBY), 256, 81920>>>(
        x, N_NODES, 64, g1h, g1l, b1c, 0, 0, nullptr, fsd, 512);
    gat_init_kernel<<<(N_NODES * 256 + 255) / 256, 256>>>(sB, acc);
    gat_fused_kernel<<<N_EDGES / 8, 256>>>(fsd, g1a, src, dst, sB, acc);

    // 6,7,8: GAT layer 2
    mma_gemm_kernel<<<dim3(4, MBY), 256, 81920>>>(
        acc, N_NODES, 256, g2h, g2l, b2c, 1, 0, sB, fsd, 512);
    gat_init_kernel<<<(N_NODES * 256 + 255) / 256, 256>>>(sB, acc);
    gat_fused_kernel<<<N_EDGES / 8, 256>>>(fsd, g2a, src, dst, sB, acc);

    // 9,10: Z and P
    zbuild_kernel<<<(N_NODES * 384 + 255) / 256, 256>>>(h1, acc, sB, z);
    mma_gemm_kernel<<<dim3(8, MBY), 256, 81920>>>(
        z, N_NODES, 384, w0h, w0l, nullptr, 0, 0, nullptr, P, 1024);

    // 11: EdgeMLP fused (BM=128)
    edge_mma_kernel<<<N_EDGES / 128, 512, 122880>>>(
        P, src, dst, eb0, w1h, w1l, eb1, ew2, eb2, out);
}

// round 7
// speedup vs baseline: 7.9529x; 1.0391x over previous
#include <cuda_runtime.h>
#include <cuda_fp16.h>
#include <cstdint>

#define N_NODES 20000
#define N_EDGES 320000

// ---------------- scratch ----------------
__device__ float  g_tmp [N_NODES * 128];
__device__ float  g_h1  [N_NODES * 128];
__device__ __half g_fsd [N_NODES * 512];   // [fs | fd] per node, fp16
__device__ float  g_acc [N_NODES * 256];
__device__ float  g_s   [N_NODES * 2];
__device__ float  g_z   [N_NODES * 384];
__device__ float  g_p   [N_NODES * 1024];
__device__ __half g_nw0h[128 * 64],   g_nw0l[128 * 64];
__device__ __half g_nw1h[128 * 128],  g_nw1l[128 * 128];
__device__ __half g_g1h [512 * 64],   g_g1l [512 * 64];
__device__ __half g_g2h [512 * 256],  g_g2l [512 * 256];
__device__ __half g_w0h [1024 * 384], g_w0l [1024 * 384];
__device__ __half g_w1h [256 * 512],  g_w1l [256 * 512];
__device__ float  g_b1cat[512], g_b2cat[512];

// ---------------- PTX helpers ----------------
__device__ __forceinline__ uint32_t smem_u32(const void* p) {
    uint32_t a;
    asm("{ .reg .u64 t; cvta.to.shared.u64 t, %1; cvt.u32.u64 %0, t; }" : "=r"(a) : "l"(p));
    return a;
}
__device__ __forceinline__ void ldm_x4(uint32_t* r, uint32_t a) {
    asm volatile("ldmatrix.sync.aligned.m8n8.x4.shared.b16 {%0,%1,%2,%3}, [%4];"
                 : "=r"(r[0]), "=r"(r[1]), "=r"(r[2]), "=r"(r[3]) : "r"(a));
}
__device__ __forceinline__ void mma_f32(float* c, const uint32_t* a, const uint32_t* b) {
    asm volatile("mma.sync.aligned.m16n8k16.row.col.f32.f16.f16.f32 "
                 "{%0,%1,%2,%3}, {%4,%5,%6,%7}, {%8,%9}, {%0,%1,%2,%3};"
                 : "+f"(c[0]), "+f"(c[1]), "+f"(c[2]), "+f"(c[3])
                 : "r"(a[0]), "r"(a[1]), "r"(a[2]), "r"(a[3]), "r"(b[0]), "r"(b[1]));
}
__device__ __forceinline__ void mma_f16(uint32_t* c, const uint32_t* a, const uint32_t* b) {
    asm volatile("mma.sync.aligned.m16n8k16.row.col.f16.f16.f16.f16 "
                 "{%0,%1}, {%2,%3,%4,%5}, {%6,%7}, {%0,%1};"
                 : "+r"(c[0]), "+r"(c[1])
                 : "r"(a[0]), "r"(a[1]), "r"(a[2]), "r"(a[3]), "r"(b[0]), "r"(b[1]));
}
__device__ __forceinline__ void cp16(uint32_t d, const void* s) {
    asm volatile("cp.async.cg.shared.global [%0], [%1], 16;" :: "r"(d), "l"(s));
}
#define CP_COMMIT() asm volatile("cp.async.commit_group;")
#define CP_WAIT0()  asm volatile("cp.async.wait_group 0;")

// ================= node-side HMMA GEMM: 512 threads, 16 warps =================
// BM=128, BN=128, BK=32. 16 warps as 4M x 4N, warp tile 32x32.
// smem/stage 40960: A_hi@0, A_lo@10240, B_hi@20480, B_lo@30720 (80B row stride), 2 stages.
// Output: fp32 C, or fp16 Ch when Ch != nullptr.
__global__ void __launch_bounds__(512)
mma_gemm_kernel(const float* __restrict__ A, int M, int K,
                const __half* __restrict__ Bh, const __half* __restrict__ Bl,
                const float* __restrict__ bias, int in_relu, int out_relu,
                const float* __restrict__ rowscale,
                float* __restrict__ C, __half* __restrict__ Ch, int NTOT)
{
    extern __shared__ char smd[];
    const uint32_t sb = smem_u32(smd);
    const int tid  = threadIdx.x;
    const int lane = tid & 31;
    const int wid  = tid >> 5;        // 0..15
    const int wm   = wid >> 2;        // 0..3
    const int wn   = wid & 3;         // 0..3
    const int bm0  = blockIdx.y * 128;
    const int n0   = blockIdx.x * 128;
    const int ra   = tid >> 2;        // loader row 0..127
    const int ua   = tid & 3;         // 16B k-unit 0..3

    float acc[2][4][4];
    uint32_t acx[2][4][2];
#pragma unroll
    for (int a = 0; a < 2; a++)
#pragma unroll
        for (int b = 0; b < 4; b++) {
#pragma unroll
            for (int c = 0; c < 4; c++) acc[a][b][c] = 0.f;
            acx[a][b][0] = 0u; acx[a][b][1] = 0u;
        }

    const int NC = K >> 5;
    float apre[8];

    auto prefA = [&](int c) {
        const int kb = c * 32 + ua * 8;
        const int m = bm0 + ra;
        if (m < M) {
            const float4* p = reinterpret_cast<const float4*>(A + (size_t)m * K + kb);
#pragma unroll
            for (int i = 0; i < 2; i++) {
                float4 v = p[i];
                apre[i * 4 + 0] = v.x; apre[i * 4 + 1] = v.y;
                apre[i * 4 + 2] = v.z; apre[i * 4 + 3] = v.w;
            }
            if (rowscale) {
                float rs = 1.f / rowscale[m * 2 + (kb >= 128 ? 1 : 0)];
#pragma unroll
                for (int i = 0; i < 8; i++) apre[i] *= rs;
            }
            if (in_relu) {
#pragma unroll
                for (int i = 0; i < 8; i++) apre[i] = fmaxf(apre[i], 0.f);
            }
        } else {
#pragma unroll
            for (int i = 0; i < 8; i++) apre[i] = 0.f;
        }
    };

    auto storeA = [&](int s) {
        char* base = smd + s * 40960;
        __half2 h2[4], l2[4];
#pragma unroll
        for (int j = 0; j < 4; j++) {
            float f0 = apre[2 * j], f1 = apre[2 * j + 1];
            __half h0 = __float2half_rn(f0), h1 = __float2half_rn(f1);
            h2[j] = __halves2half2(h0, h1);
            l2[j] = __halves2half2(__float2half_rn(f0 - __half2float(h0)),
                                   __float2half_rn(f1 - __half2float(h1)));
        }
        *reinterpret_cast<uint4*>(base + ra * 80 + ua * 16) = *reinterpret_cast<uint4*>(h2);
        *reinterpret_cast<uint4*>(base + 10240 + ra * 80 + ua * 16) = *reinterpret_cast<uint4*>(l2);
    };

    auto cpB = [&](int c, int s) {
        const size_t go = (size_t)(n0 + ra) * K + c * 32 + ua * 8;
        const uint32_t db = sb + s * 40960 + 20480 + ra * 80 + ua * 16;
        cp16(db,         Bh + go);
        cp16(db + 10240, Bl + go);
    };

    auto comp = [&](int s) {
        const uint32_t base = sb + s * 40960;
#pragma unroll
        for (int ks = 0; ks < 2; ks++) {
            uint32_t ah[2][4], al[2][4], bh[4][2], bl[4][2];
            const uint32_t arow = wm * 32 + (lane & 15);
            const uint32_t au = ks * 2 + (lane >> 4);
#pragma unroll
            for (int mt = 0; mt < 2; mt++) {
                const uint32_t ad = base + (arow + mt * 16) * 80 + au * 16;
                ldm_x4(ah[mt], ad);
                ldm_x4(al[mt], ad + 10240);
            }
            const uint32_t brow0 = wn * 32 + (lane & 7) + ((lane >> 4) << 3);
            const uint32_t bu = ks * 2 + ((lane >> 3) & 1);
#pragma unroll
            for (int pr = 0; pr < 2; pr++) {
                uint32_t t[4];
                const uint32_t bd = base + 20480 + (brow0 + pr * 16) * 80 + bu * 16;
                ldm_x4(t, bd);
                bh[2 * pr][0] = t[0]; bh[2 * pr][1] = t[1];
                bh[2 * pr + 1][0] = t[2]; bh[2 * pr + 1][1] = t[3];
                ldm_x4(t, bd + 10240);
                bl[2 * pr][0] = t[0]; bl[2 * pr][1] = t[1];
                bl[2 * pr + 1][0] = t[2]; bl[2 * pr + 1][1] = t[3];
            }
#pragma unroll
            for (int mt = 0; mt < 2; mt++)
#pragma unroll
                for (int nt = 0; nt < 4; nt++) {
                    mma_f32(acc[mt][nt], ah[mt], bh[nt]);
                    mma_f16(acx[mt][nt], ah[mt], bl[nt]);
                    mma_f16(acx[mt][nt], al[mt], bh[nt]);
                }
        }
    };

    prefA(0); storeA(0); cpB(0, 0);
    CP_COMMIT(); CP_WAIT0();
    __syncthreads();

    for (int c = 0; c < NC; c++) {
        const int s = c & 1;
        if (c + 1 < NC) { prefA(c + 1); cpB(c + 1, s ^ 1); CP_COMMIT(); }
        comp(s);
        if (c + 1 < NC) { storeA(s ^ 1); CP_WAIT0(); }
        __syncthreads();
    }

#pragma unroll
    for (int mt = 0; mt < 2; mt++)
#pragma unroll
        for (int nt = 0; nt < 4; nt++) {
            float2 f0 = __half22float2(*reinterpret_cast<__half2*>(&acx[mt][nt][0]));
            float2 f1 = __half22float2(*reinterpret_cast<__half2*>(&acx[mt][nt][1]));
            acc[mt][nt][0] += f0.x; acc[mt][nt][1] += f0.y;
            acc[mt][nt][2] += f1.x; acc[mt][nt][3] += f1.y;
        }

#pragma unroll
    for (int mt = 0; mt < 2; mt++) {
        const int row = bm0 + wm * 32 + mt * 16 + (lane >> 2);
#pragma unroll
        for (int nt = 0; nt < 4; nt++) {
            const int col = n0 + wn * 32 + nt * 8 + 2 * (lane & 3);
            float b0 = bias ? bias[col] : 0.f;
            float b1 = bias ? bias[col + 1] : 0.f;
            float v0 = acc[mt][nt][0] + b0, v1 = acc[mt][nt][1] + b1;
            float v2 = acc[mt][nt][2] + b0, v3 = acc[mt][nt][3] + b1;
            if (out_relu) {
                v0 = fmaxf(v0, 0.f); v1 = fmaxf(v1, 0.f);
                v2 = fmaxf(v2, 0.f); v3 = fmaxf(v3, 0.f);
            }
            if (Ch) {
                if (row < M)
                    *reinterpret_cast<__half2*>(Ch + (size_t)row * NTOT + col) =
                        __floats2half2_rn(v0, v1);
                if (row + 8 < M)
                    *reinterpret_cast<__half2*>(Ch + (size_t)(row + 8) * NTOT + col) =
                        __floats2half2_rn(v2, v3);
            } else {
                if (row < M)
                    *reinterpret_cast<float2*>(C + (size_t)row * NTOT + col) = make_float2(v0, v1);
                if (row + 8 < M)
                    *reinterpret_cast<float2*>(C + (size_t)(row + 8) * NTOT + col) = make_float2(v2, v3);
            }
        }
    }
}

// ================= edge HMMA kernel: BM=128, BN=256, 512 threads (proven) =================
__global__ void __launch_bounds__(512)
edge_mma_kernel(const float* __restrict__ P,
                const int* __restrict__ src, const int* __restrict__ dst,
                const float* __restrict__ eb0,
                const __half* __restrict__ Bh, const __half* __restrict__ Bl,
                const float* __restrict__ eb1, const float* __restrict__ ew2,
                const float* __restrict__ eb2, float* __restrict__ out)
{
    extern __shared__ char smd[];
    __shared__ float red[128];
    const uint32_t sb = smem_u32(smd);
    const int tid  = threadIdx.x;
    const int lane = tid & 31;
    const int wid  = tid >> 5;
    const int wm   = wid >> 2;
    const int wn   = wid & 3;
    const int e0   = blockIdx.x * 128;
    const int ra   = tid >> 2;
    const int ua   = tid & 3;
    const int rb   = tid >> 1;
    const int ub   = (tid & 1) * 2;

    const int sn = src[e0 + ra];
    const int dn = dst[e0 + ra];
    if (tid < 128) red[tid] = 0.f;

    float acc[2][8][4];
    uint32_t acx[2][8][2];
#pragma unroll
    for (int a = 0; a < 2; a++)
#pragma unroll
        for (int b = 0; b < 8; b++) {
#pragma unroll
            for (int c = 0; c < 4; c++) acc[a][b][c] = 0.f;
            acx[a][b][0] = 0u; acx[a][b][1] = 0u;
        }

    float apre[8];

    auto prefA = [&](int c) {
        const int kb = c * 32 + ua * 8;
        const float4* ps = reinterpret_cast<const float4*>(P + (size_t)sn * 1024 + kb);
        const float4* pd = reinterpret_cast<const float4*>(P + (size_t)dn * 1024 + 512 + kb);
        const float4* pb = reinterpret_cast<const float4*>(eb0 + kb);
#pragma unroll
        for (int i = 0; i < 2; i++) {
            float4 a4 = ps[i], b4 = pd[i], c4 = pb[i];
            apre[i * 4 + 0] = fmaxf(a4.x + b4.x + c4.x, 0.f);
            apre[i * 4 + 1] = fmaxf(a4.y + b4.y + c4.y, 0.f);
            apre[i * 4 + 2] = fmaxf(a4.z + b4.z + c4.z, 0.f);
            apre[i * 4 + 3] = fmaxf(a4.w + b4.w + c4.w, 0.f);
        }
    };

    auto storeA = [&](int s) {
        char* base = smd + s * 61440;
        __half2 h2[4], l2[4];
#pragma unroll
        for (int j = 0; j < 4; j++) {
            float f0 = apre[2 * j], f1 = apre[2 * j + 1];
            __half h0 = __float2half_rn(f0), h1 = __float2half_rn(f1);
            h2[j] = __halves2half2(h0, h1);
            l2[j] = __halves2half2(__float2half_rn(f0 - __half2float(h0)),
                                   __float2half_rn(f1 - __half2float(h1)));
        }
        *reinterpret_cast<uint4*>(base + ra * 80 + ua * 16) = *reinterpret_cast<uint4*>(h2);
        *reinterpret_cast<uint4*>(base + 10240 + ra * 80 + ua * 16) = *reinterpret_cast<uint4*>(l2);
    };

    auto cpB = [&](int c, int s) {
        const size_t go = (size_t)rb * 512 + c * 32;
        const uint32_t db = sb + s * 61440 + 20480 + rb * 80;
#pragma unroll
        for (int u = 0; u < 2; u++) {
            cp16(db + (ub + u) * 16,         Bh + go + (ub + u) * 8);
            cp16(db + 20480 + (ub + u) * 16, Bl + go + (ub + u) * 8);
        }
    };

    auto comp = [&](int s) {
        const uint32_t base = sb + s * 61440;
#pragma unroll
        for (int ks = 0; ks < 2; ks++) {
            uint32_t ah[2][4], al[2][4], bh[8][2], bl[8][2];
            const uint32_t arow = wm * 32 + (lane & 15);
            const uint32_t au = ks * 2 + (lane >> 4);
#pragma unroll
            for (int mt = 0; mt < 2; mt++) {
                const uint32_t ad = base + (arow + mt * 16) * 80 + au * 16;
                ldm_x4(ah[mt], ad);
                ldm_x4(al[mt], ad + 10240);
            }
            const uint32_t brow0 = wn * 64 + (lane & 7) + ((lane >> 4) << 3);
            const uint32_t bu = ks * 2 + ((lane >> 3) & 1);
#pragma unroll
            for (int pr = 0; pr < 4; pr++) {
                uint32_t t[4];
                const uint32_t bd = base + 20480 + (brow0 + pr * 16) * 80 + bu * 16;
                ldm_x4(t, bd);
                bh[2 * pr][0] = t[0]; bh[2 * pr][1] = t[1];
                bh[2 * pr + 1][0] = t[2]; bh[2 * pr + 1][1] = t[3];
                ldm_x4(t, bd + 20480);
                bl[2 * pr][0] = t[0]; bl[2 * pr][1] = t[1];
                bl[2 * pr + 1][0] = t[2]; bl[2 * pr + 1][1] = t[3];
            }
#pragma unroll
            for (int mt = 0; mt < 2; mt++)
#pragma unroll
                for (int nt = 0; nt < 8; nt++) {
                    mma_f32(acc[mt][nt], ah[mt], bh[nt]);
                    mma_f16(acx[mt][nt], ah[mt], bl[nt]);
                    mma_f16(acx[mt][nt], al[mt], bh[nt]);
                }
        }
    };

    prefA(0); storeA(0); cpB(0, 0);
    CP_COMMIT(); CP_WAIT0();
    __syncthreads();

#pragma unroll 1
    for (int c = 0; c < 16; c++) {
        const int s = c & 1;
        if (c + 1 < 16) { prefA(c + 1); cpB(c + 1, s ^ 1); CP_COMMIT(); }
        comp(s);
        if (c + 1 < 16) { storeA(s ^ 1); CP_WAIT0(); }
        __syncthreads();
    }

#pragma unroll
    for (int mt = 0; mt < 2; mt++) {
        float p0 = 0.f, p1 = 0.f;
#pragma unroll
        for (int nt = 0; nt < 8; nt++) {
            float2 f0 = __half22float2(*reinterpret_cast<__half2*>(&acx[mt][nt][0]));
            float2 f1 = __half22float2(*reinterpret_cast<__half2*>(&acx[mt][nt][1]));
            const int col = wn * 64 + nt * 8 + 2 * (lane & 3);
            const float b0 = eb1[col], b1 = eb1[col + 1];
            const float w0 = ew2[col], w1 = ew2[col + 1];
            p0 += fmaxf(acc[mt][nt][0] + f0.x + b0, 0.f) * w0
                + fmaxf(acc[mt][nt][1] + f0.y + b1, 0.f) * w1;
            p1 += fmaxf(acc[mt][nt][2] + f1.x + b0, 0.f) * w0
                + fmaxf(acc[mt][nt][3] + f1.y + b1, 0.f) * w1;
        }
        p0 += __shfl_xor_sync(0xffffffffu, p0, 1);
        p0 += __shfl_xor_sync(0xffffffffu, p0, 2);
        p1 += __shfl_xor_sync(0xffffffffu, p1, 1);
        p1 += __shfl_xor_sync(0xffffffffu, p1, 2);
        if ((lane & 3) == 0) {
            atomicAdd(&red[wm * 32 + mt * 16 + (lane >> 2)], p0);
            atomicAdd(&red[wm * 32 + mt * 16 + (lane >> 2) + 8], p1);
        }
    }
    __syncthreads();
    if (tid < 128) out[e0 + tid] = red[tid] + eb2[0];
}

// ================= fused prep kernel =================
__device__ __forceinline__ void split_at(const float* W, __half* th, __half* tl,
                                         int K, int N, int i)
{
    int n = i / K, k = i % K;
    float f = W[(size_t)k * N + n];
    __half h = __float2half_rn(f);
    th[i] = h; tl[i] = __float2half_rn(f - __half2float(h));
}

__global__ void prep_kernel(const float* nw0, const float* nw1,
                            const float* g1ws, const float* g1wd,
                            const float* g2ws, const float* g2wd,
                            const float* ew0, const float* ew1,
                            const float* g1bs, const float* g1bd,
                            const float* g2bs, const float* g2bd,
                            __half* nw0h, __half* nw0l, __half* nw1h, __half* nw1l,
                            __half* g1h, __half* g1l, __half* g2h, __half* g2l,
                            __half* w0h, __half* w0l, __half* w1h, __half* w1l,
                            float* b1c, float* b2c)
{
    int i = blockIdx.x * blockDim.x + threadIdx.x;
    if (i < 8192) { split_at(nw0, nw0h, nw0l, 64, 128, i); return; }
    i -= 8192;
    if (i < 16384) { split_at(nw1, nw1h, nw1l, 128, 128, i); return; }
    i -= 16384;
    if (i < 16384) { split_at(g1ws, g1h, g1l, 64, 256, i); return; }
    i -= 16384;
    if (i < 16384) { split_at(g1wd, g1h + 16384, g1l + 16384, 64, 256, i); return; }
    i -= 16384;
    if (i < 65536) { split_at(g2ws, g2h, g2l, 256, 256, i); return; }
    i -= 65536;
    if (i < 65536) { split_at(g2wd, g2h + 65536, g2l + 65536, 256, 256, i); return; }
    i -= 65536;
    if (i < 196608) {
        int n = i / 384, k = i % 384;
        int rs = (k < 128) ? k : k + 128;
        int rd = (k < 128) ? k + 128 : k + 384;
        float f = ew0[rs * 512 + n];
        __half h = __float2half_rn(f);
        w0h[i] = h; w0l[i] = __float2half_rn(f - __half2float(h));
        f = ew0[rd * 512 + n];
        h = __float2half_rn(f);
        w0h[196608 + i] = h;
        w0l[196608 + i] = __float2half_rn(f - __half2float(h));
        return;
    }
    i -= 196608;
    if (i < 131072) { split_at(ew1, w1h, w1l, 512, 256, i); return; }
    i -= 131072;
    if (i < 512) { b1c[i] = (i < 256) ? g1bs[i] : g1bd[i - 256]; return; }
    i -= 512;
    if (i < 512) { b2c[i] = (i < 256) ? g2bs[i] : g2bd[i - 256]; return; }
}

// ---------------- misc kernels ----------------
__global__ void zbuild_kernel(const float* __restrict__ h1, const float* __restrict__ a2,
                              const float* __restrict__ s, float* __restrict__ z)
{
    int i = blockIdx.x * blockDim.x + threadIdx.x;
    if (i >= N_NODES * 384) return;
    int n = i / 384, j = i % 384;
    if (j < 128) z[i] = h1[n * 128 + j];
    else {
        int q = j - 128;
        z[i] = fmaxf(a2[n * 256 + q] / s[n * 2 + (q >= 128 ? 1 : 0)], 0.f);
    }
}

__global__ void gat_init_kernel(float* s, float* acc)
{
    int i = blockIdx.x * blockDim.x + threadIdx.x;
    if (i < N_NODES * 256) acc[i] = 0.f;
    if (i < N_NODES * 2) s[i] = 0.f;
}

// fused GAT pass, fp16 feature gather
__global__ void gat_fused_kernel(const __half* __restrict__ fsd,
                                 const float* __restrict__ attn,
                                 const int* __restrict__ src, const int* __restrict__ dst,
                                 float* __restrict__ s, float* __restrict__ acc)
{
    int e = (blockIdx.x * blockDim.x + threadIdx.x) >> 5;
    int lane = threadIdx.x & 31;
    if (e >= N_EDGES) return;
    int sN = src[e], tN = dst[e];
#pragma unroll
    for (int h = 0; h < 2; h++) {
        const __half2* pa = reinterpret_cast<const __half2*>(fsd + (size_t)sN * 512 + h * 128 + lane * 4);
        const __half2* pb = reinterpret_cast<const __half2*>(fsd + (size_t)tN * 512 + 256 + h * 128 + lane * 4);
        float2 a0 = __half22float2(pa[0]), a1 = __half22float2(pa[1]);
        float2 b0 = __half22float2(pb[0]), b1 = __half22float2(pb[1]);
        float4 t = *reinterpret_cast<const float4*>(attn + h * 128 + lane * 4);
        float v0 = a0.x + b0.x, v1 = a0.y + b0.y, v2 = a1.x + b1.x, v3 = a1.y + b1.y;
        v0 = (v0 > 0.f) ? v0 : 0.2f * v0;
        v1 = (v1 > 0.f) ? v1 : 0.2f * v1;
        v2 = (v2 > 0.f) ? v2 : 0.2f * v2;
        v3 = (v3 > 0.f) ? v3 : 0.2f * v3;
        float lg = v0 * t.x + v1 * t.y + v2 * t.z + v3 * t.w;
#pragma unroll
        for (int o = 16; o; o >>= 1) lg += __shfl_xor_sync(0xffffffffu, lg, o);
        float ev = expf(lg);
        if (lane == 0) atomicAdd(&s[tN * 2 + h], ev);
        float4 v = make_float4(a0.x * ev, a0.y * ev, a1.x * ev, a1.y * ev);
        atomicAdd(reinterpret_cast<float4*>(acc + (size_t)tN * 256 + h * 128 + lane * 4), v);
    }
}

// ---------------- host launch ----------------
extern "C" void kernel_launch(void* const* d_in, const int* in_sizes, int n_in,
                              void* d_out, int out_size)
{
    const float* x    = (const float*)d_in[0];
    const int*   src  = (const int*)d_in[1];
    const int*   dst  = (const int*)d_in[2];
    const float* nw0  = (const float*)d_in[3];
    const float* nb0  = (const float*)d_in[4];
    const float* nw1  = (const float*)d_in[5];
    const float* nb1  = (const float*)d_in[6];
    const float* g1ws = (const float*)d_in[7];
    const float* g1bs = (const float*)d_in[8];
    const float* g1wd = (const float*)d_in[9];
    const float* g1bd = (const float*)d_in[10];
    const float* g1a  = (const float*)d_in[11];
    const float* g2ws = (const float*)d_in[12];
    const float* g2bs = (const float*)d_in[13];
    const float* g2wd = (const float*)d_in[14];
    const float* g2bd = (const float*)d_in[15];
    const float* g2a  = (const float*)d_in[16];
    const float* ew0  = (const float*)d_in[17];
    const float* eb0  = (const float*)d_in[18];
    const float* ew1  = (const float*)d_in[19];
    const float* eb1  = (const float*)d_in[20];
    const float* ew2  = (const float*)d_in[21];
    const float* eb2  = (const float*)d_in[22];
    float* out = (float*)d_out;

    float *tmp, *h1, *acc, *sB, *z, *P, *b1c, *b2c;
    __half *fsd;
    __half *nw0h, *nw0l, *nw1h, *nw1l, *g1h, *g1l, *g2h, *g2l, *w0h, *w0l, *w1h, *w1l;
    cudaGetSymbolAddress((void**)&tmp,  g_tmp);
    cudaGetSymbolAddress((void**)&h1,   g_h1);
    cudaGetSymbolAddress((void**)&fsd,  g_fsd);
    cudaGetSymbolAddress((void**)&acc,  g_acc);
    cudaGetSymbolAddress((void**)&sB,   g_s);
    cudaGetSymbolAddress((void**)&z,    g_z);
    cudaGetSymbolAddress((void**)&P,    g_p);
    cudaGetSymbolAddress((void**)&b1c,  g_b1cat);
    cudaGetSymbolAddress((void**)&b2c,  g_b2cat);
    cudaGetSymbolAddress((void**)&nw0h, g_nw0h);
    cudaGetSymbolAddress((void**)&nw0l, g_nw0l);
    cudaGetSymbolAddress((void**)&nw1h, g_nw1h);
    cudaGetSymbolAddress((void**)&nw1l, g_nw1l);
    cudaGetSymbolAddress((void**)&g1h,  g_g1h);
    cudaGetSymbolAddress((void**)&g1l,  g_g1l);
    cudaGetSymbolAddress((void**)&g2h,  g_g2h);
    cudaGetSymbolAddress((void**)&g2l,  g_g2l);
    cudaGetSymbolAddress((void**)&w0h,  g_w0h);
    cudaGetSymbolAddress((void**)&w0l,  g_w0l);
    cudaGetSymbolAddress((void**)&w1h,  g_w1h);
    cudaGetSymbolAddress((void**)&w1l,  g_w1l);

    cudaFuncSetAttribute(mma_gemm_kernel, cudaFuncAttributeMaxDynamicSharedMemorySize, 81920);
    cudaFuncSetAttribute(edge_mma_kernel, cudaFuncAttributeMaxDynamicSharedMemorySize, 122880);

    // 0: prep
    prep_kernel<<<(517120 + 255) / 256, 256>>>(
        nw0, nw1, g1ws, g1wd, g2ws, g2wd, ew0, ew1,
        g1bs, g1bd, g2bs, g2bd,
        nw0h, nw0l, nw1h, nw1l, g1h, g1l, g2h, g2l,
        w0h, w0l, w1h, w1l, b1c, b2c);

    const int MBY = (N_NODES + 127) / 128;   // 157

    // 1,2: NodeMLP (fp32 out)
    mma_gemm_kernel<<<dim3(1, MBY), 512, 81920>>>(
        x, N_NODES, 64, nw0h, nw0l, nb0, 0, 1, nullptr, tmp, nullptr, 128);
    mma_gemm_kernel<<<dim3(1, MBY), 512, 81920>>>(
        tmp, N_NODES, 128, nw1h, nw1l, nb1, 0, 1, nullptr, h1, nullptr, 128);

    // 3,4,5: GAT layer 1 (fsd fp16 out)
    mma_gemm_kernel<<<dim3(4, MBY), 512, 81920>>>(
        x, N_NODES, 64, g1h, g1l, b1c, 0, 0, nullptr, nullptr, fsd, 512);
    gat_init_kernel<<<(N_NODES * 256 + 255) / 256, 256>>>(sB, acc);
    gat_fused_kernel<<<N_EDGES / 8, 256>>>(fsd, g1a, src, dst, sB, acc);

    // 6,7,8: GAT layer 2
    mma_gemm_kernel<<<dim3(4, MBY), 512, 81920>>>(
        acc, N_NODES, 256, g2h, g2l, b2c, 1, 0, sB, nullptr, fsd, 512);
    gat_init_kernel<<<(N_NODES * 256 + 255) / 256, 256>>>(sB, acc);
    gat_fused_kernel<<<N_EDGES / 8, 256>>>(fsd, g2a, src, dst, sB, acc);

    // 9,10: Z and P (fp32)
    zbuild_kernel<<<(N_NODES * 384 + 255) / 256, 256>>>(h1, acc, sB, z);
    mma_gemm_kernel<<<dim3(8, MBY), 512, 81920>>>(
        z, N_NODES, 384, w0h, w0l, nullptr, 0, 0, nullptr, P, nullptr, 1024);

    // 11: EdgeMLP fused
    edge_mma_kernel<<<N_EDGES / 128, 512, 122880>>>(
        P, src, dst, eb0, w1h, w1l, eb1, ew2, eb2, out);
}

// round 8
// speedup vs baseline: 11.3406x; 1.4260x over previous
#include <cuda_runtime.h>
#include <cuda_fp16.h>
#include <cstdint>

#define N_NODES 20000
#define N_EDGES 320000

// ---------------- scratch ----------------
__device__ float  g_tmp [N_NODES * 128];
__device__ float  g_h1  [N_NODES * 128];
__device__ __half g_fsd [N_NODES * 512];   // [fs | fd] per node, fp16
__device__ float  g_acc [N_NODES * 256];
__device__ float  g_s   [N_NODES * 2];
__device__ float  g_z   [N_NODES * 384];
__device__ __half g_p   [N_NODES * 1024];  // [Psrc | Pdst], fp16
__device__ __half g_nw0h[128 * 64],   g_nw0l[128 * 64];
__device__ __half g_nw1h[128 * 128],  g_nw1l[128 * 128];
__device__ __half g_g1h [512 * 64],   g_g1l [512 * 64];
__device__ __half g_g2h [512 * 256],  g_g2l [512 * 256];
__device__ __half g_w0h [1024 * 384], g_w0l [1024 * 384];
__device__ __half g_w1h [256 * 512],  g_w1l [256 * 512];
__device__ float  g_b1cat[512], g_b2cat[512];

// ---------------- PTX helpers ----------------
__device__ __forceinline__ uint32_t smem_u32(const void* p) {
    uint32_t a;
    asm("{ .reg .u64 t; cvta.to.shared.u64 t, %1; cvt.u32.u64 %0, t; }" : "=r"(a) : "l"(p));
    return a;
}
__device__ __forceinline__ void ldm_x4(uint32_t* r, uint32_t a) {
    asm volatile("ldmatrix.sync.aligned.m8n8.x4.shared.b16 {%0,%1,%2,%3}, [%4];"
                 : "=r"(r[0]), "=r"(r[1]), "=r"(r[2]), "=r"(r[3]) : "r"(a));
}
__device__ __forceinline__ void mma_f32(float* c, const uint32_t* a, const uint32_t* b) {
    asm volatile("mma.sync.aligned.m16n8k16.row.col.f32.f16.f16.f32 "
                 "{%0,%1,%2,%3}, {%4,%5,%6,%7}, {%8,%9}, {%0,%1,%2,%3};"
                 : "+f"(c[0]), "+f"(c[1]), "+f"(c[2]), "+f"(c[3])
                 : "r"(a[0]), "r"(a[1]), "r"(a[2]), "r"(a[3]), "r"(b[0]), "r"(b[1]));
}
__device__ __forceinline__ void mma_f16(uint32_t* c, const uint32_t* a, const uint32_t* b) {
    asm volatile("mma.sync.aligned.m16n8k16.row.col.f16.f16.f16.f16 "
                 "{%0,%1}, {%2,%3,%4,%5}, {%6,%7}, {%0,%1};"
                 : "+r"(c[0]), "+r"(c[1])
                 : "r"(a[0]), "r"(a[1]), "r"(a[2]), "r"(a[3]), "r"(b[0]), "r"(b[1]));
}
__device__ __forceinline__ void cp16(uint32_t d, const void* s) {
    asm volatile("cp.async.cg.shared.global [%0], [%1], 16;" :: "r"(d), "l"(s));
}
#define CP_COMMIT() asm volatile("cp.async.commit_group;")
#define CP_WAIT0()  asm volatile("cp.async.wait_group 0;")

// ================= node-side HMMA GEMM: 512 threads, 16 warps (proven) =================
__global__ void __launch_bounds__(512)
mma_gemm_kernel(const float* __restrict__ A, int M, int K,
                const __half* __restrict__ Bh, const __half* __restrict__ Bl,
                const float* __restrict__ bias, int in_relu, int out_relu,
                const float* __restrict__ rowscale,
                float* __restrict__ C, __half* __restrict__ Ch, int NTOT)
{
    extern __shared__ char smd[];
    const uint32_t sb = smem_u32(smd);
    const int tid  = threadIdx.x;
    const int lane = tid & 31;
    const int wid  = tid >> 5;
    const int wm   = wid >> 2;
    const int wn   = wid & 3;
    const int bm0  = blockIdx.y * 128;
    const int n0   = blockIdx.x * 128;
    const int ra   = tid >> 2;
    const int ua   = tid & 3;

    float acc[2][4][4];
    uint32_t acx[2][4][2];
#pragma unroll
    for (int a = 0; a < 2; a++)
#pragma unroll
        for (int b = 0; b < 4; b++) {
#pragma unroll
            for (int c = 0; c < 4; c++) acc[a][b][c] = 0.f;
            acx[a][b][0] = 0u; acx[a][b][1] = 0u;
        }

    const int NC = K >> 5;
    float apre[8];

    auto prefA = [&](int c) {
        const int kb = c * 32 + ua * 8;
        const int m = bm0 + ra;
        if (m < M) {
            const float4* p = reinterpret_cast<const float4*>(A + (size_t)m * K + kb);
#pragma unroll
            for (int i = 0; i < 2; i++) {
                float4 v = p[i];
                apre[i * 4 + 0] = v.x; apre[i * 4 + 1] = v.y;
                apre[i * 4 + 2] = v.z; apre[i * 4 + 3] = v.w;
            }
            if (rowscale) {
                float rs = 1.f / rowscale[m * 2 + (kb >= 128 ? 1 : 0)];
#pragma unroll
                for (int i = 0; i < 8; i++) apre[i] *= rs;
            }
            if (in_relu) {
#pragma unroll
                for (int i = 0; i < 8; i++) apre[i] = fmaxf(apre[i], 0.f);
            }
        } else {
#pragma unroll
            for (int i = 0; i < 8; i++) apre[i] = 0.f;
        }
    };

    auto storeA = [&](int s) {
        char* base = smd + s * 40960;
        __half2 h2[4], l2[4];
#pragma unroll
        for (int j = 0; j < 4; j++) {
            float f0 = apre[2 * j], f1 = apre[2 * j + 1];
            __half h0 = __float2half_rn(f0), h1 = __float2half_rn(f1);
            h2[j] = __halves2half2(h0, h1);
            l2[j] = __halves2half2(__float2half_rn(f0 - __half2float(h0)),
                                   __float2half_rn(f1 - __half2float(h1)));
        }
        *reinterpret_cast<uint4*>(base + ra * 80 + ua * 16) = *reinterpret_cast<uint4*>(h2);
        *reinterpret_cast<uint4*>(base + 10240 + ra * 80 + ua * 16) = *reinterpret_cast<uint4*>(l2);
    };

    auto cpB = [&](int c, int s) {
        const size_t go = (size_t)(n0 + ra) * K + c * 32 + ua * 8;
        const uint32_t db = sb + s * 40960 + 20480 + ra * 80 + ua * 16;
        cp16(db,         Bh + go);
        cp16(db + 10240, Bl + go);
    };

    auto comp = [&](int s) {
        const uint32_t base = sb + s * 40960;
#pragma unroll
        for (int ks = 0; ks < 2; ks++) {
            uint32_t ah[2][4], al[2][4], bh[4][2], bl[4][2];
            const uint32_t arow = wm * 32 + (lane & 15);
            const uint32_t au = ks * 2 + (lane >> 4);
#pragma unroll
            for (int mt = 0; mt < 2; mt++) {
                const uint32_t ad = base + (arow + mt * 16) * 80 + au * 16;
                ldm_x4(ah[mt], ad);
                ldm_x4(al[mt], ad + 10240);
            }
            const uint32_t brow0 = wn * 32 + (lane & 7) + ((lane >> 4) << 3);
            const uint32_t bu = ks * 2 + ((lane >> 3) & 1);
#pragma unroll
            for (int pr = 0; pr < 2; pr++) {
                uint32_t t[4];
                const uint32_t bd = base + 20480 + (brow0 + pr * 16) * 80 + bu * 16;
                ldm_x4(t, bd);
                bh[2 * pr][0] = t[0]; bh[2 * pr][1] = t[1];
                bh[2 * pr + 1][0] = t[2]; bh[2 * pr + 1][1] = t[3];
                ldm_x4(t, bd + 10240);
                bl[2 * pr][0] = t[0]; bl[2 * pr][1] = t[1];
                bl[2 * pr + 1][0] = t[2]; bl[2 * pr + 1][1] = t[3];
            }
#pragma unroll
            for (int mt = 0; mt < 2; mt++)
#pragma unroll
                for (int nt = 0; nt < 4; nt++) {
                    mma_f32(acc[mt][nt], ah[mt], bh[nt]);
                    mma_f16(acx[mt][nt], ah[mt], bl[nt]);
                    mma_f16(acx[mt][nt], al[mt], bh[nt]);
                }
        }
    };

    prefA(0); storeA(0); cpB(0, 0);
    CP_COMMIT(); CP_WAIT0();
    __syncthreads();

    for (int c = 0; c < NC; c++) {
        const int s = c & 1;
        if (c + 1 < NC) { prefA(c + 1); cpB(c + 1, s ^ 1); CP_COMMIT(); }
        comp(s);
        if (c + 1 < NC) { storeA(s ^ 1); CP_WAIT0(); }
        __syncthreads();
    }

#pragma unroll
    for (int mt = 0; mt < 2; mt++)
#pragma unroll
        for (int nt = 0; nt < 4; nt++) {
            float2 f0 = __half22float2(*reinterpret_cast<__half2*>(&acx[mt][nt][0]));
            float2 f1 = __half22float2(*reinterpret_cast<__half2*>(&acx[mt][nt][1]));
            acc[mt][nt][0] += f0.x; acc[mt][nt][1] += f0.y;
            acc[mt][nt][2] += f1.x; acc[mt][nt][3] += f1.y;
        }

#pragma unroll
    for (int mt = 0; mt < 2; mt++) {
        const int row = bm0 + wm * 32 + mt * 16 + (lane >> 2);
#pragma unroll
        for (int nt = 0; nt < 4; nt++) {
            const int col = n0 + wn * 32 + nt * 8 + 2 * (lane & 3);
            float b0 = bias ? bias[col] : 0.f;
            float b1 = bias ? bias[col + 1] : 0.f;
            float v0 = acc[mt][nt][0] + b0, v1 = acc[mt][nt][1] + b1;
            float v2 = acc[mt][nt][2] + b0, v3 = acc[mt][nt][3] + b1;
            if (out_relu) {
                v0 = fmaxf(v0, 0.f); v1 = fmaxf(v1, 0.f);
                v2 = fmaxf(v2, 0.f); v3 = fmaxf(v3, 0.f);
            }
            if (Ch) {
                if (row < M)
                    *reinterpret_cast<__half2*>(Ch + (size_t)row * NTOT + col) =
                        __floats2half2_rn(v0, v1);
                if (row + 8 < M)
                    *reinterpret_cast<__half2*>(Ch + (size_t)(row + 8) * NTOT + col) =
                        __floats2half2_rn(v2, v3);
            } else {
                if (row < M)
                    *reinterpret_cast<float2*>(C + (size_t)row * NTOT + col) = make_float2(v0, v1);
                if (row + 8 < M)
                    *reinterpret_cast<float2*>(C + (size_t)(row + 8) * NTOT + col) = make_float2(v2, v3);
            }
        }
    }
}

// ================= edge HMMA kernel: pure fp16, BM=128, BN=256, 512 threads =================
// A(e,k) = fp16(relu(P[src[e]][k] + P[dst[e]][512+k] + eb0[k])); P fp16; K=512.
// Single-term HMMA (fp32 acc). smem/stage 30720: A@0 (128x80), B@10240 (256x80).
__global__ void __launch_bounds__(512)
edge_mma_kernel(const __half* __restrict__ P,
                const int* __restrict__ src, const int* __restrict__ dst,
                const float* __restrict__ eb0,
                const __half* __restrict__ Bh,
                const float* __restrict__ eb1, const float* __restrict__ ew2,
                const float* __restrict__ eb2, float* __restrict__ out)
{
    extern __shared__ char smd[];
    __shared__ float red[128];
    const uint32_t sb = smem_u32(smd);
    const int tid  = threadIdx.x;
    const int lane = tid & 31;
    const int wid  = tid >> 5;
    const int wm   = wid >> 2;
    const int wn   = wid & 3;
    const int e0   = blockIdx.x * 128;
    const int ra   = tid >> 2;        // A row 0..127
    const int ua   = tid & 3;         // k-unit 0..3 (8 halfs each)
    const int rb   = tid >> 1;        // B row 0..255
    const int ub   = (tid & 1) * 2;

    const int sn = src[e0 + ra];
    const int dn = dst[e0 + ra];
    if (tid < 128) red[tid] = 0.f;

    float acc[2][8][4];
#pragma unroll
    for (int a = 0; a < 2; a++)
#pragma unroll
        for (int b = 0; b < 8; b++)
#pragma unroll
            for (int c = 0; c < 4; c++) acc[a][b][c] = 0.f;

    __half2 apre[4];

    auto prefA = [&](int c) {
        const int kb = c * 32 + ua * 8;
        const __half2* ps = reinterpret_cast<const __half2*>(P + (size_t)sn * 1024 + kb);
        const __half2* pd = reinterpret_cast<const __half2*>(P + (size_t)dn * 1024 + 512 + kb);
        const float4* pb4 = reinterpret_cast<const float4*>(eb0 + kb);
        float4 b0 = pb4[0], b1 = pb4[1];
        float bb[8] = {b0.x, b0.y, b0.z, b0.w, b1.x, b1.y, b1.z, b1.w};
#pragma unroll
        for (int i = 0; i < 4; i++) {
            float2 a2 = __half22float2(ps[i]);
            float2 d2 = __half22float2(pd[i]);
            float f0 = fmaxf(a2.x + d2.x + bb[2 * i], 0.f);
            float f1 = fmaxf(a2.y + d2.y + bb[2 * i + 1], 0.f);
            apre[i] = __floats2half2_rn(f0, f1);
        }
    };

    auto storeA = [&](int s) {
        *reinterpret_cast<uint4*>(smd + s * 30720 + ra * 80 + ua * 16) =
            *reinterpret_cast<uint4*>(apre);
    };

    auto cpB = [&](int c, int s) {
        const size_t go = (size_t)rb * 512 + c * 32;
        const uint32_t db = sb + s * 30720 + 10240 + rb * 80;
#pragma unroll
        for (int u = 0; u < 2; u++)
            cp16(db + (ub + u) * 16, Bh + go + (ub + u) * 8);
    };

    auto comp = [&](int s) {
        const uint32_t base = sb + s * 30720;
#pragma unroll
        for (int ks = 0; ks < 2; ks++) {
            uint32_t ah[2][4], bh[8][2];
            const uint32_t arow = wm * 32 + (lane & 15);
            const uint32_t au = ks * 2 + (lane >> 4);
#pragma unroll
            for (int mt = 0; mt < 2; mt++)
                ldm_x4(ah[mt], base + (arow + mt * 16) * 80 + au * 16);
            const uint32_t brow0 = wn * 64 + (lane & 7) + ((lane >> 4) << 3);
            const uint32_t bu = ks * 2 + ((lane >> 3) & 1);
#pragma unroll
            for (int pr = 0; pr < 4; pr++) {
                uint32_t t[4];
                ldm_x4(t, base + 10240 + (brow0 + pr * 16) * 80 + bu * 16);
                bh[2 * pr][0] = t[0]; bh[2 * pr][1] = t[1];
                bh[2 * pr + 1][0] = t[2]; bh[2 * pr + 1][1] = t[3];
            }
#pragma unroll
            for (int mt = 0; mt < 2; mt++)
#pragma unroll
                for (int nt = 0; nt < 8; nt++)
                    mma_f32(acc[mt][nt], ah[mt], bh[nt]);
        }
    };

    prefA(0); storeA(0); cpB(0, 0);
    CP_COMMIT(); CP_WAIT0();
    __syncthreads();

#pragma unroll 1
    for (int c = 0; c < 16; c++) {
        const int s = c & 1;
        if (c + 1 < 16) { prefA(c + 1); cpB(c + 1, s ^ 1); CP_COMMIT(); }
        comp(s);
        if (c + 1 < 16) { storeA(s ^ 1); CP_WAIT0(); }
        __syncthreads();
    }

#pragma unroll
    for (int mt = 0; mt < 2; mt++) {
        float p0 = 0.f, p1 = 0.f;
#pragma unroll
        for (int nt = 0; nt < 8; nt++) {
            const int col = wn * 64 + nt * 8 + 2 * (lane & 3);
            const float b0 = eb1[col], b1 = eb1[col + 1];
            const float w0 = ew2[col], w1 = ew2[col + 1];
            p0 += fmaxf(acc[mt][nt][0] + b0, 0.f) * w0 + fmaxf(acc[mt][nt][1] + b1, 0.f) * w1;
            p1 += fmaxf(acc[mt][nt][2] + b0, 0.f) * w0 + fmaxf(acc[mt][nt][3] + b1, 0.f) * w1;
        }
        p0 += __shfl_xor_sync(0xffffffffu, p0, 1);
        p0 += __shfl_xor_sync(0xffffffffu, p0, 2);
        p1 += __shfl_xor_sync(0xffffffffu, p1, 1);
        p1 += __shfl_xor_sync(0xffffffffu, p1, 2);
        if ((lane & 3) == 0) {
            atomicAdd(&red[wm * 32 + mt * 16 + (lane >> 2)], p0);
            atomicAdd(&red[wm * 32 + mt * 16 + (lane >> 2) + 8], p1);
        }
    }
    __syncthreads();
    if (tid < 128) out[e0 + tid] = red[tid] + eb2[0];
}

// ================= fused prep kernel =================
__device__ __forceinline__ void split_at(const float* W, __half* th, __half* tl,
                                         int K, int N, int i)
{
    int n = i / K, k = i % K;
    float f = W[(size_t)k * N + n];
    __half h = __float2half_rn(f);
    th[i] = h; tl[i] = __float2half_rn(f - __half2float(h));
}

__global__ void prep_kernel(const float* nw0, const float* nw1,
                            const float* g1ws, const float* g1wd,
                            const float* g2ws, const float* g2wd,
                            const float* ew0, const float* ew1,
                            const float* g1bs, const float* g1bd,
                            const float* g2bs, const float* g2bd,
                            __half* nw0h, __half* nw0l, __half* nw1h, __half* nw1l,
                            __half* g1h, __half* g1l, __half* g2h, __half* g2l,
                            __half* w0h, __half* w0l, __half* w1h, __half* w1l,
                            float* b1c, float* b2c)
{
    int i = blockIdx.x * blockDim.x + threadIdx.x;
    if (i < 8192) { split_at(nw0, nw0h, nw0l, 64, 128, i); return; }
    i -= 8192;
    if (i < 16384) { split_at(nw1, nw1h, nw1l, 128, 128, i); return; }
    i -= 16384;
    if (i < 16384) { split_at(g1ws, g1h, g1l, 64, 256, i); return; }
    i -= 16384;
    if (i < 16384) { split_at(g1wd, g1h + 16384, g1l + 16384, 64, 256, i); return; }
    i -= 16384;
    if (i < 65536) { split_at(g2ws, g2h, g2l, 256, 256, i); return; }
    i -= 65536;
    if (i < 65536) { split_at(g2wd, g2h + 65536, g2l + 65536, 256, 256, i); return; }
    i -= 65536;
    if (i < 196608) {
        int n = i / 384, k = i % 384;
        int rs = (k < 128) ? k : k + 128;
        int rd = (k < 128) ? k + 128 : k + 384;
        float f = ew0[rs * 512 + n];
        __half h = __float2half_rn(f);
        w0h[i] = h; w0l[i] = __float2half_rn(f - __half2float(h));
        f = ew0[rd * 512 + n];
        h = __float2half_rn(f);
        w0h[196608 + i] = h;
        w0l[196608 + i] = __float2half_rn(f - __half2float(h));
        return;
    }
    i -= 196608;
    if (i < 131072) { split_at(ew1, w1h, w1l, 512, 256, i); return; }
    i -= 131072;
    if (i < 512) { b1c[i] = (i < 256) ? g1bs[i] : g1bd[i - 256]; return; }
    i -= 512;
    if (i < 512) { b2c[i] = (i < 256) ? g2bs[i] : g2bd[i - 256]; return; }
}

// ---------------- misc kernels ----------------
__global__ void zbuild_kernel(const float* __restrict__ h1, const float* __restrict__ a2,
                              const float* __restrict__ s, float* __restrict__ z)
{
    int i = blockIdx.x * blockDim.x + threadIdx.x;
    if (i >= N_NODES * 384) return;
    int n = i / 384, j = i % 384;
    if (j < 128) z[i] = h1[n * 128 + j];
    else {
        int q = j - 128;
        z[i] = fmaxf(a2[n * 256 + q] / s[n * 2 + (q >= 128 ? 1 : 0)], 0.f);
    }
}

// fused GAT pass, fp16 feature gather
__global__ void gat_fused_kernel(const __half* __restrict__ fsd,
                                 const float* __restrict__ attn,
                                 const int* __restrict__ src, const int* __restrict__ dst,
                                 float* __restrict__ s, float* __restrict__ acc)
{
    int e = (blockIdx.x * blockDim.x + threadIdx.x) >> 5;
    int lane = threadIdx.x & 31;
    if (e >= N_EDGES) return;
    int sN = src[e], tN = dst[e];
#pragma unroll
    for (int h = 0; h < 2; h++) {
        const __half2* pa = reinterpret_cast<const __half2*>(fsd + (size_t)sN * 512 + h * 128 + lane * 4);
        const __half2* pb = reinterpret_cast<const __half2*>(fsd + (size_t)tN * 512 + 256 + h * 128 + lane * 4);
        float2 a0 = __half22float2(pa[0]), a1 = __half22float2(pa[1]);
        float2 b0 = __half22float2(pb[0]), b1 = __half22float2(pb[1]);
        float4 t = *reinterpret_cast<const float4*>(attn + h * 128 + lane * 4);
        float v0 = a0.x + b0.x, v1 = a0.y + b0.y, v2 = a1.x + b1.x, v3 = a1.y + b1.y;
        v0 = (v0 > 0.f) ? v0 : 0.2f * v0;
        v1 = (v1 > 0.f) ? v1 : 0.2f * v1;
        v2 = (v2 > 0.f) ? v2 : 0.2f * v2;
        v3 = (v3 > 0.f) ? v3 : 0.2f * v3;
        float lg = v0 * t.x + v1 * t.y + v2 * t.z + v3 * t.w;
#pragma unroll
        for (int o = 16; o; o >>= 1) lg += __shfl_xor_sync(0xffffffffu, lg, o);
        float ev = expf(lg);
        if (lane == 0) atomicAdd(&s[tN * 2 + h], ev);
        float4 v = make_float4(a0.x * ev, a0.y * ev, a1.x * ev, a1.y * ev);
        atomicAdd(reinterpret_cast<float4*>(acc + (size_t)tN * 256 + h * 128 + lane * 4), v);
    }
}

// ---------------- host launch ----------------
extern "C" void kernel_launch(void* const* d_in, const int* in_sizes, int n_in,
                              void* d_out, int out_size)
{
    const float* x    = (const float*)d_in[0];
    const int*   src  = (const int*)d_in[1];
    const int*   dst  = (const int*)d_in[2];
    const float* nw0  = (const float*)d_in[3];
    const float* nb0  = (const float*)d_in[4];
    const float* nw1  = (const float*)d_in[5];
    const float* nb1  = (const float*)d_in[6];
    const float* g1ws = (const float*)d_in[7];
    const float* g1bs = (const float*)d_in[8];
    const float* g1wd = (const float*)d_in[9];
    const float* g1bd = (const float*)d_in[10];
    const float* g1a  = (const float*)d_in[11];
    const float* g2ws = (const float*)d_in[12];
    const float* g2bs = (const float*)d_in[13];
    const float* g2wd = (const float*)d_in[14];
    const float* g2bd = (const float*)d_in[15];
    const float* g2a  = (const float*)d_in[16];
    const float* ew0  = (const float*)d_in[17];
    const float* eb0  = (const float*)d_in[18];
    const float* ew1  = (const float*)d_in[19];
    const float* eb1  = (const float*)d_in[20];
    const float* ew2  = (const float*)d_in[21];
    const float* eb2  = (const float*)d_in[22];
    float* out = (float*)d_out;

    float *tmp, *h1, *acc, *sB, *z, *b1c, *b2c;
    __half *fsd, *P;
    __half *nw0h, *nw0l, *nw1h, *nw1l, *g1h, *g1l, *g2h, *g2l, *w0h, *w0l, *w1h, *w1l;
    cudaGetSymbolAddress((void**)&tmp,  g_tmp);
    cudaGetSymbolAddress((void**)&h1,   g_h1);
    cudaGetSymbolAddress((void**)&fsd,  g_fsd);
    cudaGetSymbolAddress((void**)&acc,  g_acc);
    cudaGetSymbolAddress((void**)&sB,   g_s);
    cudaGetSymbolAddress((void**)&z,    g_z);
    cudaGetSymbolAddress((void**)&P,    g_p);
    cudaGetSymbolAddress((void**)&b1c,  g_b1cat);
    cudaGetSymbolAddress((void**)&b2c,  g_b2cat);
    cudaGetSymbolAddress((void**)&nw0h, g_nw0h);
    cudaGetSymbolAddress((void**)&nw0l, g_nw0l);
    cudaGetSymbolAddress((void**)&nw1h, g_nw1h);
    cudaGetSymbolAddress((void**)&nw1l, g_nw1l);
    cudaGetSymbolAddress((void**)&g1h,  g_g1h);
    cudaGetSymbolAddress((void**)&g1l,  g_g1l);
    cudaGetSymbolAddress((void**)&g2h,  g_g2h);
    cudaGetSymbolAddress((void**)&g2l,  g_g2l);
    cudaGetSymbolAddress((void**)&w0h,  g_w0h);
    cudaGetSymbolAddress((void**)&w0l,  g_w0l);
    cudaGetSymbolAddress((void**)&w1h,  g_w1h);
    cudaGetSymbolAddress((void**)&w1l,  g_w1l);

    cudaFuncSetAttribute(mma_gemm_kernel, cudaFuncAttributeMaxDynamicSharedMemorySize, 81920);
    cudaFuncSetAttribute(edge_mma_kernel, cudaFuncAttributeMaxDynamicSharedMemorySize, 61440);

    // 0: prep
    prep_kernel<<<(517120 + 255) / 256, 256>>>(
        nw0, nw1, g1ws, g1wd, g2ws, g2wd, ew0, ew1,
        g1bs, g1bd, g2bs, g2bd,
        nw0h, nw0l, nw1h, nw1l, g1h, g1l, g2h, g2l,
        w0h, w0l, w1h, w1l, b1c, b2c);

    const int MBY = (N_NODES + 127) / 128;   // 157

    // NodeMLP (fp32 out)
    mma_gemm_kernel<<<dim3(1, MBY), 512, 81920>>>(
        x, N_NODES, 64, nw0h, nw0l, nb0, 0, 1, nullptr, tmp, nullptr, 128);
    mma_gemm_kernel<<<dim3(1, MBY), 512, 81920>>>(
        tmp, N_NODES, 128, nw1h, nw1l, nb1, 0, 1, nullptr, h1, nullptr, 128);

    // GAT layer 1
    mma_gemm_kernel<<<dim3(4, MBY), 512, 81920>>>(
        x, N_NODES, 64, g1h, g1l, b1c, 0, 0, nullptr, nullptr, fsd, 512);
    cudaMemsetAsync(acc, 0, (size_t)N_NODES * 256 * sizeof(float));
    cudaMemsetAsync(sB, 0, (size_t)N_NODES * 2 * sizeof(float));
    gat_fused_kernel<<<N_EDGES / 8, 256>>>(fsd, g1a, src, dst, sB, acc);

    // GAT layer 2
    mma_gemm_kernel<<<dim3(4, MBY), 512, 81920>>>(
        acc, N_NODES, 256, g2h, g2l, b2c, 1, 0, sB, nullptr, fsd, 512);
    cudaMemsetAsync(acc, 0, (size_t)N_NODES * 256 * sizeof(float));
    cudaMemsetAsync(sB, 0, (size_t)N_NODES * 2 * sizeof(float));
    gat_fused_kernel<<<N_EDGES / 8, 256>>>(fsd, g2a, src, dst, sB, acc);

    // Z and P (P fp16)
    zbuild_kernel<<<(N_NODES * 384 + 255) / 256, 256>>>(h1, acc, sB, z);
    mma_gemm_kernel<<<dim3(8, MBY), 512, 81920>>>(
        z, N_NODES, 384, w0h, w0l, nullptr, 0, 0, nullptr, nullptr, P, 1024);

    // EdgeMLP fused (pure fp16)
    edge_mma_kernel<<<N_EDGES / 128, 512, 61440>>>(
        P, src, dst, eb0, w1h, eb1, ew2, eb2, out);
}

// round 9
// speedup vs baseline: 13.3480x; 1.1770x over previous
#include <cuda_runtime.h>
#include <cuda_fp16.h>
#include <cstdint>

#define N_NODES 20000
#define N_EDGES 320000

// ---------------- scratch ----------------
__device__ float  g_tmp [N_NODES * 128];
__device__ float  g_h1  [N_NODES * 128];
__device__ __half g_fsd [N_NODES * 512];   // [fs | fd] per node, fp16
__device__ float  g_acc [N_NODES * 256];
__device__ float  g_s   [N_NODES * 2];
__device__ __half g_p   [N_NODES * 1024];  // [Psrc | Pdst], fp16
__device__ __half g_nw0h[128 * 64];
__device__ __half g_nw1h[128 * 128];
__device__ __half g_g1h [512 * 64];
__device__ __half g_g2h [512 * 256];
__device__ __half g_w0h [1024 * 384];
__device__ __half g_w1h [256 * 512];
__device__ float  g_b1cat[512], g_b2cat[512];

// ---------------- PTX helpers ----------------
__device__ __forceinline__ uint32_t smem_u32(const void* p) {
    uint32_t a;
    asm("{ .reg .u64 t; cvta.to.shared.u64 t, %1; cvt.u32.u64 %0, t; }" : "=r"(a) : "l"(p));
    return a;
}
__device__ __forceinline__ void ldm_x4(uint32_t* r, uint32_t a) {
    asm volatile("ldmatrix.sync.aligned.m8n8.x4.shared.b16 {%0,%1,%2,%3}, [%4];"
                 : "=r"(r[0]), "=r"(r[1]), "=r"(r[2]), "=r"(r[3]) : "r"(a));
}
__device__ __forceinline__ void mma_f32(float* c, const uint32_t* a, const uint32_t* b) {
    asm volatile("mma.sync.aligned.m16n8k16.row.col.f32.f16.f16.f32 "
                 "{%0,%1,%2,%3}, {%4,%5,%6,%7}, {%8,%9}, {%0,%1,%2,%3};"
                 : "+f"(c[0]), "+f"(c[1]), "+f"(c[2]), "+f"(c[3])
                 : "r"(a[0]), "r"(a[1]), "r"(a[2]), "r"(a[3]), "r"(b[0]), "r"(b[1]));
}
__device__ __forceinline__ void cp16(uint32_t d, const void* s) {
    asm volatile("cp.async.cg.shared.global [%0], [%1], 16;" :: "r"(d), "l"(s));
}
#define CP_COMMIT() asm volatile("cp.async.commit_group;")
#define CP_WAIT0()  asm volatile("cp.async.wait_group 0;")

// ================= node-side HMMA GEMM: single fp16, 512 threads, 2 CTAs/SM =================
// BM=128, BN=128, BK=32. 16 warps (4M x 4N), warp tile 32x32.
// smem/stage 20480: A@0 (128x80), B@10240 (128x80). 2 stages = 40960.
// A2 mode (A2 != nullptr): A_logical(m,k) = k<128 ? A[m*128+k]
//                                         : relu(A2[m*256+(k-128)] / rowscale[m*2+((k-128)>=128)])
__global__ void __launch_bounds__(512, 2)
mma_gemm_kernel(const float* __restrict__ A, int M, int K,
                const float* __restrict__ A2,
                const __half* __restrict__ Bh,
                const float* __restrict__ bias, int in_relu, int out_relu,
                const float* __restrict__ rowscale,
                float* __restrict__ C, __half* __restrict__ Ch, int NTOT)
{
    extern __shared__ char smd[];
    const uint32_t sb = smem_u32(smd);
    const int tid  = threadIdx.x;
    const int lane = tid & 31;
    const int wid  = tid >> 5;
    const int wm   = wid >> 2;
    const int wn   = wid & 3;
    const int bm0  = blockIdx.y * 128;
    const int n0   = blockIdx.x * 128;
    const int ra   = tid >> 2;
    const int ua   = tid & 3;

    float acc[2][4][4];
#pragma unroll
    for (int a = 0; a < 2; a++)
#pragma unroll
        for (int b = 0; b < 4; b++)
#pragma unroll
            for (int c = 0; c < 4; c++) acc[a][b][c] = 0.f;

    const int NC = K >> 5;
    float apre[8];

    auto prefA = [&](int c) {
        const int kb = c * 32 + ua * 8;
        const int m = bm0 + ra;
        if (m < M) {
            if (A2 != nullptr && kb >= 128) {
                const int q = kb - 128;
                const float4* p = reinterpret_cast<const float4*>(A2 + (size_t)m * 256 + q);
#pragma unroll
                for (int i = 0; i < 2; i++) {
                    float4 v = p[i];
                    apre[i * 4 + 0] = v.x; apre[i * 4 + 1] = v.y;
                    apre[i * 4 + 2] = v.z; apre[i * 4 + 3] = v.w;
                }
                float rs = 1.f / rowscale[m * 2 + (q >= 128 ? 1 : 0)];
#pragma unroll
                for (int i = 0; i < 8; i++) apre[i] = fmaxf(apre[i] * rs, 0.f);
            } else {
                const int stride = (A2 != nullptr) ? 128 : K;
                const float4* p = reinterpret_cast<const float4*>(A + (size_t)m * stride + kb);
#pragma unroll
                for (int i = 0; i < 2; i++) {
                    float4 v = p[i];
                    apre[i * 4 + 0] = v.x; apre[i * 4 + 1] = v.y;
                    apre[i * 4 + 2] = v.z; apre[i * 4 + 3] = v.w;
                }
                if (A2 == nullptr && rowscale != nullptr) {
                    float rs = 1.f / rowscale[m * 2 + (kb >= 128 ? 1 : 0)];
#pragma unroll
                    for (int i = 0; i < 8; i++) apre[i] *= rs;
                }
                if (in_relu) {
#pragma unroll
                    for (int i = 0; i < 8; i++) apre[i] = fmaxf(apre[i], 0.f);
                }
            }
        } else {
#pragma unroll
            for (int i = 0; i < 8; i++) apre[i] = 0.f;
        }
    };

    auto storeA = [&](int s) {
        __half2 h2[4];
#pragma unroll
        for (int j = 0; j < 4; j++)
            h2[j] = __floats2half2_rn(apre[2 * j], apre[2 * j + 1]);
        *reinterpret_cast<uint4*>(smd + s * 20480 + ra * 80 + ua * 16) =
            *reinterpret_cast<uint4*>(h2);
    };

    auto cpB = [&](int c, int s) {
        const size_t go = (size_t)(n0 + ra) * K + c * 32 + ua * 8;
        cp16(sb + s * 20480 + 10240 + ra * 80 + ua * 16, Bh + go);
    };

    auto comp = [&](int s) {
        const uint32_t base = sb + s * 20480;
#pragma unroll
        for (int ks = 0; ks < 2; ks++) {
            uint32_t ah[2][4], bh[4][2];
            const uint32_t arow = wm * 32 + (lane & 15);
            const uint32_t au = ks * 2 + (lane >> 4);
#pragma unroll
            for (int mt = 0; mt < 2; mt++)
                ldm_x4(ah[mt], base + (arow + mt * 16) * 80 + au * 16);
            const uint32_t brow0 = wn * 32 + (lane & 7) + ((lane >> 4) << 3);
            const uint32_t bu = ks * 2 + ((lane >> 3) & 1);
#pragma unroll
            for (int pr = 0; pr < 2; pr++) {
                uint32_t t[4];
                ldm_x4(t, base + 10240 + (brow0 + pr * 16) * 80 + bu * 16);
                bh[2 * pr][0] = t[0]; bh[2 * pr][1] = t[1];
                bh[2 * pr + 1][0] = t[2]; bh[2 * pr + 1][1] = t[3];
            }
#pragma unroll
            for (int mt = 0; mt < 2; mt++)
#pragma unroll
                for (int nt = 0; nt < 4; nt++)
                    mma_f32(acc[mt][nt], ah[mt], bh[nt]);
        }
    };

    prefA(0); storeA(0); cpB(0, 0);
    CP_COMMIT(); CP_WAIT0();
    __syncthreads();

    for (int c = 0; c < NC; c++) {
        const int s = c & 1;
        if (c + 1 < NC) { prefA(c + 1); cpB(c + 1, s ^ 1); CP_COMMIT(); }
        comp(s);
        if (c + 1 < NC) { storeA(s ^ 1); CP_WAIT0(); }
        __syncthreads();
    }

#pragma unroll
    for (int mt = 0; mt < 2; mt++) {
        const int row = bm0 + wm * 32 + mt * 16 + (lane >> 2);
#pragma unroll
        for (int nt = 0; nt < 4; nt++) {
            const int col = n0 + wn * 32 + nt * 8 + 2 * (lane & 3);
            float b0 = bias ? bias[col] : 0.f;
            float b1 = bias ? bias[col + 1] : 0.f;
            float v0 = acc[mt][nt][0] + b0, v1 = acc[mt][nt][1] + b1;
            float v2 = acc[mt][nt][2] + b0, v3 = acc[mt][nt][3] + b1;
            if (out_relu) {
                v0 = fmaxf(v0, 0.f); v1 = fmaxf(v1, 0.f);
                v2 = fmaxf(v2, 0.f); v3 = fmaxf(v3, 0.f);
            }
            if (Ch) {
                if (row < M)
                    *reinterpret_cast<__half2*>(Ch + (size_t)row * NTOT + col) =
                        __floats2half2_rn(v0, v1);
                if (row + 8 < M)
                    *reinterpret_cast<__half2*>(Ch + (size_t)(row + 8) * NTOT + col) =
                        __floats2half2_rn(v2, v3);
            } else {
                if (row < M)
                    *reinterpret_cast<float2*>(C + (size_t)row * NTOT + col) = make_float2(v0, v1);
                if (row + 8 < M)
                    *reinterpret_cast<float2*>(C + (size_t)(row + 8) * NTOT + col) = make_float2(v2, v3);
            }
        }
    }
}

// ================= edge HMMA kernel: pure fp16, BM=128, BN=256, 512 threads (proven) =================
__global__ void __launch_bounds__(512)
edge_mma_kernel(const __half* __restrict__ P,
                const int* __restrict__ src, const int* __restrict__ dst,
                const float* __restrict__ eb0,
                const __half* __restrict__ Bh,
                const float* __restrict__ eb1, const float* __restrict__ ew2,
                const float* __restrict__ eb2, float* __restrict__ out)
{
    extern __shared__ char smd[];
    __shared__ float red[128];
    const uint32_t sb = smem_u32(smd);
    const int tid  = threadIdx.x;
    const int lane = tid & 31;
    const int wid  = tid >> 5;
    const int wm   = wid >> 2;
    const int wn   = wid & 3;
    const int e0   = blockIdx.x * 128;
    const int ra   = tid >> 2;
    const int ua   = tid & 3;
    const int rb   = tid >> 1;
    const int ub   = (tid & 1) * 2;

    const int sn = src[e0 + ra];
    const int dn = dst[e0 + ra];
    if (tid < 128) red[tid] = 0.f;

    float acc[2][8][4];
#pragma unroll
    for (int a = 0; a < 2; a++)
#pragma unroll
        for (int b = 0; b < 8; b++)
#pragma unroll
            for (int c = 0; c < 4; c++) acc[a][b][c] = 0.f;

    __half2 apre[4];

    auto prefA = [&](int c) {
        const int kb = c * 32 + ua * 8;
        const __half2* ps = reinterpret_cast<const __half2*>(P + (size_t)sn * 1024 + kb);
        const __half2* pd = reinterpret_cast<const __half2*>(P + (size_t)dn * 1024 + 512 + kb);
        const float4* pb4 = reinterpret_cast<const float4*>(eb0 + kb);
        float4 b0 = pb4[0], b1 = pb4[1];
        float bb[8] = {b0.x, b0.y, b0.z, b0.w, b1.x, b1.y, b1.z, b1.w};
#pragma unroll
        for (int i = 0; i < 4; i++) {
            float2 a2 = __half22float2(ps[i]);
            float2 d2 = __half22float2(pd[i]);
            float f0 = fmaxf(a2.x + d2.x + bb[2 * i], 0.f);
            float f1 = fmaxf(a2.y + d2.y + bb[2 * i + 1], 0.f);
            apre[i] = __floats2half2_rn(f0, f1);
        }
    };

    auto storeA = [&](int s) {
        *reinterpret_cast<uint4*>(smd + s * 30720 + ra * 80 + ua * 16) =
            *reinterpret_cast<uint4*>(apre);
    };

    auto cpB = [&](int c, int s) {
        const size_t go = (size_t)rb * 512 + c * 32;
        const uint32_t db = sb + s * 30720 + 10240 + rb * 80;
#pragma unroll
        for (int u = 0; u < 2; u++)
            cp16(db + (ub + u) * 16, Bh + go + (ub + u) * 8);
    };

    auto comp = [&](int s) {
        const uint32_t base = sb + s * 30720;
#pragma unroll
        for (int ks = 0; ks < 2; ks++) {
            uint32_t ah[2][4], bh[8][2];
            const uint32_t arow = wm * 32 + (lane & 15);
            const uint32_t au = ks * 2 + (lane >> 4);
#pragma unroll
            for (int mt = 0; mt < 2; mt++)
                ldm_x4(ah[mt], base + (arow + mt * 16) * 80 + au * 16);
            const uint32_t brow0 = wn * 64 + (lane & 7) + ((lane >> 4) << 3);
            const uint32_t bu = ks * 2 + ((lane >> 3) & 1);
#pragma unroll
            for (int pr = 0; pr < 4; pr++) {
                uint32_t t[4];
                ldm_x4(t, base + 10240 + (brow0 + pr * 16) * 80 + bu * 16);
                bh[2 * pr][0] = t[0]; bh[2 * pr][1] = t[1];
                bh[2 * pr + 1][0] = t[2]; bh[2 * pr + 1][1] = t[3];
            }
#pragma unroll
            for (int mt = 0; mt < 2; mt++)
#pragma unroll
                for (int nt = 0; nt < 8; nt++)
                    mma_f32(acc[mt][nt], ah[mt], bh[nt]);
        }
    };

    prefA(0); storeA(0); cpB(0, 0);
    CP_COMMIT(); CP_WAIT0();
    __syncthreads();

#pragma unroll 1
    for (int c = 0; c < 16; c++) {
        const int s = c & 1;
        if (c + 1 < 16) { prefA(c + 1); cpB(c + 1, s ^ 1); CP_COMMIT(); }
        comp(s);
        if (c + 1 < 16) { storeA(s ^ 1); CP_WAIT0(); }
        __syncthreads();
    }

#pragma unroll
    for (int mt = 0; mt < 2; mt++) {
        float p0 = 0.f, p1 = 0.f;
#pragma unroll
        for (int nt = 0; nt < 8; nt++) {
            const int col = wn * 64 + nt * 8 + 2 * (lane & 3);
            const float b0 = eb1[col], b1 = eb1[col + 1];
            const float w0 = ew2[col], w1 = ew2[col + 1];
            p0 += fmaxf(acc[mt][nt][0] + b0, 0.f) * w0 + fmaxf(acc[mt][nt][1] + b1, 0.f) * w1;
            p1 += fmaxf(acc[mt][nt][2] + b0, 0.f) * w0 + fmaxf(acc[mt][nt][3] + b1, 0.f) * w1;
        }
        p0 += __shfl_xor_sync(0xffffffffu, p0, 1);
        p0 += __shfl_xor_sync(0xffffffffu, p0, 2);
        p1 += __shfl_xor_sync(0xffffffffu, p1, 1);
        p1 += __shfl_xor_sync(0xffffffffu, p1, 2);
        if ((lane & 3) == 0) {
            atomicAdd(&red[wm * 32 + mt * 16 + (lane >> 2)], p0);
            atomicAdd(&red[wm * 32 + mt * 16 + (lane >> 2) + 8], p1);
        }
    }
    __syncthreads();
    if (tid < 128) out[e0 + tid] = red[tid] + eb2[0];
}

// ================= fused prep kernel (fp16 hi only) =================
__device__ __forceinline__ void split_at(const float* W, __half* th, int K, int N, int i)
{
    int n = i / K, k = i % K;
    th[i] = __float2half_rn(W[(size_t)k * N + n]);
}

__global__ void prep_kernel(const float* nw0, const float* nw1,
                            const float* g1ws, const float* g1wd,
                            const float* g2ws, const float* g2wd,
                            const float* ew0, const float* ew1,
                            const float* g1bs, const float* g1bd,
                            const float* g2bs, const float* g2bd,
                            __half* nw0h, __half* nw1h,
                            __half* g1h, __half* g2h,
                            __half* w0h, __half* w1h,
                            float* b1c, float* b2c)
{
    int i = blockIdx.x * blockDim.x + threadIdx.x;
    if (i < 8192) { split_at(nw0, nw0h, 64, 128, i); return; }
    i -= 8192;
    if (i < 16384) { split_at(nw1, nw1h, 128, 128, i); return; }
    i -= 16384;
    if (i < 16384) { split_at(g1ws, g1h, 64, 256, i); return; }
    i -= 16384;
    if (i < 16384) { split_at(g1wd, g1h + 16384, 64, 256, i); return; }
    i -= 16384;
    if (i < 65536) { split_at(g2ws, g2h, 256, 256, i); return; }
    i -= 65536;
    if (i < 65536) { split_at(g2wd, g2h + 65536, 256, 256, i); return; }
    i -= 65536;
    if (i < 196608) {
        int n = i / 384, k = i % 384;
        int rs = (k < 128) ? k : k + 128;
        int rd = (k < 128) ? k + 128 : k + 384;
        w0h[i] = __float2half_rn(ew0[rs * 512 + n]);
        w0h[196608 + i] = __float2half_rn(ew0[rd * 512 + n]);
        return;
    }
    i -= 196608;
    if (i < 131072) { split_at(ew1, w1h, 512, 256, i); return; }
    i -= 131072;
    if (i < 512) { b1c[i] = (i < 256) ? g1bs[i] : g1bd[i - 256]; return; }
    i -= 512;
    if (i < 512) { b2c[i] = (i < 256) ? g2bs[i] : g2bd[i - 256]; return; }
}

// ---------------- GAT fused pass (proven) ----------------
__global__ void gat_fused_kernel(const __half* __restrict__ fsd,
                                 const float* __restrict__ attn,
                                 const int* __restrict__ src, const int* __restrict__ dst,
                                 float* __restrict__ s, float* __restrict__ acc)
{
    int e = (blockIdx.x * blockDim.x + threadIdx.x) >> 5;
    int lane = threadIdx.x & 31;
    if (e >= N_EDGES) return;
    int sN = src[e], tN = dst[e];
#pragma unroll
    for (int h = 0; h < 2; h++) {
        const __half2* pa = reinterpret_cast<const __half2*>(fsd + (size_t)sN * 512 + h * 128 + lane * 4);
        const __half2* pb = reinterpret_cast<const __half2*>(fsd + (size_t)tN * 512 + 256 + h * 128 + lane * 4);
        float2 a0 = __half22float2(pa[0]), a1 = __half22float2(pa[1]);
        float2 b0 = __half22float2(pb[0]), b1 = __half22float2(pb[1]);
        float4 t = *reinterpret_cast<const float4*>(attn + h * 128 + lane * 4);
        float v0 = a0.x + b0.x, v1 = a0.y + b0.y, v2 = a1.x + b1.x, v3 = a1.y + b1.y;
        v0 = (v0 > 0.f) ? v0 : 0.2f * v0;
        v1 = (v1 > 0.f) ? v1 : 0.2f * v1;
        v2 = (v2 > 0.f) ? v2 : 0.2f * v2;
        v3 = (v3 > 0.f) ? v3 : 0.2f * v3;
        float lg = v0 * t.x + v1 * t.y + v2 * t.z + v3 * t.w;
#pragma unroll
        for (int o = 16; o; o >>= 1) lg += __shfl_xor_sync(0xffffffffu, lg, o);
        float ev = expf(lg);
        if (lane == 0) atomicAdd(&s[tN * 2 + h], ev);
        float4 v = make_float4(a0.x * ev, a0.y * ev, a1.x * ev, a1.y * ev);
        atomicAdd(reinterpret_cast<float4*>(acc + (size_t)tN * 256 + h * 128 + lane * 4), v);
    }
}

// ---------------- host launch ----------------
extern "C" void kernel_launch(void* const* d_in, const int* in_sizes, int n_in,
                              void* d_out, int out_size)
{
    const float* x    = (const float*)d_in[0];
    const int*   src  = (const int*)d_in[1];
    const int*   dst  = (const int*)d_in[2];
    const float* nw0  = (const float*)d_in[3];
    const float* nb0  = (const float*)d_in[4];
    const float* nw1  = (const float*)d_in[5];
    const float* nb1  = (const float*)d_in[6];
    const float* g1ws = (const float*)d_in[7];
    const float* g1bs = (const float*)d_in[8];
    const float* g1wd = (const float*)d_in[9];
    const float* g1bd = (const float*)d_in[10];
    const float* g1a  = (const float*)d_in[11];
    const float* g2ws = (const float*)d_in[12];
    const float* g2bs = (const float*)d_in[13];
    const float* g2wd = (const float*)d_in[14];
    const float* g2bd = (const float*)d_in[15];
    const float* g2a  = (const float*)d_in[16];
    const float* ew0  = (const float*)d_in[17];
    const float* eb0  = (const float*)d_in[18];
    const float* ew1  = (const float*)d_in[19];
    const float* eb1  = (const float*)d_in[20];
    const float* ew2  = (const float*)d_in[21];
    const float* eb2  = (const float*)d_in[22];
    float* out = (float*)d_out;

    float *tmp, *h1, *acc, *sB, *b1c, *b2c;
    __half *fsd, *P;
    __half *nw0h, *nw1h, *g1h, *g2h, *w0h, *w1h;
    cudaGetSymbolAddress((void**)&tmp,  g_tmp);
    cudaGetSymbolAddress((void**)&h1,   g_h1);
    cudaGetSymbolAddress((void**)&fsd,  g_fsd);
    cudaGetSymbolAddress((void**)&acc,  g_acc);
    cudaGetSymbolAddress((void**)&sB,   g_s);
    cudaGetSymbolAddress((void**)&P,    g_p);
    cudaGetSymbolAddress((void**)&b1c,  g_b1cat);
    cudaGetSymbolAddress((void**)&b2c,  g_b2cat);
    cudaGetSymbolAddress((void**)&nw0h, g_nw0h);
    cudaGetSymbolAddress((void**)&nw1h, g_nw1h);
    cudaGetSymbolAddress((void**)&g1h,  g_g1h);
    cudaGetSymbolAddress((void**)&g2h,  g_g2h);
    cudaGetSymbolAddress((void**)&w0h,  g_w0h);
    cudaGetSymbolAddress((void**)&w1h,  g_w1h);

    cudaFuncSetAttribute(mma_gemm_kernel, cudaFuncAttributeMaxDynamicSharedMemorySize, 40960);
    cudaFuncSetAttribute(edge_mma_kernel, cudaFuncAttributeMaxDynamicSharedMemorySize, 61440);

    // 0: prep
    prep_kernel<<<(517120 + 255) / 256, 256>>>(
        nw0, nw1, g1ws, g1wd, g2ws, g2wd, ew0, ew1,
        g1bs, g1bd, g2bs, g2bd,
        nw0h, nw1h, g1h, g2h, w0h, w1h, b1c, b2c);

    const int MBY = (N_NODES + 127) / 128;   // 157

    // NodeMLP (fp32 out)
    mma_gemm_kernel<<<dim3(1, MBY), 512, 40960>>>(
        x, N_NODES, 64, nullptr, nw0h, nb0, 0, 1, nullptr, tmp, nullptr, 128);
    mma_gemm_kernel<<<dim3(1, MBY), 512, 40960>>>(
        tmp, N_NODES, 128, nullptr, nw1h, nb1, 0, 1, nullptr, h1, nullptr, 128);

    // GAT layer 1
    mma_gemm_kernel<<<dim3(4, MBY), 512, 40960>>>(
        x, N_NODES, 64, nullptr, g1h, b1c, 0, 0, nullptr, nullptr, fsd, 512);
    cudaMemsetAsync(acc, 0, (size_t)N_NODES * 256 * sizeof(float));
    cudaMemsetAsync(sB, 0, (size_t)N_NODES * 2 * sizeof(float));
    gat_fused_kernel<<<N_EDGES / 8, 256>>>(fsd, g1a, src, dst, sB, acc);

    // GAT layer 2 (input = relu(acc/s) via rowscale)
    mma_gemm_kernel<<<dim3(4, MBY), 512, 40960>>>(
        acc, N_NODES, 256, nullptr, g2h, b2c, 1, 0, sB, nullptr, fsd, 512);
    cudaMemsetAsync(acc, 0, (size_t)N_NODES * 256 * sizeof(float));
    cudaMemsetAsync(sB, 0, (size_t)N_NODES * 2 * sizeof(float));
    gat_fused_kernel<<<N_EDGES / 8, 256>>>(fsd, g2a, src, dst, sB, acc);

    // P = [h1 | relu(acc/s)] @ [W0s|W0d]  (zbuild fused into A-load; P fp16)
    mma_gemm_kernel<<<dim3(8, MBY), 512, 40960>>>(
        h1, N_NODES, 384, acc, w0h, nullptr, 0, 0, sB, nullptr, P, 1024);

    // EdgeMLP fused (pure fp16)
    edge_mma_kernel<<<N_EDGES / 128, 512, 61440>>>(
        P, src, dst, eb0, w1h, eb1, ew2, eb2, out);
}